// round 1
// baseline (speedup 1.0000x reference)
#include <cuda_runtime.h>
#include <math.h>

#define Bn   8192
#define In   512
#define Hn   1024
#define Rn   64
#define FourH 4096   // 4*Hn

// ------------------------------------------------------------------
// Device scratch (no allocations allowed in kernel_launch)
// ------------------------------------------------------------------
__device__ float g_P[Bn * 128];        // [B, 128]  = [x@u_x | h@u_h]
__device__ float g_Vt[128 * FourH];    // [128, 4096], col = j*4+g
__device__ float g_cfx[FourH];         // coef_x laid out [j*4+g] (0 for j>=I)
__device__ float g_cfh[FourH];         // coef_h laid out [j*4+g]
__device__ float g_bias[FourH];        // b_x+b_h laid out [j*4+g]

// ------------------------------------------------------------------
// packed f32x2 helpers (B300: 2x fp32 FMA throughput vs scalar FFMA)
// ------------------------------------------------------------------
__device__ __forceinline__ unsigned long long pk2(float lo, float hi) {
    unsigned long long r;
    asm("mov.b64 %0, {%1, %2};" : "=l"(r) : "f"(lo), "f"(hi));
    return r;
}
__device__ __forceinline__ void upk2(unsigned long long v, float& lo, float& hi) {
    asm("mov.b64 {%0, %1}, %2;" : "=f"(lo), "=f"(hi) : "l"(v));
}
__device__ __forceinline__ void ffma2(unsigned long long& d,
                                      unsigned long long a,
                                      unsigned long long b) {
    asm("fma.rn.f32x2 %0, %1, %2, %3;" : "=l"(d) : "l"(a), "l"(b), "l"(d));
}

// ------------------------------------------------------------------
// Prep 1: per-(j,gate) coefficients and fused bias
// coef_x[j*4+g] = sum_r u_x[j,r] * v_x[g*H+j, r]   (j < I, else 0)
// coef_h[j*4+g] = sum_r u_h[j,r] * v_h[g*H+j, r]
// bias  [j*4+g] = b_x[g*H+j] + b_h[g*H+j]
// ------------------------------------------------------------------
__global__ void prep_coef_kernel(const float* __restrict__ u_x,
                                 const float* __restrict__ u_h,
                                 const float* __restrict__ v_x,
                                 const float* __restrict__ v_h,
                                 const float* __restrict__ b_x,
                                 const float* __restrict__ b_h) {
    int idx = blockIdx.x * blockDim.x + threadIdx.x;   // idx = j*4+g
    if (idx >= FourH) return;
    int j = idx >> 2;
    int g = idx & 3;
    int row4h = g * Hn + j;

    float cx = 0.f;
    if (j < In) {
        const float* uxr = u_x + j * Rn;
        const float* vxr = v_x + row4h * Rn;
        #pragma unroll 8
        for (int r = 0; r < Rn; r++) cx += uxr[r] * vxr[r];
    }
    float ch = 0.f;
    {
        const float* uhr = u_h + j * Rn;
        const float* vhr = v_h + row4h * Rn;
        #pragma unroll 8
        for (int r = 0; r < Rn; r++) ch += uhr[r] * vhr[r];
    }
    g_cfx[idx]  = cx;
    g_cfh[idx]  = ch;
    g_bias[idx] = b_x[row4h] + b_h[row4h];
}

// ------------------------------------------------------------------
// Prep 2: build Vt [128][4096]: Vt[r][j*4+g] = v_x[g*H+j, r] (r<64)
//                               Vt[r][j*4+g] = v_h[g*H+j, r-64] (r>=64)
// ------------------------------------------------------------------
__global__ void prep_vt_kernel(const float* __restrict__ v_x,
                               const float* __restrict__ v_h) {
    int idx = blockIdx.x * blockDim.x + threadIdx.x;   // linear into g_Vt
    if (idx >= 128 * FourH) return;
    int r   = idx >> 12;          // /4096
    int col = idx & (FourH - 1);
    int j = col >> 2;
    int g = col & 3;
    int row4h = g * Hn + j;
    float v = (r < 64) ? v_x[row4h * Rn + r] : v_h[row4h * Rn + (r - 64)];
    g_Vt[idx] = v;
}

// ------------------------------------------------------------------
// Projection GEMM: P[:, colOff : colOff+64] = A[B,K] @ U[K,64]
// tile: 64 rows x 64 cols, 256 threads (16x16), thread = 4 rows x 4 cols
// ------------------------------------------------------------------
__global__ void proj_kernel(const float* __restrict__ A,
                            const float* __restrict__ U,
                            int K, int colOff) {
    __shared__ float  As[64][33];
    __shared__ float4 Us[32][16];

    int tid = threadIdx.x;
    int tx = tid & 15;       // col group (4 cols)
    int ty = tid >> 4;       // 0..15
    int rowBase = blockIdx.x * 64;

    unsigned long long acc01[4] = {0ull, 0ull, 0ull, 0ull};
    unsigned long long acc23[4] = {0ull, 0ull, 0ull, 0ull};

    for (int k0 = 0; k0 < K; k0 += 32) {
        // load A tile: 64 rows x 32 cols = 512 float4
        #pragma unroll
        for (int p = 0; p < 2; p++) {
            int e = p * 256 + tid;
            int row = e >> 3;
            int c4  = e & 7;
            float4 v = *reinterpret_cast<const float4*>(
                A + (size_t)(rowBase + row) * K + k0 + c4 * 4);
            As[row][c4 * 4 + 0] = v.x;
            As[row][c4 * 4 + 1] = v.y;
            As[row][c4 * 4 + 2] = v.z;
            As[row][c4 * 4 + 3] = v.w;
        }
        // load U tile: 32 x 64 = 512 float4
        #pragma unroll
        for (int p = 0; p < 2; p++) {
            int e = p * 256 + tid;
            int k  = e >> 4;
            int c4 = e & 15;
            Us[k][c4] = *reinterpret_cast<const float4*>(
                U + (size_t)(k0 + k) * 64 + c4 * 4);
        }
        __syncthreads();

        #pragma unroll
        for (int k = 0; k < 32; k++) {
            float4 u = Us[k][tx];
            unsigned long long u01 = pk2(u.x, u.y);
            unsigned long long u23 = pk2(u.z, u.w);
            #pragma unroll
            for (int i = 0; i < 4; i++) {
                float a = As[ty + 16 * i][k];
                unsigned long long aa = pk2(a, a);
                ffma2(acc01[i], aa, u01);
                ffma2(acc23[i], aa, u23);
            }
        }
        __syncthreads();
    }

    #pragma unroll
    for (int i = 0; i < 4; i++) {
        float4 o;
        upk2(acc01[i], o.x, o.y);
        upk2(acc23[i], o.z, o.w);
        int row = rowBase + ty + 16 * i;
        *reinterpret_cast<float4*>(g_P + (size_t)row * 128 + colOff + tx * 4) = o;
    }
}

// ------------------------------------------------------------------
// Main GEMM + fused LSTM epilogue.
// tile: 128 B-rows x 64 gate-cols (= 16 j x 4 gates), K = 128
// 256 threads (16x16), thread = 8 rows x 4 cols (the 4 gates of one j)
// ------------------------------------------------------------------
__global__ void main_kernel(const float* __restrict__ x,
                            const float* __restrict__ h,
                            const float* __restrict__ c,
                            const float* __restrict__ dia_x,
                            const float* __restrict__ dia_h,
                            float* __restrict__ out) {
    __shared__ float  Ps[128][33];
    __shared__ float4 Vts[32][16];

    int tid = threadIdx.x;
    int tx = tid & 15;       // j within tile
    int ty = tid >> 4;       // 0..15
    int rowBase = blockIdx.y * 128;
    int colBase = blockIdx.x * 64;      // gate-column base (j*4+g space)
    int jBase   = colBase >> 2;         // hidden-unit base

    unsigned long long acc01[8] = {0,0,0,0,0,0,0,0};
    unsigned long long acc23[8] = {0,0,0,0,0,0,0,0};

    #pragma unroll
    for (int k0 = 0; k0 < 128; k0 += 32) {
        // P tile: 128 x 32 = 1024 float4
        #pragma unroll
        for (int p = 0; p < 4; p++) {
            int e = p * 256 + tid;
            int row = e >> 3;
            int c4  = e & 7;
            float4 v = *reinterpret_cast<const float4*>(
                g_P + (size_t)(rowBase + row) * 128 + k0 + c4 * 4);
            Ps[row][c4 * 4 + 0] = v.x;
            Ps[row][c4 * 4 + 1] = v.y;
            Ps[row][c4 * 4 + 2] = v.z;
            Ps[row][c4 * 4 + 3] = v.w;
        }
        // Vt tile: 32 x 64 = 512 float4
        #pragma unroll
        for (int p = 0; p < 2; p++) {
            int e = p * 256 + tid;
            int k  = e >> 4;
            int c4 = e & 15;
            Vts[k][c4] = *reinterpret_cast<const float4*>(
                g_Vt + (size_t)(k0 + k) * FourH + colBase + c4 * 4);
        }
        __syncthreads();

        #pragma unroll
        for (int k = 0; k < 32; k++) {
            float4 u = Vts[k][tx];
            unsigned long long u01 = pk2(u.x, u.y);
            unsigned long long u23 = pk2(u.z, u.w);
            #pragma unroll
            for (int i = 0; i < 8; i++) {
                float a = Ps[ty + 16 * i][k];
                unsigned long long aa = pk2(a, a);
                ffma2(acc01[i], aa, u01);
                ffma2(acc23[i], aa, u23);
            }
        }
        __syncthreads();
    }

    // -------- fused epilogue --------
    int j = jBase + tx;                 // hidden unit, 0..1023
    const float4 cfx = *reinterpret_cast<const float4*>(g_cfx  + j * 4);
    const float4 cfh = *reinterpret_cast<const float4*>(g_cfh  + j * 4);
    const float4 bs  = *reinterpret_cast<const float4*>(g_bias + j * 4);
    const bool hasX = (j < In);
    const float dx = hasX ? dia_x[j] : 0.f;
    const float dh = dia_h[j];

    #pragma unroll
    for (int i = 0; i < 8; i++) {
        int b = rowBase + ty + 16 * i;
        float xv = hasX ? x[(size_t)b * In + j] : 0.f;
        float hv = h[(size_t)b * Hn + j];
        float cv = c[(size_t)b * Hn + j];
        float z  = dx * xv + dh * hv;

        float a0, a1, a2, a3;
        upk2(acc01[i], a0, a1);
        upk2(acc23[i], a2, a3);

        float gi = a0 - xv * cfx.x - hv * cfh.x + bs.x + z;
        float gf = a1 - xv * cfx.y - hv * cfh.y + bs.y + z;
        float go = a2 - xv * cfx.z - hv * cfh.z + bs.z + z;
        float gn = a3 - xv * cfx.w - hv * cfh.w + bs.w + z;

        float ig = 1.f / (1.f + expf(-gi));
        float fg = 1.f / (1.f + expf(-gf));
        float og = 1.f / (1.f + expf(-go));
        float ng = tanhf(gn);

        float cn = fg * cv + ig * ng;
        float hn = og * tanhf(cn);

        out[(size_t)b * Hn + j]                       = hn;   // h_next
        out[(size_t)Bn * Hn + (size_t)b * Hn + j]     = cn;   // c_next
    }
}

// ------------------------------------------------------------------
extern "C" void kernel_launch(void* const* d_in, const int* in_sizes, int n_in,
                              void* d_out, int out_size) {
    const float* x     = (const float*)d_in[0];
    const float* h     = (const float*)d_in[1];
    const float* c     = (const float*)d_in[2];
    const float* u_x   = (const float*)d_in[3];
    const float* u_h   = (const float*)d_in[4];
    const float* v_x   = (const float*)d_in[5];
    const float* v_h   = (const float*)d_in[6];
    const float* b_x   = (const float*)d_in[7];
    const float* b_h   = (const float*)d_in[8];
    const float* dia_x = (const float*)d_in[9];
    const float* dia_h = (const float*)d_in[10];
    float* out = (float*)d_out;

    // prep (tiny)
    prep_coef_kernel<<<FourH / 256, 256>>>(u_x, u_h, v_x, v_h, b_x, b_h);
    prep_vt_kernel<<<(128 * FourH) / 256, 256>>>(v_x, v_h);

    // P = [x@u_x | h@u_h]
    proj_kernel<<<Bn / 64, 256>>>(x, u_x, In, 0);
    proj_kernel<<<Bn / 64, 256>>>(h, u_h, Hn, 64);

    // gates GEMM + fused LSTM epilogue
    dim3 grid(FourH / 64, Bn / 128);
    main_kernel<<<grid, 256>>>(x, h, c, dia_x, dia_h, out);
}

// round 2
// speedup vs baseline: 1.6604x; 1.6604x over previous
#include <cuda_runtime.h>
#include <cuda_bf16.h>
#include <math.h>
#include <stdint.h>

#define Bn   8192
#define In   512
#define Hn   1024
#define Rn   64
#define FourH 4096

// ------------------------------------------------------------------
// Device scratch
// ------------------------------------------------------------------
__device__ __nv_bfloat16 g_Phi[Bn * 128];      // P hi  [B][128]
__device__ __nv_bfloat16 g_Plo[Bn * 128];      // P lo
__device__ __nv_bfloat16 g_Vthi[128 * FourH];  // Vt hi [k][4096], col = j*4+g
__device__ __nv_bfloat16 g_Vtlo[128 * FourH];  // Vt lo
__device__ float g_cfx[FourH];
__device__ float g_cfh[FourH];
__device__ float g_bias[FourH];

// ------------------------------------------------------------------
// PTX helpers
// ------------------------------------------------------------------
__device__ __forceinline__ uint32_t smem_u32(const void* p) {
    return (uint32_t)__cvta_generic_to_shared(p);
}
__device__ __forceinline__ void ldsm_x4(uint32_t* r, uint32_t a) {
    asm volatile("ldmatrix.sync.aligned.m8n8.x4.shared.b16 {%0,%1,%2,%3}, [%4];"
        : "=r"(r[0]), "=r"(r[1]), "=r"(r[2]), "=r"(r[3]) : "r"(a));
}
__device__ __forceinline__ void ldsm_x4_t(uint32_t* r, uint32_t a) {
    asm volatile("ldmatrix.sync.aligned.m8n8.x4.trans.shared.b16 {%0,%1,%2,%3}, [%4];"
        : "=r"(r[0]), "=r"(r[1]), "=r"(r[2]), "=r"(r[3]) : "r"(a));
}
__device__ __forceinline__ void mma16816(float* c, const uint32_t* a,
                                         uint32_t b0, uint32_t b1) {
    asm volatile("mma.sync.aligned.m16n8k16.row.col.f32.bf16.bf16.f32 "
        "{%0,%1,%2,%3}, {%4,%5,%6,%7}, {%8,%9}, {%0,%1,%2,%3};"
        : "+f"(c[0]), "+f"(c[1]), "+f"(c[2]), "+f"(c[3])
        : "r"(a[0]), "r"(a[1]), "r"(a[2]), "r"(a[3]), "r"(b0), "r"(b1));
}
__device__ __forceinline__ uint32_t pack_bf16(__nv_bfloat16 lo16, __nv_bfloat16 hi16) {
    return (uint32_t)__bfloat16_as_ushort(lo16) |
           ((uint32_t)__bfloat16_as_ushort(hi16) << 16);
}

// ------------------------------------------------------------------
// Prep 1: coefficients + fused bias (fp32, exact)
// ------------------------------------------------------------------
__global__ void prep_coef_kernel(const float* __restrict__ u_x,
                                 const float* __restrict__ u_h,
                                 const float* __restrict__ v_x,
                                 const float* __restrict__ v_h,
                                 const float* __restrict__ b_x,
                                 const float* __restrict__ b_h) {
    int idx = blockIdx.x * blockDim.x + threadIdx.x;   // j*4+g
    if (idx >= FourH) return;
    int j = idx >> 2;
    int g = idx & 3;
    int row4h = g * Hn + j;

    float cx = 0.f;
    if (j < In) {
        const float* uxr = u_x + j * Rn;
        const float* vxr = v_x + row4h * Rn;
        #pragma unroll 8
        for (int r = 0; r < Rn; r++) cx += uxr[r] * vxr[r];
    }
    float ch = 0.f;
    {
        const float* uhr = u_h + j * Rn;
        const float* vhr = v_h + row4h * Rn;
        #pragma unroll 8
        for (int r = 0; r < Rn; r++) ch += uhr[r] * vhr[r];
    }
    g_cfx[idx]  = cx;
    g_cfh[idx]  = ch;
    g_bias[idx] = b_x[row4h] + b_h[row4h];
}

// ------------------------------------------------------------------
// Prep 2: Vt hi/lo bf16   [k=0..127][col=j*4+g]
// ------------------------------------------------------------------
__global__ void prep_vt_kernel(const float* __restrict__ v_x,
                               const float* __restrict__ v_h) {
    int idx = blockIdx.x * blockDim.x + threadIdx.x;
    int r   = idx >> 12;
    int col = idx & (FourH - 1);
    int j = col >> 2;
    int g = col & 3;
    int row4h = g * Hn + j;
    float v = (r < 64) ? v_x[row4h * Rn + r] : v_h[row4h * Rn + (r - 64)];
    __nv_bfloat16 hi = __float2bfloat16(v);
    g_Vthi[idx] = hi;
    g_Vtlo[idx] = __float2bfloat16(v - __bfloat162float(hi));
}

// ------------------------------------------------------------------
// Projection: P[:,0:64] = x@u_x, P[:,64:128] = h@u_h, output bf16 hi/lo
// block: 256 thr, tile M=64, N=64, K-chunk 64. grid (128, 2)
// warps: 4(m) x 2(n); warp tile 16 x 32
// ------------------------------------------------------------------
__global__ __launch_bounds__(256)
void proj_kernel(const float* __restrict__ x, const float* __restrict__ u_x,
                 const float* __restrict__ h, const float* __restrict__ u_h) {
    __shared__ __nv_bfloat16 sA[2][64 * 72];   // [hi/lo][row][k], pad 72
    __shared__ __nv_bfloat16 sB[2][64 * 72];   // [hi/lo][k][n],  pad 72

    int tid = threadIdx.x;
    int lane = tid & 31, w = tid >> 5;
    int wm = w >> 1, wn = w & 1;

    int src = blockIdx.y;
    const float* A = src ? h   : x;
    const float* U = src ? u_h : u_x;
    int K       = src ? Hn : In;
    int colOff  = src ? 64 : 0;
    int rowBase = blockIdx.x * 64;

    float C[4][4];
    #pragma unroll
    for (int n = 0; n < 4; n++)
        #pragma unroll
        for (int q = 0; q < 4; q++) C[n][q] = 0.f;

    for (int k0 = 0; k0 < K; k0 += 64) {
        #pragma unroll
        for (int p = 0; p < 4; p++) {
            int e = p * 256 + tid;
            int row = e >> 4, c4 = e & 15;
            // A tile
            float4 v = *(const float4*)(A + (size_t)(rowBase + row) * K + k0 + c4 * 4);
            __nv_bfloat16 h0 = __float2bfloat16(v.x), h1 = __float2bfloat16(v.y);
            __nv_bfloat16 h2 = __float2bfloat16(v.z), h3 = __float2bfloat16(v.w);
            uint2 hv; hv.x = pack_bf16(h0, h1); hv.y = pack_bf16(h2, h3);
            *(uint2*)&sA[0][row * 72 + c4 * 4] = hv;
            uint2 lv;
            lv.x = pack_bf16(__float2bfloat16(v.x - __bfloat162float(h0)),
                             __float2bfloat16(v.y - __bfloat162float(h1)));
            lv.y = pack_bf16(__float2bfloat16(v.z - __bfloat162float(h2)),
                             __float2bfloat16(v.w - __bfloat162float(h3)));
            *(uint2*)&sA[1][row * 72 + c4 * 4] = lv;
            // B (u) tile: [k][n]
            float4 u = *(const float4*)(U + (size_t)(k0 + row) * 64 + c4 * 4);
            __nv_bfloat16 g0 = __float2bfloat16(u.x), g1 = __float2bfloat16(u.y);
            __nv_bfloat16 g2 = __float2bfloat16(u.z), g3 = __float2bfloat16(u.w);
            uint2 hu; hu.x = pack_bf16(g0, g1); hu.y = pack_bf16(g2, g3);
            *(uint2*)&sB[0][row * 72 + c4 * 4] = hu;
            uint2 lu;
            lu.x = pack_bf16(__float2bfloat16(u.x - __bfloat162float(g0)),
                             __float2bfloat16(u.y - __bfloat162float(g1)));
            lu.y = pack_bf16(__float2bfloat16(u.z - __bfloat162float(g2)),
                             __float2bfloat16(u.w - __bfloat162float(g3)));
            *(uint2*)&sB[1][row * 72 + c4 * 4] = lu;
        }
        __syncthreads();

        #pragma unroll
        for (int kk = 0; kk < 64; kk += 16) {
            uint32_t aH[4], aL[4];
            {
                int row = wm * 16 + (lane & 15);
                int col = kk + 8 * (lane >> 4);
                ldsm_x4(aH, smem_u32(&sA[0][row * 72 + col]));
                ldsm_x4(aL, smem_u32(&sA[1][row * 72 + col]));
            }
            uint32_t bH[4][2], bL[4][2];
            #pragma unroll
            for (int p = 0; p < 2; p++) {
                int kr = kk + (lane & 15);
                int nc = wn * 32 + p * 16 + 8 * (lane >> 4);
                uint32_t r[4];
                ldsm_x4_t(r, smem_u32(&sB[0][kr * 72 + nc]));
                bH[2 * p][0] = r[0]; bH[2 * p][1] = r[1];
                bH[2 * p + 1][0] = r[2]; bH[2 * p + 1][1] = r[3];
                ldsm_x4_t(r, smem_u32(&sB[1][kr * 72 + nc]));
                bL[2 * p][0] = r[0]; bL[2 * p][1] = r[1];
                bL[2 * p + 1][0] = r[2]; bL[2 * p + 1][1] = r[3];
            }
            #pragma unroll
            for (int n = 0; n < 4; n++) {
                mma16816(C[n], aH, bH[n][0], bH[n][1]);
                mma16816(C[n], aH, bL[n][0], bL[n][1]);
                mma16816(C[n], aL, bH[n][0], bH[n][1]);
            }
        }
        __syncthreads();
    }

    // write P hi/lo
    int quad = lane >> 2, a4 = lane & 3;
    #pragma unroll
    for (int n = 0; n < 4; n++) {
        int col = colOff + wn * 32 + n * 8 + a4 * 2;
        int r0  = rowBase + wm * 16 + quad;
        {
            __nv_bfloat16 h0 = __float2bfloat16(C[n][0]);
            __nv_bfloat16 h1 = __float2bfloat16(C[n][1]);
            *(uint32_t*)&g_Phi[(size_t)r0 * 128 + col] = pack_bf16(h0, h1);
            *(uint32_t*)&g_Plo[(size_t)r0 * 128 + col] =
                pack_bf16(__float2bfloat16(C[n][0] - __bfloat162float(h0)),
                          __float2bfloat16(C[n][1] - __bfloat162float(h1)));
        }
        {
            int r1 = r0 + 8;
            __nv_bfloat16 h2 = __float2bfloat16(C[n][2]);
            __nv_bfloat16 h3 = __float2bfloat16(C[n][3]);
            *(uint32_t*)&g_Phi[(size_t)r1 * 128 + col] = pack_bf16(h2, h3);
            *(uint32_t*)&g_Plo[(size_t)r1 * 128 + col] =
                pack_bf16(__float2bfloat16(C[n][2] - __bfloat162float(h2)),
                          __float2bfloat16(C[n][3] - __bfloat162float(h3)));
        }
    }
}

// ------------------------------------------------------------------
// Main GEMM (P @ Vt, K=128, bf16 3-pass) + fused LSTM epilogue
// block: 256 thr, tile M=128, N=128 gate-cols. warps 2(m) x 4(n); warp 64x32
// ------------------------------------------------------------------
#define SM_AHI 0
#define SM_ALO (128 * 72)
#define SM_BHI (2 * 128 * 72)
#define SM_BLO (2 * 128 * 72 + 64 * 136)
#define SM_ELEMS (2 * 128 * 72 + 2 * 64 * 136)

__global__ __launch_bounds__(256, 2)
void main_kernel(const float* __restrict__ x, const float* __restrict__ h,
                 const float* __restrict__ c,
                 const float* __restrict__ dia_x, const float* __restrict__ dia_h,
                 float* __restrict__ out) {
    extern __shared__ __nv_bfloat16 sm[];
    __nv_bfloat16* sAhi = sm + SM_AHI;
    __nv_bfloat16* sAlo = sm + SM_ALO;
    __nv_bfloat16* sBhi = sm + SM_BHI;
    __nv_bfloat16* sBlo = sm + SM_BLO;

    int tid = threadIdx.x;
    int lane = tid & 31, w = tid >> 5;
    int wm = w >> 2, wn = w & 3;
    int rowBase = blockIdx.y * 128;
    int colBase = blockIdx.x * 128;

    float C[4][4][4];
    #pragma unroll
    for (int m = 0; m < 4; m++)
        #pragma unroll
        for (int n = 0; n < 4; n++)
            #pragma unroll
            for (int q = 0; q < 4; q++) C[m][n][q] = 0.f;

    #pragma unroll
    for (int k0 = 0; k0 < 128; k0 += 64) {
        #pragma unroll
        for (int p = 0; p < 4; p++) {   // A: 128 rows x 64 k
            int e = p * 256 + tid;
            int row = e >> 3, cc = e & 7;
            *(uint4*)&sAhi[row * 72 + cc * 8] =
                *(const uint4*)&g_Phi[(size_t)(rowBase + row) * 128 + k0 + cc * 8];
            *(uint4*)&sAlo[row * 72 + cc * 8] =
                *(const uint4*)&g_Plo[(size_t)(rowBase + row) * 128 + k0 + cc * 8];
        }
        #pragma unroll
        for (int p = 0; p < 4; p++) {   // B: 64 k x 128 n
            int e = p * 256 + tid;
            int kr = e >> 4, cc = e & 15;
            *(uint4*)&sBhi[kr * 136 + cc * 8] =
                *(const uint4*)&g_Vthi[(size_t)(k0 + kr) * FourH + colBase + cc * 8];
            *(uint4*)&sBlo[kr * 136 + cc * 8] =
                *(const uint4*)&g_Vtlo[(size_t)(k0 + kr) * FourH + colBase + cc * 8];
        }
        __syncthreads();

        #pragma unroll
        for (int kk = 0; kk < 64; kk += 16) {
            uint32_t bH[4][2], bL[4][2];
            #pragma unroll
            for (int p = 0; p < 2; p++) {
                int kr = kk + (lane & 15);
                int nc = wn * 32 + p * 16 + 8 * (lane >> 4);
                uint32_t r[4];
                ldsm_x4_t(r, smem_u32(&sBhi[kr * 136 + nc]));
                bH[2 * p][0] = r[0]; bH[2 * p][1] = r[1];
                bH[2 * p + 1][0] = r[2]; bH[2 * p + 1][1] = r[3];
                ldsm_x4_t(r, smem_u32(&sBlo[kr * 136 + nc]));
                bL[2 * p][0] = r[0]; bL[2 * p][1] = r[1];
                bL[2 * p + 1][0] = r[2]; bL[2 * p + 1][1] = r[3];
            }
            #pragma unroll
            for (int m = 0; m < 4; m++) {
                uint32_t aH[4], aL[4];
                int row = wm * 64 + m * 16 + (lane & 15);
                int col = kk + 8 * (lane >> 4);
                ldsm_x4(aH, smem_u32(&sAhi[row * 72 + col]));
                ldsm_x4(aL, smem_u32(&sAlo[row * 72 + col]));
                #pragma unroll
                for (int n = 0; n < 4; n++) {
                    mma16816(C[m][n], aH, bH[n][0], bH[n][1]);
                    mma16816(C[m][n], aH, bL[n][0], bL[n][1]);
                    mma16816(C[m][n], aL, bH[n][0], bH[n][1]);
                }
            }
        }
        __syncthreads();
    }

    // ---------------- fused LSTM epilogue ----------------
    int quad = lane >> 2, a4 = lane & 3;
    bool oddA = (a4 & 1) != 0;
    int jBase = colBase >> 2;

    #pragma unroll
    for (int n = 0; n < 4; n++) {
        int j = jBase + wn * 8 + n * 2 + (a4 >> 1);
        float4 cfx = *(const float4*)(g_cfx  + j * 4);
        float4 cfh = *(const float4*)(g_cfh  + j * 4);
        float4 bs  = *(const float4*)(g_bias + j * 4);
        bool hasX = (j < In);
        float dxv = hasX ? dia_x[j] : 0.f;
        float dhv = dia_h[j];

        #pragma unroll
        for (int m = 0; m < 4; m++) {
            float p0 = __shfl_xor_sync(0xffffffffu, C[m][n][0], 1);
            float p1 = __shfl_xor_sync(0xffffffffu, C[m][n][1], 1);
            float p2 = __shfl_xor_sync(0xffffffffu, C[m][n][2], 1);
            float p3 = __shfl_xor_sync(0xffffffffu, C[m][n][3], 1);

            int b;
            float g0, g1, g2, g3;
            if (!oddA) {
                b = rowBase + wm * 64 + m * 16 + quad;
                g0 = C[m][n][0]; g1 = C[m][n][1]; g2 = p0; g3 = p1;
            } else {
                b = rowBase + wm * 64 + m * 16 + quad + 8;
                g0 = p2; g1 = p3; g2 = C[m][n][2]; g3 = C[m][n][3];
            }

            float xv = hasX ? x[(size_t)b * In + j] : 0.f;
            float hv = h[(size_t)b * Hn + j];
            float cv = c[(size_t)b * Hn + j];
            float z  = dxv * xv + dhv * hv;

            float gi = g0 - xv * cfx.x - hv * cfh.x + bs.x + z;
            float gf = g1 - xv * cfx.y - hv * cfh.y + bs.y + z;
            float go = g2 - xv * cfx.z - hv * cfh.z + bs.z + z;
            float gn = g3 - xv * cfx.w - hv * cfh.w + bs.w + z;

            float ig = 1.f / (1.f + expf(-gi));
            float fg = 1.f / (1.f + expf(-gf));
            float og = 1.f / (1.f + expf(-go));
            float ng = tanhf(gn);

            float cn = fg * cv + ig * ng;
            float hn = og * tanhf(cn);

            out[(size_t)b * Hn + j]                   = hn;
            out[(size_t)Bn * Hn + (size_t)b * Hn + j] = cn;
        }
    }
}

// ------------------------------------------------------------------
extern "C" void kernel_launch(void* const* d_in, const int* in_sizes, int n_in,
                              void* d_out, int out_size) {
    const float* x     = (const float*)d_in[0];
    const float* h     = (const float*)d_in[1];
    const float* c     = (const float*)d_in[2];
    const float* u_x   = (const float*)d_in[3];
    const float* u_h   = (const float*)d_in[4];
    const float* v_x   = (const float*)d_in[5];
    const float* v_h   = (const float*)d_in[6];
    const float* b_x   = (const float*)d_in[7];
    const float* b_h   = (const float*)d_in[8];
    const float* dia_x = (const float*)d_in[9];
    const float* dia_h = (const float*)d_in[10];
    float* out = (float*)d_out;

    prep_coef_kernel<<<FourH / 256, 256>>>(u_x, u_h, v_x, v_h, b_x, b_h);
    prep_vt_kernel<<<(128 * FourH) / 256, 256>>>(v_x, v_h);

    proj_kernel<<<dim3(Bn / 64, 2), 256>>>(x, u_x, h, u_h);

    size_t smem = SM_ELEMS * sizeof(__nv_bfloat16);   // 71680 B
    cudaFuncSetAttribute(main_kernel,
                         cudaFuncAttributeMaxDynamicSharedMemorySize, (int)smem);
    dim3 grid(FourH / 128, Bn / 128);
    main_kernel<<<grid, 256, smem>>>(x, h, c, dia_x, dia_h, out);
}

// round 4
// speedup vs baseline: 1.7334x; 1.0439x over previous
#include <cuda_runtime.h>
#include <cuda_bf16.h>
#include <math.h>
#include <stdint.h>

#define Bn   8192
#define In   512
#define Hn   1024
#define Rn   64
#define FourH 4096

// ------------------------------------------------------------------
// Device scratch
// ------------------------------------------------------------------
__device__ __nv_bfloat16 g_Phi[Bn * 128];      // P hi  [B][128]
__device__ __nv_bfloat16 g_Plo[Bn * 128];      // P lo
__device__ __nv_bfloat16 g_Vthi[128 * FourH];  // Vt hi [k][4096], col = j*4+g
__device__ __nv_bfloat16 g_Vtlo[128 * FourH];  // Vt lo
__device__ float g_cfx[FourH];
__device__ float g_cfh[FourH];
__device__ float g_bias[FourH];

// ------------------------------------------------------------------
// PTX helpers
// ------------------------------------------------------------------
__device__ __forceinline__ uint32_t smem_u32(const void* p) {
    return (uint32_t)__cvta_generic_to_shared(p);
}
__device__ __forceinline__ void ldsm_x4(uint32_t* r, uint32_t a) {
    asm volatile("ldmatrix.sync.aligned.m8n8.x4.shared.b16 {%0,%1,%2,%3}, [%4];"
        : "=r"(r[0]), "=r"(r[1]), "=r"(r[2]), "=r"(r[3]) : "r"(a));
}
__device__ __forceinline__ void ldsm_x4_t(uint32_t* r, uint32_t a) {
    asm volatile("ldmatrix.sync.aligned.m8n8.x4.trans.shared.b16 {%0,%1,%2,%3}, [%4];"
        : "=r"(r[0]), "=r"(r[1]), "=r"(r[2]), "=r"(r[3]) : "r"(a));
}
__device__ __forceinline__ void mma16816(float* c, const uint32_t* a,
                                         uint32_t b0, uint32_t b1) {
    asm volatile("mma.sync.aligned.m16n8k16.row.col.f32.bf16.bf16.f32 "
        "{%0,%1,%2,%3}, {%4,%5,%6,%7}, {%8,%9}, {%0,%1,%2,%3};"
        : "+f"(c[0]), "+f"(c[1]), "+f"(c[2]), "+f"(c[3])
        : "r"(a[0]), "r"(a[1]), "r"(a[2]), "r"(a[3]), "r"(b0), "r"(b1));
}
__device__ __forceinline__ uint32_t pack_bf16(__nv_bfloat16 lo16, __nv_bfloat16 hi16) {
    return (uint32_t)__bfloat16_as_ushort(lo16) |
           ((uint32_t)__bfloat16_as_ushort(hi16) << 16);
}
__device__ __forceinline__ void cpa16(uint32_t dst, const void* src) {
    asm volatile("cp.async.cg.shared.global [%0], [%1], 16;"
        :: "r"(dst), "l"(src) : "memory");
}
#define CP_COMMIT() asm volatile("cp.async.commit_group;" ::: "memory")
#define CP_WAIT1()  asm volatile("cp.async.wait_group 1;" ::: "memory")
#define CP_WAIT0()  asm volatile("cp.async.wait_group 0;" ::: "memory")

// ------------------------------------------------------------------
// Prep 1: coefficients + fused bias (fp32, exact)
// ------------------------------------------------------------------
__global__ void prep_coef_kernel(const float* __restrict__ u_x,
                                 const float* __restrict__ u_h,
                                 const float* __restrict__ v_x,
                                 const float* __restrict__ v_h,
                                 const float* __restrict__ b_x,
                                 const float* __restrict__ b_h) {
    int idx = blockIdx.x * blockDim.x + threadIdx.x;   // j*4+g
    if (idx >= FourH) return;
    int j = idx >> 2;
    int g = idx & 3;
    int row4h = g * Hn + j;

    float cx = 0.f;
    if (j < In) {
        const float* uxr = u_x + j * Rn;
        const float* vxr = v_x + row4h * Rn;
        #pragma unroll 8
        for (int r = 0; r < Rn; r++) cx += uxr[r] * vxr[r];
    }
    float ch = 0.f;
    {
        const float* uhr = u_h + j * Rn;
        const float* vhr = v_h + row4h * Rn;
        #pragma unroll 8
        for (int r = 0; r < Rn; r++) ch += uhr[r] * vhr[r];
    }
    g_cfx[idx]  = cx;
    g_cfh[idx]  = ch;
    g_bias[idx] = b_x[row4h] + b_h[row4h];
}

// ------------------------------------------------------------------
// Prep 2: Vt hi/lo bf16   [k=0..127][col=j*4+g]
// ------------------------------------------------------------------
__global__ void prep_vt_kernel(const float* __restrict__ v_x,
                               const float* __restrict__ v_h) {
    int idx = blockIdx.x * blockDim.x + threadIdx.x;
    int r   = idx >> 12;
    int col = idx & (FourH - 1);
    int j = col >> 2;
    int g = col & 3;
    int row4h = g * Hn + j;
    float v = (r < 64) ? v_x[row4h * Rn + r] : v_h[row4h * Rn + (r - 64)];
    __nv_bfloat16 hi = __float2bfloat16(v);
    g_Vthi[idx] = hi;
    g_Vtlo[idx] = __float2bfloat16(v - __bfloat162float(hi));
}

// ------------------------------------------------------------------
// Projection (HMMA): P[:,0:64]=x@u_x, P[:,64:128]=h@u_h (as round 2)
// ------------------------------------------------------------------
__global__ __launch_bounds__(256)
void proj_kernel(const float* __restrict__ x, const float* __restrict__ u_x,
                 const float* __restrict__ h, const float* __restrict__ u_h) {
    __shared__ __nv_bfloat16 sA[2][64 * 72];
    __shared__ __nv_bfloat16 sB[2][64 * 72];

    int tid = threadIdx.x;
    int lane = tid & 31, w = tid >> 5;
    int wm = w >> 1, wn = w & 1;

    int src = blockIdx.y;
    const float* A = src ? h   : x;
    const float* U = src ? u_h : u_x;
    int K       = src ? Hn : In;
    int colOff  = src ? 64 : 0;
    int rowBase = blockIdx.x * 64;

    float C[4][4];
    #pragma unroll
    for (int n = 0; n < 4; n++)
        #pragma unroll
        for (int q = 0; q < 4; q++) C[n][q] = 0.f;

    for (int k0 = 0; k0 < K; k0 += 64) {
        #pragma unroll
        for (int p = 0; p < 4; p++) {
            int e = p * 256 + tid;
            int row = e >> 4, c4 = e & 15;
            float4 v = *(const float4*)(A + (size_t)(rowBase + row) * K + k0 + c4 * 4);
            __nv_bfloat16 h0 = __float2bfloat16(v.x), h1 = __float2bfloat16(v.y);
            __nv_bfloat16 h2 = __float2bfloat16(v.z), h3 = __float2bfloat16(v.w);
            uint2 hv; hv.x = pack_bf16(h0, h1); hv.y = pack_bf16(h2, h3);
            *(uint2*)&sA[0][row * 72 + c4 * 4] = hv;
            uint2 lv;
            lv.x = pack_bf16(__float2bfloat16(v.x - __bfloat162float(h0)),
                             __float2bfloat16(v.y - __bfloat162float(h1)));
            lv.y = pack_bf16(__float2bfloat16(v.z - __bfloat162float(h2)),
                             __float2bfloat16(v.w - __bfloat162float(h3)));
            *(uint2*)&sA[1][row * 72 + c4 * 4] = lv;
            float4 u = *(const float4*)(U + (size_t)(k0 + row) * 64 + c4 * 4);
            __nv_bfloat16 g0 = __float2bfloat16(u.x), g1 = __float2bfloat16(u.y);
            __nv_bfloat16 g2 = __float2bfloat16(u.z), g3 = __float2bfloat16(u.w);
            uint2 hu; hu.x = pack_bf16(g0, g1); hu.y = pack_bf16(g2, g3);
            *(uint2*)&sB[0][row * 72 + c4 * 4] = hu;
            uint2 lu;
            lu.x = pack_bf16(__float2bfloat16(u.x - __bfloat162float(g0)),
                             __float2bfloat16(u.y - __bfloat162float(g1)));
            lu.y = pack_bf16(__float2bfloat16(u.z - __bfloat162float(g2)),
                             __float2bfloat16(u.w - __bfloat162float(g3)));
            *(uint2*)&sB[1][row * 72 + c4 * 4] = lu;
        }
        __syncthreads();

        #pragma unroll
        for (int kk = 0; kk < 64; kk += 16) {
            uint32_t aH[4], aL[4];
            {
                int row = wm * 16 + (lane & 15);
                int col = kk + 8 * (lane >> 4);
                ldsm_x4(aH, smem_u32(&sA[0][row * 72 + col]));
                ldsm_x4(aL, smem_u32(&sA[1][row * 72 + col]));
            }
            uint32_t bH[4][2], bL[4][2];
            #pragma unroll
            for (int p = 0; p < 2; p++) {
                int kr = kk + (lane & 15);
                int nc = wn * 32 + p * 16 + 8 * (lane >> 4);
                uint32_t r[4];
                ldsm_x4_t(r, smem_u32(&sB[0][kr * 72 + nc]));
                bH[2 * p][0] = r[0]; bH[2 * p][1] = r[1];
                bH[2 * p + 1][0] = r[2]; bH[2 * p + 1][1] = r[3];
                ldsm_x4_t(r, smem_u32(&sB[1][kr * 72 + nc]));
                bL[2 * p][0] = r[0]; bL[2 * p][1] = r[1];
                bL[2 * p + 1][0] = r[2]; bL[2 * p + 1][1] = r[3];
            }
            #pragma unroll
            for (int n = 0; n < 4; n++) {
                mma16816(C[n], aH, bH[n][0], bH[n][1]);
                mma16816(C[n], aH, bL[n][0], bL[n][1]);
                mma16816(C[n], aL, bH[n][0], bH[n][1]);
            }
        }
        __syncthreads();
    }

    int quad = lane >> 2, a4 = lane & 3;
    #pragma unroll
    for (int n = 0; n < 4; n++) {
        int col = colOff + wn * 32 + n * 8 + a4 * 2;
        int r0  = rowBase + wm * 16 + quad;
        {
            __nv_bfloat16 h0 = __float2bfloat16(C[n][0]);
            __nv_bfloat16 h1 = __float2bfloat16(C[n][1]);
            *(uint32_t*)&g_Phi[(size_t)r0 * 128 + col] = pack_bf16(h0, h1);
            *(uint32_t*)&g_Plo[(size_t)r0 * 128 + col] =
                pack_bf16(__float2bfloat16(C[n][0] - __bfloat162float(h0)),
                          __float2bfloat16(C[n][1] - __bfloat162float(h1)));
        }
        {
            int r1 = r0 + 8;
            __nv_bfloat16 h2 = __float2bfloat16(C[n][2]);
            __nv_bfloat16 h3 = __float2bfloat16(C[n][3]);
            *(uint32_t*)&g_Phi[(size_t)r1 * 128 + col] = pack_bf16(h2, h3);
            *(uint32_t*)&g_Plo[(size_t)r1 * 128 + col] =
                pack_bf16(__float2bfloat16(C[n][2] - __bfloat162float(h2)),
                          __float2bfloat16(C[n][3] - __bfloat162float(h3)));
        }
    }
}

// ------------------------------------------------------------------
// Main GEMM (P @ Vt, K=128, bf16 3-pass) + fused LSTM epilogue.
// cp.async 2-stage pipeline over four 32-k chunks.
// block: 256 thr, tile M=128 x N=128. warps 2(m) x 4(n); warp 64x32.
// Stage layout (bf16 units): Ahi[128][40], Alo[128][40], Bhi[32][136], Blo[32][136]
// ------------------------------------------------------------------
#define AST 40
#define BST 136
#define U_AHI 0
#define U_ALO (128 * AST)
#define U_BHI (2 * 128 * AST)
#define U_BLO (2 * 128 * AST + 32 * BST)
#define STAGE_UNITS (2 * 128 * AST + 2 * 32 * BST)   // 18944 units = 37888 B
#define SMEM_TOTAL (2 * STAGE_UNITS * 2)             // bytes: 75776

__global__ __launch_bounds__(256, 2)
void main_kernel(const float* __restrict__ x, const float* __restrict__ h,
                 const float* __restrict__ c,
                 const float* __restrict__ dia_x, const float* __restrict__ dia_h,
                 float* __restrict__ out) {
    extern __shared__ __nv_bfloat16 sm[];

    int tid = threadIdx.x;
    int lane = tid & 31, w = tid >> 5;
    int wm = w >> 2, wn = w & 3;
    int rowBase = blockIdx.y * 128;
    int colBase = blockIdx.x * 128;

    uint32_t sbase = smem_u32(sm);

    // ---- cp.async chunk loader (k-chunk of 32) ----
    auto load_chunk = [&](int k0, int stage) {
        uint32_t sb = sbase + stage * STAGE_UNITS * 2;
        #pragma unroll
        for (int t = 0; t < 8; t++) {
            int e = t * 256 + tid;
            int part = e >> 9, wi = e & 511;
            if (part < 2) {
                const __nv_bfloat16* g = part ? g_Plo : g_Phi;
                int r = wi >> 2, cc = wi & 3;
                cpa16(sb + (part ? U_ALO : U_AHI) * 2 + (r * AST + cc * 8) * 2,
                      g + (size_t)(rowBase + r) * 128 + k0 + cc * 8);
            } else {
                const __nv_bfloat16* g = (part == 3) ? g_Vtlo : g_Vthi;
                int kr = wi >> 4, cc = wi & 15;
                cpa16(sb + ((part == 3) ? U_BLO : U_BHI) * 2 + (kr * BST + cc * 8) * 2,
                      g + (size_t)(k0 + kr) * FourH + colBase + cc * 8);
            }
        }
        CP_COMMIT();
    };

    float C[4][4][4];
    #pragma unroll
    for (int m = 0; m < 4; m++)
        #pragma unroll
        for (int n = 0; n < 4; n++)
            #pragma unroll
            for (int q = 0; q < 4; q++) C[m][n][q] = 0.f;

    load_chunk(0, 0);
    load_chunk(32, 1);

    #pragma unroll
    for (int ck = 0; ck < 4; ck++) {
        if (ck < 3) { CP_WAIT1(); } else { CP_WAIT0(); }
        __syncthreads();

        __nv_bfloat16* sAhi = sm + (ck & 1) * STAGE_UNITS + U_AHI;
        __nv_bfloat16* sAlo = sm + (ck & 1) * STAGE_UNITS + U_ALO;
        __nv_bfloat16* sBhi = sm + (ck & 1) * STAGE_UNITS + U_BHI;
        __nv_bfloat16* sBlo = sm + (ck & 1) * STAGE_UNITS + U_BLO;

        #pragma unroll
        for (int kk = 0; kk < 32; kk += 16) {
            uint32_t bH[4][2], bL[4][2];
            #pragma unroll
            for (int p = 0; p < 2; p++) {
                int kr = kk + (lane & 15);
                int nc = wn * 32 + p * 16 + 8 * (lane >> 4);
                uint32_t r[4];
                ldsm_x4_t(r, smem_u32(&sBhi[kr * BST + nc]));
                bH[2 * p][0] = r[0]; bH[2 * p][1] = r[1];
                bH[2 * p + 1][0] = r[2]; bH[2 * p + 1][1] = r[3];
                ldsm_x4_t(r, smem_u32(&sBlo[kr * BST + nc]));
                bL[2 * p][0] = r[0]; bL[2 * p][1] = r[1];
                bL[2 * p + 1][0] = r[2]; bL[2 * p + 1][1] = r[3];
            }
            #pragma unroll
            for (int m = 0; m < 4; m++) {
                uint32_t aH[4], aL[4];
                int row = wm * 64 + m * 16 + (lane & 15);
                int col = kk + 8 * (lane >> 4);
                ldsm_x4(aH, smem_u32(&sAhi[row * AST + col]));
                ldsm_x4(aL, smem_u32(&sAlo[row * AST + col]));
                #pragma unroll
                for (int n = 0; n < 4; n++) {
                    mma16816(C[m][n], aH, bH[n][0], bH[n][1]);
                    mma16816(C[m][n], aH, bL[n][0], bL[n][1]);
                    mma16816(C[m][n], aL, bH[n][0], bH[n][1]);
                }
            }
        }
        __syncthreads();
        if (ck < 2) load_chunk((ck + 2) * 32, ck & 1);
    }

    // ---------------- fused LSTM epilogue ----------------
    int quad = lane >> 2, a4 = lane & 3;
    bool oddA = (a4 & 1) != 0;
    int jBase = colBase >> 2;

    #pragma unroll
    for (int n = 0; n < 4; n++) {
        int j = jBase + wn * 8 + n * 2 + (a4 >> 1);
        float4 cfx = *(const float4*)(g_cfx  + j * 4);
        float4 cfh = *(const float4*)(g_cfh  + j * 4);
        float4 bs  = *(const float4*)(g_bias + j * 4);
        bool hasX = (j < In);
        float dxv = hasX ? dia_x[j] : 0.f;
        float dhv = dia_h[j];

        #pragma unroll
        for (int m = 0; m < 4; m++) {
            float p0 = __shfl_xor_sync(0xffffffffu, C[m][n][0], 1);
            float p1 = __shfl_xor_sync(0xffffffffu, C[m][n][1], 1);
            float p2 = __shfl_xor_sync(0xffffffffu, C[m][n][2], 1);
            float p3 = __shfl_xor_sync(0xffffffffu, C[m][n][3], 1);

            int b;
            float g0, g1, g2, g3;
            if (!oddA) {
                b = rowBase + wm * 64 + m * 16 + quad;
                g0 = C[m][n][0]; g1 = C[m][n][1]; g2 = p0; g3 = p1;
            } else {
                b = rowBase + wm * 64 + m * 16 + quad + 8;
                g0 = p2; g1 = p3; g2 = C[m][n][2]; g3 = C[m][n][3];
            }

            float xv = hasX ? x[(size_t)b * In + j] : 0.f;
            float hv = h[(size_t)b * Hn + j];
            float cv = c[(size_t)b * Hn + j];
            float z  = dxv * xv + dhv * hv;

            float gi = g0 - xv * cfx.x - hv * cfh.x + bs.x + z;
            float gf = g1 - xv * cfx.y - hv * cfh.y + bs.y + z;
            float go = g2 - xv * cfx.z - hv * cfh.z + bs.z + z;
            float gn = g3 - xv * cfx.w - hv * cfh.w + bs.w + z;

            float ig = 1.f / (1.f + expf(-gi));
            float fg = 1.f / (1.f + expf(-gf));
            float og = 1.f / (1.f + expf(-go));
            float ng = tanhf(gn);

            float cn = fg * cv + ig * ng;
            float hn = og * tanhf(cn);

            out[(size_t)b * Hn + j]                   = hn;
            out[(size_t)Bn * Hn + (size_t)b * Hn + j] = cn;
        }
    }
}

// ------------------------------------------------------------------
extern "C" void kernel_launch(void* const* d_in, const int* in_sizes, int n_in,
                              void* d_out, int out_size) {
    const float* x     = (const float*)d_in[0];
    const float* h     = (const float*)d_in[1];
    const float* c     = (const float*)d_in[2];
    const float* u_x   = (const float*)d_in[3];
    const float* u_h   = (const float*)d_in[4];
    const float* v_x   = (const float*)d_in[5];
    const float* v_h   = (const float*)d_in[6];
    const float* b_x   = (const float*)d_in[7];
    const float* b_h   = (const float*)d_in[8];
    const float* dia_x = (const float*)d_in[9];
    const float* dia_h = (const float*)d_in[10];
    float* out = (float*)d_out;

    prep_coef_kernel<<<FourH / 256, 256>>>(u_x, u_h, v_x, v_h, b_x, b_h);
    prep_vt_kernel<<<(128 * FourH) / 256, 256>>>(v_x, v_h);

    proj_kernel<<<dim3(Bn / 64, 2), 256>>>(x, u_x, h, u_h);

    cudaFuncSetAttribute(main_kernel,
                         cudaFuncAttributeMaxDynamicSharedMemorySize, SMEM_TOTAL);
    dim3 grid(FourH / 128, Bn / 128);
    main_kernel<<<grid, 256, SMEM_TOTAL>>>(x, h, c, dia_x, dia_h, out);
}

// round 5
// speedup vs baseline: 1.7516x; 1.0105x over previous
#include <cuda_runtime.h>
#include <cuda_bf16.h>
#include <math.h>
#include <stdint.h>

#define Bn   8192
#define In   512
#define Hn   1024
#define Rn   64
#define FourH 4096

// ------------------------------------------------------------------
// Device scratch
// ------------------------------------------------------------------
__device__ __nv_bfloat16 g_Phi[Bn * 128];      // P hi  [B][128]
__device__ __nv_bfloat16 g_Plo[Bn * 128];      // P lo
__device__ __nv_bfloat16 g_Vthi[128 * FourH];  // Vt hi [k][4096], col = j*4+g
__device__ __nv_bfloat16 g_Vtlo[128 * FourH];  // Vt lo
__device__ float g_cfx[FourH];
__device__ float g_cfh[FourH];
__device__ float g_bias[FourH];

// ------------------------------------------------------------------
// PTX helpers
// ------------------------------------------------------------------
__device__ __forceinline__ uint32_t smem_u32(const void* p) {
    return (uint32_t)__cvta_generic_to_shared(p);
}
__device__ __forceinline__ void ldsm_x4(uint32_t* r, uint32_t a) {
    asm volatile("ldmatrix.sync.aligned.m8n8.x4.shared.b16 {%0,%1,%2,%3}, [%4];"
        : "=r"(r[0]), "=r"(r[1]), "=r"(r[2]), "=r"(r[3]) : "r"(a));
}
__device__ __forceinline__ void ldsm_x4_t(uint32_t* r, uint32_t a) {
    asm volatile("ldmatrix.sync.aligned.m8n8.x4.trans.shared.b16 {%0,%1,%2,%3}, [%4];"
        : "=r"(r[0]), "=r"(r[1]), "=r"(r[2]), "=r"(r[3]) : "r"(a));
}
__device__ __forceinline__ void mma16816(float* c, const uint32_t* a,
                                         uint32_t b0, uint32_t b1) {
    asm volatile("mma.sync.aligned.m16n8k16.row.col.f32.bf16.bf16.f32 "
        "{%0,%1,%2,%3}, {%4,%5,%6,%7}, {%8,%9}, {%0,%1,%2,%3};"
        : "+f"(c[0]), "+f"(c[1]), "+f"(c[2]), "+f"(c[3])
        : "r"(a[0]), "r"(a[1]), "r"(a[2]), "r"(a[3]), "r"(b0), "r"(b1));
}
__device__ __forceinline__ uint32_t pack_bf16(__nv_bfloat16 lo16, __nv_bfloat16 hi16) {
    return (uint32_t)__bfloat16_as_ushort(lo16) |
           ((uint32_t)__bfloat16_as_ushort(hi16) << 16);
}
__device__ __forceinline__ void cpa16(uint32_t dst, const void* src) {
    asm volatile("cp.async.cg.shared.global [%0], [%1], 16;"
        :: "r"(dst), "l"(src) : "memory");
}
#define CP_COMMIT() asm volatile("cp.async.commit_group;" ::: "memory")
#define CP_WAIT1()  asm volatile("cp.async.wait_group 1;" ::: "memory")
#define CP_WAIT0()  asm volatile("cp.async.wait_group 0;" ::: "memory")

// ------------------------------------------------------------------
// Prep 1: coefficients + fused bias (fp32, exact)
// ------------------------------------------------------------------
__global__ void prep_coef_kernel(const float* __restrict__ u_x,
                                 const float* __restrict__ u_h,
                                 const float* __restrict__ v_x,
                                 const float* __restrict__ v_h,
                                 const float* __restrict__ b_x,
                                 const float* __restrict__ b_h) {
    int idx = blockIdx.x * blockDim.x + threadIdx.x;   // j*4+g
    if (idx >= FourH) return;
    int j = idx >> 2;
    int g = idx & 3;
    int row4h = g * Hn + j;

    float cx = 0.f;
    if (j < In) {
        const float* uxr = u_x + j * Rn;
        const float* vxr = v_x + row4h * Rn;
        #pragma unroll 8
        for (int r = 0; r < Rn; r++) cx += uxr[r] * vxr[r];
    }
    float ch = 0.f;
    {
        const float* uhr = u_h + j * Rn;
        const float* vhr = v_h + row4h * Rn;
        #pragma unroll 8
        for (int r = 0; r < Rn; r++) ch += uhr[r] * vhr[r];
    }
    g_cfx[idx]  = cx;
    g_cfh[idx]  = ch;
    g_bias[idx] = b_x[row4h] + b_h[row4h];
}

// ------------------------------------------------------------------
// Prep 2: Vt hi/lo bf16   [k=0..127][col=j*4+g]
// ------------------------------------------------------------------
__global__ void prep_vt_kernel(const float* __restrict__ v_x,
                               const float* __restrict__ v_h) {
    int idx = blockIdx.x * blockDim.x + threadIdx.x;
    int r   = idx >> 12;
    int col = idx & (FourH - 1);
    int j = col >> 2;
    int g = col & 3;
    int row4h = g * Hn + j;
    float v = (r < 64) ? v_x[row4h * Rn + r] : v_h[row4h * Rn + (r - 64)];
    __nv_bfloat16 hi = __float2bfloat16(v);
    g_Vthi[idx] = hi;
    g_Vtlo[idx] = __float2bfloat16(v - __bfloat162float(hi));
}

// ------------------------------------------------------------------
// Projection (HMMA): P[:,0:64]=x@u_x, P[:,64:128]=h@u_h
// ------------------------------------------------------------------
__global__ __launch_bounds__(256)
void proj_kernel(const float* __restrict__ x, const float* __restrict__ u_x,
                 const float* __restrict__ h, const float* __restrict__ u_h) {
    __shared__ __nv_bfloat16 sA[2][64 * 72];
    __shared__ __nv_bfloat16 sB[2][64 * 72];

    int tid = threadIdx.x;
    int lane = tid & 31, w = tid >> 5;
    int wm = w >> 1, wn = w & 1;

    int src = blockIdx.y;
    const float* A = src ? h   : x;
    const float* U = src ? u_h : u_x;
    int K       = src ? Hn : In;
    int colOff  = src ? 64 : 0;
    int rowBase = blockIdx.x * 64;

    float C[4][4];
    #pragma unroll
    for (int n = 0; n < 4; n++)
        #pragma unroll
        for (int q = 0; q < 4; q++) C[n][q] = 0.f;

    for (int k0 = 0; k0 < K; k0 += 64) {
        #pragma unroll
        for (int p = 0; p < 4; p++) {
            int e = p * 256 + tid;
            int row = e >> 4, c4 = e & 15;
            float4 v = *(const float4*)(A + (size_t)(rowBase + row) * K + k0 + c4 * 4);
            __nv_bfloat16 h0 = __float2bfloat16(v.x), h1 = __float2bfloat16(v.y);
            __nv_bfloat16 h2 = __float2bfloat16(v.z), h3 = __float2bfloat16(v.w);
            uint2 hv; hv.x = pack_bf16(h0, h1); hv.y = pack_bf16(h2, h3);
            *(uint2*)&sA[0][row * 72 + c4 * 4] = hv;
            uint2 lv;
            lv.x = pack_bf16(__float2bfloat16(v.x - __bfloat162float(h0)),
                             __float2bfloat16(v.y - __bfloat162float(h1)));
            lv.y = pack_bf16(__float2bfloat16(v.z - __bfloat162float(h2)),
                             __float2bfloat16(v.w - __bfloat162float(h3)));
            *(uint2*)&sA[1][row * 72 + c4 * 4] = lv;
            float4 u = *(const float4*)(U + (size_t)(k0 + row) * 64 + c4 * 4);
            __nv_bfloat16 g0 = __float2bfloat16(u.x), g1 = __float2bfloat16(u.y);
            __nv_bfloat16 g2 = __float2bfloat16(u.z), g3 = __float2bfloat16(u.w);
            uint2 hu; hu.x = pack_bf16(g0, g1); hu.y = pack_bf16(g2, g3);
            *(uint2*)&sB[0][row * 72 + c4 * 4] = hu;
            uint2 lu;
            lu.x = pack_bf16(__float2bfloat16(u.x - __bfloat162float(g0)),
                             __float2bfloat16(u.y - __bfloat162float(g1)));
            lu.y = pack_bf16(__float2bfloat16(u.z - __bfloat162float(g2)),
                             __float2bfloat16(u.w - __bfloat162float(g3)));
            *(uint2*)&sB[1][row * 72 + c4 * 4] = lu;
        }
        __syncthreads();

        #pragma unroll
        for (int kk = 0; kk < 64; kk += 16) {
            uint32_t aH[4], aL[4];
            {
                int row = wm * 16 + (lane & 15);
                int col = kk + 8 * (lane >> 4);
                ldsm_x4(aH, smem_u32(&sA[0][row * 72 + col]));
                ldsm_x4(aL, smem_u32(&sA[1][row * 72 + col]));
            }
            uint32_t bH[4][2], bL[4][2];
            #pragma unroll
            for (int p = 0; p < 2; p++) {
                int kr = kk + (lane & 15);
                int nc = wn * 32 + p * 16 + 8 * (lane >> 4);
                uint32_t r[4];
                ldsm_x4_t(r, smem_u32(&sB[0][kr * 72 + nc]));
                bH[2 * p][0] = r[0]; bH[2 * p][1] = r[1];
                bH[2 * p + 1][0] = r[2]; bH[2 * p + 1][1] = r[3];
                ldsm_x4_t(r, smem_u32(&sB[1][kr * 72 + nc]));
                bL[2 * p][0] = r[0]; bL[2 * p][1] = r[1];
                bL[2 * p + 1][0] = r[2]; bL[2 * p + 1][1] = r[3];
            }
            #pragma unroll
            for (int n = 0; n < 4; n++) {
                mma16816(C[n], aH, bH[n][0], bH[n][1]);
                mma16816(C[n], aH, bL[n][0], bL[n][1]);
                mma16816(C[n], aL, bH[n][0], bH[n][1]);
            }
        }
        __syncthreads();
    }

    int quad = lane >> 2, a4 = lane & 3;
    #pragma unroll
    for (int n = 0; n < 4; n++) {
        int col = colOff + wn * 32 + n * 8 + a4 * 2;
        int r0  = rowBase + wm * 16 + quad;
        {
            __nv_bfloat16 h0 = __float2bfloat16(C[n][0]);
            __nv_bfloat16 h1 = __float2bfloat16(C[n][1]);
            *(uint32_t*)&g_Phi[(size_t)r0 * 128 + col] = pack_bf16(h0, h1);
            *(uint32_t*)&g_Plo[(size_t)r0 * 128 + col] =
                pack_bf16(__float2bfloat16(C[n][0] - __bfloat162float(h0)),
                          __float2bfloat16(C[n][1] - __bfloat162float(h1)));
        }
        {
            int r1 = r0 + 8;
            __nv_bfloat16 h2 = __float2bfloat16(C[n][2]);
            __nv_bfloat16 h3 = __float2bfloat16(C[n][3]);
            *(uint32_t*)&g_Phi[(size_t)r1 * 128 + col] = pack_bf16(h2, h3);
            *(uint32_t*)&g_Plo[(size_t)r1 * 128 + col] =
                pack_bf16(__float2bfloat16(C[n][2] - __bfloat162float(h2)),
                          __float2bfloat16(C[n][3] - __bfloat162float(h3)));
        }
    }
}

// ------------------------------------------------------------------
// Main GEMM (P @ Vt, K=128, bf16 3-pass) + fused LSTM epilogue.
// Retiled for occupancy: CTA tile M=64 x N=128, 256 thr, 8 warps (2m x 4n),
// warp tile 32x32, C=32 regs. 2-stage cp.async over four 32-k chunks.
// Stage layout (bf16 units): Ahi[64][40], Alo[64][40], Bhi[32][136], Blo[32][136]
// ------------------------------------------------------------------
#define AST 40
#define BST 136
#define U_AHI 0
#define U_ALO (64 * AST)
#define U_BHI (2 * 64 * AST)
#define U_BLO (2 * 64 * AST + 32 * BST)
#define STAGE_UNITS (2 * 64 * AST + 2 * 32 * BST)    // 13824 units = 27648 B
#define SMEM_TOTAL (2 * STAGE_UNITS * 2)             // 55296 B

__global__ __launch_bounds__(256, 3)
void main_kernel(const float* __restrict__ x, const float* __restrict__ h,
                 const float* __restrict__ c,
                 const float* __restrict__ dia_x, const float* __restrict__ dia_h,
                 float* __restrict__ out) {
    extern __shared__ __nv_bfloat16 sm[];

    int tid = threadIdx.x;
    int lane = tid & 31, w = tid >> 5;
    int wm = w >> 2, wn = w & 3;
    int rowBase = blockIdx.y * 64;
    int colBase = blockIdx.x * 128;

    uint32_t sbase = smem_u32(sm);

    // ---- cp.async chunk loader (k-chunk of 32): 1536 x 16B chunks ----
    auto load_chunk = [&](int k0, int stage) {
        uint32_t sb = sbase + stage * STAGE_UNITS * 2;
        // A: 512 chunks (hi 256, lo 256)
        #pragma unroll
        for (int t = 0; t < 2; t++) {
            int e = t * 256 + tid;
            const __nv_bfloat16* g = (e >> 8) ? g_Plo : g_Phi;
            uint32_t uoff = (e >> 8) ? U_ALO : U_AHI;
            int wi = e & 255;
            int r = wi >> 2, cc = wi & 3;
            cpa16(sb + uoff * 2 + (r * AST + cc * 8) * 2,
                  g + (size_t)(rowBase + r) * 128 + k0 + cc * 8);
        }
        // B: 1024 chunks (hi 512, lo 512)
        #pragma unroll
        for (int t = 0; t < 4; t++) {
            int e = t * 256 + tid;
            const __nv_bfloat16* g = (e >> 9) ? g_Vtlo : g_Vthi;
            uint32_t uoff = (e >> 9) ? U_BLO : U_BHI;
            int wi = e & 511;
            int kr = wi >> 4, cc = wi & 15;
            cpa16(sb + uoff * 2 + (kr * BST + cc * 8) * 2,
                  g + (size_t)(k0 + kr) * FourH + colBase + cc * 8);
        }
        CP_COMMIT();
    };

    float C[2][4][4];
    #pragma unroll
    for (int m = 0; m < 2; m++)
        #pragma unroll
        for (int n = 0; n < 4; n++)
            #pragma unroll
            for (int q = 0; q < 4; q++) C[m][n][q] = 0.f;

    load_chunk(0, 0);
    load_chunk(32, 1);

    #pragma unroll
    for (int ck = 0; ck < 4; ck++) {
        if (ck < 3) { CP_WAIT1(); } else { CP_WAIT0(); }
        __syncthreads();

        __nv_bfloat16* sAhi = sm + (ck & 1) * STAGE_UNITS + U_AHI;
        __nv_bfloat16* sAlo = sm + (ck & 1) * STAGE_UNITS + U_ALO;
        __nv_bfloat16* sBhi = sm + (ck & 1) * STAGE_UNITS + U_BHI;
        __nv_bfloat16* sBlo = sm + (ck & 1) * STAGE_UNITS + U_BLO;

        #pragma unroll
        for (int kk = 0; kk < 32; kk += 16) {
            uint32_t bH[4][2], bL[4][2];
            #pragma unroll
            for (int p = 0; p < 2; p++) {
                int kr = kk + (lane & 15);
                int nc = wn * 32 + p * 16 + 8 * (lane >> 4);
                uint32_t r[4];
                ldsm_x4_t(r, smem_u32(&sBhi[kr * BST + nc]));
                bH[2 * p][0] = r[0]; bH[2 * p][1] = r[1];
                bH[2 * p + 1][0] = r[2]; bH[2 * p + 1][1] = r[3];
                ldsm_x4_t(r, smem_u32(&sBlo[kr * BST + nc]));
                bL[2 * p][0] = r[0]; bL[2 * p][1] = r[1];
                bL[2 * p + 1][0] = r[2]; bL[2 * p + 1][1] = r[3];
            }
            #pragma unroll
            for (int m = 0; m < 2; m++) {
                uint32_t aH[4], aL[4];
                int row = wm * 32 + m * 16 + (lane & 15);
                int col = kk + 8 * (lane >> 4);
                ldsm_x4(aH, smem_u32(&sAhi[row * AST + col]));
                ldsm_x4(aL, smem_u32(&sAlo[row * AST + col]));
                #pragma unroll
                for (int n = 0; n < 4; n++) {
                    mma16816(C[m][n], aH, bH[n][0], bH[n][1]);
                    mma16816(C[m][n], aH, bL[n][0], bL[n][1]);
                    mma16816(C[m][n], aL, bH[n][0], bH[n][1]);
                }
            }
        }
        __syncthreads();
        if (ck < 2) load_chunk((ck + 2) * 32, ck & 1);
    }

    // ---------------- fused LSTM epilogue ----------------
    int quad = lane >> 2, a4 = lane & 3;
    bool oddA = (a4 & 1) != 0;
    int jBase = colBase >> 2;

    #pragma unroll
    for (int n = 0; n < 4; n++) {
        int j = jBase + wn * 8 + n * 2 + (a4 >> 1);
        float4 cfx = *(const float4*)(g_cfx  + j * 4);
        float4 cfh = *(const float4*)(g_cfh  + j * 4);
        float4 bs  = *(const float4*)(g_bias + j * 4);
        bool hasX = (j < In);
        float dxv = hasX ? dia_x[j] : 0.f;
        float dhv = dia_h[j];

        #pragma unroll
        for (int m = 0; m < 2; m++) {
            float p0 = __shfl_xor_sync(0xffffffffu, C[m][n][0], 1);
            float p1 = __shfl_xor_sync(0xffffffffu, C[m][n][1], 1);
            float p2 = __shfl_xor_sync(0xffffffffu, C[m][n][2], 1);
            float p3 = __shfl_xor_sync(0xffffffffu, C[m][n][3], 1);

            int b;
            float g0, g1, g2, g3;
            if (!oddA) {
                b = rowBase + wm * 32 + m * 16 + quad;
                g0 = C[m][n][0]; g1 = C[m][n][1]; g2 = p0; g3 = p1;
            } else {
                b = rowBase + wm * 32 + m * 16 + quad + 8;
                g0 = p2; g1 = p3; g2 = C[m][n][2]; g3 = C[m][n][3];
            }

            float xv = hasX ? x[(size_t)b * In + j] : 0.f;
            float hv = h[(size_t)b * Hn + j];
            float cv = c[(size_t)b * Hn + j];
            float z  = dxv * xv + dhv * hv;

            float gi = g0 - xv * cfx.x - hv * cfh.x + bs.x + z;
            float gf = g1 - xv * cfx.y - hv * cfh.y + bs.y + z;
            float go = g2 - xv * cfx.z - hv * cfh.z + bs.z + z;
            float gn = g3 - xv * cfx.w - hv * cfh.w + bs.w + z;

            float ig = 1.f / (1.f + expf(-gi));
            float fg = 1.f / (1.f + expf(-gf));
            float og = 1.f / (1.f + expf(-go));
            float ng = tanhf(gn);

            float cn = fg * cv + ig * ng;
            float hn = og * tanhf(cn);

            out[(size_t)b * Hn + j]                   = hn;
            out[(size_t)Bn * Hn + (size_t)b * Hn + j] = cn;
        }
    }
}

// ------------------------------------------------------------------
extern "C" void kernel_launch(void* const* d_in, const int* in_sizes, int n_in,
                              void* d_out, int out_size) {
    const float* x     = (const float*)d_in[0];
    const float* h     = (const float*)d_in[1];
    const float* c     = (const float*)d_in[2];
    const float* u_x   = (const float*)d_in[3];
    const float* u_h   = (const float*)d_in[4];
    const float* v_x   = (const float*)d_in[5];
    const float* v_h   = (const float*)d_in[6];
    const float* b_x   = (const float*)d_in[7];
    const float* b_h   = (const float*)d_in[8];
    const float* dia_x = (const float*)d_in[9];
    const float* dia_h = (const float*)d_in[10];
    float* out = (float*)d_out;

    prep_coef_kernel<<<FourH / 256, 256>>>(u_x, u_h, v_x, v_h, b_x, b_h);
    prep_vt_kernel<<<(128 * FourH) / 256, 256>>>(v_x, v_h);

    proj_kernel<<<dim3(Bn / 64, 2), 256>>>(x, u_x, h, u_h);

    cudaFuncSetAttribute(main_kernel,
                         cudaFuncAttributeMaxDynamicSharedMemorySize, SMEM_TOTAL);
    dim3 grid(FourH / 128, Bn / 64);
    main_kernel<<<grid, 256, SMEM_TOTAL>>>(x, h, c, dia_x, dia_h, out);
}

// round 6
// speedup vs baseline: 2.1183x; 1.2093x over previous
#include <cuda_runtime.h>
#include <cuda_bf16.h>
#include <math.h>
#include <stdint.h>

#define Bn   8192
#define In   512
#define Hn   1024
#define Rn   64
#define FourH 4096
#define SLAB (Bn * 64)

// ------------------------------------------------------------------
// Device scratch
// ------------------------------------------------------------------
__device__ __nv_bfloat16 g_Phi[Bn * 128];      // P hi  [B][128]
__device__ __nv_bfloat16 g_Plo[Bn * 128];      // P lo
__device__ __nv_bfloat16 g_Vthi[128 * FourH];  // Vt hi [k][4096], col = j*4+g
__device__ __nv_bfloat16 g_Vtlo[128 * FourH];  // Vt lo
__device__ float g_Pp[6 * SLAB];               // proj partial slabs
__device__ float g_cfx[FourH];
__device__ float g_cfh[FourH];
__device__ float g_bias[FourH];

// ------------------------------------------------------------------
// PTX helpers
// ------------------------------------------------------------------
__device__ __forceinline__ uint32_t smem_u32(const void* p) {
    return (uint32_t)__cvta_generic_to_shared(p);
}
__device__ __forceinline__ void ldsm_x4(uint32_t* r, uint32_t a) {
    asm volatile("ldmatrix.sync.aligned.m8n8.x4.shared.b16 {%0,%1,%2,%3}, [%4];"
        : "=r"(r[0]), "=r"(r[1]), "=r"(r[2]), "=r"(r[3]) : "r"(a));
}
__device__ __forceinline__ void ldsm_x4_t(uint32_t* r, uint32_t a) {
    asm volatile("ldmatrix.sync.aligned.m8n8.x4.trans.shared.b16 {%0,%1,%2,%3}, [%4];"
        : "=r"(r[0]), "=r"(r[1]), "=r"(r[2]), "=r"(r[3]) : "r"(a));
}
__device__ __forceinline__ void mma16816(float* c, const uint32_t* a,
                                         uint32_t b0, uint32_t b1) {
    asm volatile("mma.sync.aligned.m16n8k16.row.col.f32.bf16.bf16.f32 "
        "{%0,%1,%2,%3}, {%4,%5,%6,%7}, {%8,%9}, {%0,%1,%2,%3};"
        : "+f"(c[0]), "+f"(c[1]), "+f"(c[2]), "+f"(c[3])
        : "r"(a[0]), "r"(a[1]), "r"(a[2]), "r"(a[3]), "r"(b0), "r"(b1));
}
__device__ __forceinline__ uint32_t pack_bf16(__nv_bfloat16 lo16, __nv_bfloat16 hi16) {
    return (uint32_t)__bfloat16_as_ushort(lo16) |
           ((uint32_t)__bfloat16_as_ushort(hi16) << 16);
}
__device__ __forceinline__ void cpa16(uint32_t dst, const void* src) {
    asm volatile("cp.async.cg.shared.global [%0], [%1], 16;"
        :: "r"(dst), "l"(src) : "memory");
}
#define CP_COMMIT() asm volatile("cp.async.commit_group;" ::: "memory")
#define CP_WAIT1()  asm volatile("cp.async.wait_group 1;" ::: "memory")
#define CP_WAIT0()  asm volatile("cp.async.wait_group 0;" ::: "memory")

// ------------------------------------------------------------------
// Prep 1: coefficients + fused bias (fp32, exact)
// ------------------------------------------------------------------
__global__ void prep_coef_kernel(const float* __restrict__ u_x,
                                 const float* __restrict__ u_h,
                                 const float* __restrict__ v_x,
                                 const float* __restrict__ v_h,
                                 const float* __restrict__ b_x,
                                 const float* __restrict__ b_h) {
    int idx = blockIdx.x * blockDim.x + threadIdx.x;   // j*4+g
    if (idx >= FourH) return;
    int j = idx >> 2;
    int g = idx & 3;
    int row4h = g * Hn + j;

    float cx = 0.f;
    if (j < In) {
        const float* uxr = u_x + j * Rn;
        const float* vxr = v_x + row4h * Rn;
        #pragma unroll 8
        for (int r = 0; r < Rn; r++) cx += uxr[r] * vxr[r];
    }
    float ch = 0.f;
    {
        const float* uhr = u_h + j * Rn;
        const float* vhr = v_h + row4h * Rn;
        #pragma unroll 8
        for (int r = 0; r < Rn; r++) ch += uhr[r] * vhr[r];
    }
    g_cfx[idx]  = cx;
    g_cfh[idx]  = ch;
    g_bias[idx] = b_x[row4h] + b_h[row4h];
}

// ------------------------------------------------------------------
// Prep 2: Vt hi/lo bf16   [k=0..127][col=j*4+g]
// ------------------------------------------------------------------
__global__ void prep_vt_kernel(const float* __restrict__ v_x,
                               const float* __restrict__ v_h) {
    int idx = blockIdx.x * blockDim.x + threadIdx.x;
    int r   = idx >> 12;
    int col = idx & (FourH - 1);
    int j = col >> 2;
    int g = col & 3;
    int row4h = g * Hn + j;
    float v = (r < 64) ? v_x[row4h * Rn + r] : v_h[row4h * Rn + (r - 64)];
    __nv_bfloat16 hi = __float2bfloat16(v);
    g_Vthi[idx] = hi;
    g_Vtlo[idx] = __float2bfloat16(v - __bfloat162float(hi));
}

// ------------------------------------------------------------------
// Projection split-K partials: grid (128 row-tiles, 6 K-slices).
// slice 0-1: x @ u_x[k-slice]   (K=512, two 256-slices)  -> slabs 0,1
// slice 2-5: h @ u_h[k-slice]   (K=1024, four 256-slices)-> slabs 2..5
// CTA: 64 rows x 64 cols, 8 warps (4m x 2n), warp 16x32, 3-pass bf16 HMMA.
// ------------------------------------------------------------------
__global__ __launch_bounds__(256)
void proj_part_kernel(const float* __restrict__ x, const float* __restrict__ u_x,
                      const float* __restrict__ h, const float* __restrict__ u_h) {
    __shared__ __nv_bfloat16 sA[2][64 * 72];
    __shared__ __nv_bfloat16 sB[2][64 * 72];

    int tid = threadIdx.x;
    int lane = tid & 31, w = tid >> 5;
    int wm = w >> 1, wn = w & 1;

    int slice = blockIdx.y;
    bool isX = (slice < 2);
    const float* A = isX ? x   : h;
    const float* U = isX ? u_x : u_h;
    int K      = isX ? In : Hn;
    int kBase  = (isX ? slice : (slice - 2)) * 256;
    int rowBase = blockIdx.x * 64;
    float* outSlab = g_Pp + (size_t)slice * SLAB;

    float C[4][4];
    #pragma unroll
    for (int n = 0; n < 4; n++)
        #pragma unroll
        for (int q = 0; q < 4; q++) C[n][q] = 0.f;

    #pragma unroll
    for (int kc = 0; kc < 4; kc++) {
        int k0 = kBase + kc * 64;
        #pragma unroll
        for (int p = 0; p < 4; p++) {
            int e = p * 256 + tid;
            int row = e >> 4, c4 = e & 15;
            float4 v = *(const float4*)(A + (size_t)(rowBase + row) * K + k0 + c4 * 4);
            __nv_bfloat16 h0 = __float2bfloat16(v.x), h1 = __float2bfloat16(v.y);
            __nv_bfloat16 h2 = __float2bfloat16(v.z), h3 = __float2bfloat16(v.w);
            uint2 hv; hv.x = pack_bf16(h0, h1); hv.y = pack_bf16(h2, h3);
            *(uint2*)&sA[0][row * 72 + c4 * 4] = hv;
            uint2 lv;
            lv.x = pack_bf16(__float2bfloat16(v.x - __bfloat162float(h0)),
                             __float2bfloat16(v.y - __bfloat162float(h1)));
            lv.y = pack_bf16(__float2bfloat16(v.z - __bfloat162float(h2)),
                             __float2bfloat16(v.w - __bfloat162float(h3)));
            *(uint2*)&sA[1][row * 72 + c4 * 4] = lv;
            float4 u = *(const float4*)(U + (size_t)(k0 + row) * 64 + c4 * 4);
            __nv_bfloat16 g0 = __float2bfloat16(u.x), g1 = __float2bfloat16(u.y);
            __nv_bfloat16 g2 = __float2bfloat16(u.z), g3 = __float2bfloat16(u.w);
            uint2 hu; hu.x = pack_bf16(g0, g1); hu.y = pack_bf16(g2, g3);
            *(uint2*)&sB[0][row * 72 + c4 * 4] = hu;
            uint2 lu;
            lu.x = pack_bf16(__float2bfloat16(u.x - __bfloat162float(g0)),
                             __float2bfloat16(u.y - __bfloat162float(g1)));
            lu.y = pack_bf16(__float2bfloat16(u.z - __bfloat162float(g2)),
                             __float2bfloat16(u.w - __bfloat162float(g3)));
            *(uint2*)&sB[1][row * 72 + c4 * 4] = lu;
        }
        __syncthreads();

        #pragma unroll
        for (int kk = 0; kk < 64; kk += 16) {
            uint32_t aH[4], aL[4];
            {
                int row = wm * 16 + (lane & 15);
                int col = kk + 8 * (lane >> 4);
                ldsm_x4(aH, smem_u32(&sA[0][row * 72 + col]));
                ldsm_x4(aL, smem_u32(&sA[1][row * 72 + col]));
            }
            uint32_t bH[4][2], bL[4][2];
            #pragma unroll
            for (int p = 0; p < 2; p++) {
                int kr = kk + (lane & 15);
                int nc = wn * 32 + p * 16 + 8 * (lane >> 4);
                uint32_t r[4];
                ldsm_x4_t(r, smem_u32(&sB[0][kr * 72 + nc]));
                bH[2 * p][0] = r[0]; bH[2 * p][1] = r[1];
                bH[2 * p + 1][0] = r[2]; bH[2 * p + 1][1] = r[3];
                ldsm_x4_t(r, smem_u32(&sB[1][kr * 72 + nc]));
                bL[2 * p][0] = r[0]; bL[2 * p][1] = r[1];
                bL[2 * p + 1][0] = r[2]; bL[2 * p + 1][1] = r[3];
            }
            #pragma unroll
            for (int n = 0; n < 4; n++) {
                mma16816(C[n], aH, bH[n][0], bH[n][1]);
                mma16816(C[n], aH, bL[n][0], bL[n][1]);
                mma16816(C[n], aL, bH[n][0], bH[n][1]);
            }
        }
        __syncthreads();
    }

    // write fp32 partial
    int quad = lane >> 2, a4 = lane & 3;
    #pragma unroll
    for (int n = 0; n < 4; n++) {
        int col = wn * 32 + n * 8 + a4 * 2;
        int r0  = rowBase + wm * 16 + quad;
        *(float2*)(outSlab + (size_t)r0 * 64 + col) = make_float2(C[n][0], C[n][1]);
        *(float2*)(outSlab + (size_t)(r0 + 8) * 64 + col) = make_float2(C[n][2], C[n][3]);
    }
}

// ------------------------------------------------------------------
// Combine: sum partial slabs, emit P hi/lo bf16.
// ------------------------------------------------------------------
__global__ __launch_bounds__(256)
void combine_kernel() {
    int idx = blockIdx.x * 256 + threadIdx.x;     // 0 .. Bn*32-1
    int row = idx >> 5;
    int c4  = idx & 31;
    int col = c4 * 4;

    float4 v;
    if (col < 64) {
        const float* p = g_Pp + (size_t)row * 64 + col;
        float4 a = *(const float4*)p;
        float4 b = *(const float4*)(p + SLAB);
        v = make_float4(a.x + b.x, a.y + b.y, a.z + b.z, a.w + b.w);
    } else {
        const float* p = g_Pp + 2 * (size_t)SLAB + (size_t)row * 64 + (col - 64);
        float4 a = *(const float4*)p;
        float4 b = *(const float4*)(p + SLAB);
        float4 cc = *(const float4*)(p + 2 * (size_t)SLAB);
        float4 d = *(const float4*)(p + 3 * (size_t)SLAB);
        v = make_float4(a.x + b.x + cc.x + d.x, a.y + b.y + cc.y + d.y,
                        a.z + b.z + cc.z + d.z, a.w + b.w + cc.w + d.w);
    }

    __nv_bfloat16 h0 = __float2bfloat16(v.x), h1 = __float2bfloat16(v.y);
    __nv_bfloat16 h2 = __float2bfloat16(v.z), h3 = __float2bfloat16(v.w);
    uint2 hv; hv.x = pack_bf16(h0, h1); hv.y = pack_bf16(h2, h3);
    *(uint2*)&g_Phi[(size_t)row * 128 + col] = hv;
    uint2 lv;
    lv.x = pack_bf16(__float2bfloat16(v.x - __bfloat162float(h0)),
                     __float2bfloat16(v.y - __bfloat162float(h1)));
    lv.y = pack_bf16(__float2bfloat16(v.z - __bfloat162float(h2)),
                     __float2bfloat16(v.w - __bfloat162float(h3)));
    *(uint2*)&g_Plo[(size_t)row * 128 + col] = lv;
}

// ------------------------------------------------------------------
// Main GEMM (P @ Vt, K=128, bf16 3-pass) + smem-staged coalesced epilogue.
// CTA tile M=64 x N=128, 256 thr, 8 warps (2m x 4n), warp 32x32.
// ------------------------------------------------------------------
#define AST 40
#define BST 136
#define U_AHI 0
#define U_ALO (64 * AST)
#define U_BHI (2 * 64 * AST)
#define U_BLO (2 * 64 * AST + 32 * BST)
#define STAGE_UNITS (2 * 64 * AST + 2 * 32 * BST)    // 13824 units = 27648 B
#define SMEM_TOTAL (2 * STAGE_UNITS * 2)             // 55296 B
#define CST 132                                      // epilogue C stage stride (floats)

__global__ __launch_bounds__(256, 3)
void main_kernel(const float* __restrict__ x, const float* __restrict__ h,
                 const float* __restrict__ c,
                 const float* __restrict__ dia_x, const float* __restrict__ dia_h,
                 float* __restrict__ out) {
    extern __shared__ __nv_bfloat16 sm[];

    int tid = threadIdx.x;
    int lane = tid & 31, w = tid >> 5;
    int wm = w >> 2, wn = w & 3;
    int rowBase = blockIdx.y * 64;
    int colBase = blockIdx.x * 128;

    uint32_t sbase = smem_u32(sm);

    auto load_chunk = [&](int k0, int stage) {
        uint32_t sb = sbase + stage * STAGE_UNITS * 2;
        #pragma unroll
        for (int t = 0; t < 2; t++) {
            int e = t * 256 + tid;
            const __nv_bfloat16* g = (e >> 8) ? g_Plo : g_Phi;
            uint32_t uoff = (e >> 8) ? U_ALO : U_AHI;
            int wi = e & 255;
            int r = wi >> 2, cc = wi & 3;
            cpa16(sb + uoff * 2 + (r * AST + cc * 8) * 2,
                  g + (size_t)(rowBase + r) * 128 + k0 + cc * 8);
        }
        #pragma unroll
        for (int t = 0; t < 4; t++) {
            int e = t * 256 + tid;
            const __nv_bfloat16* g = (e >> 9) ? g_Vtlo : g_Vthi;
            uint32_t uoff = (e >> 9) ? U_BLO : U_BHI;
            int wi = e & 511;
            int kr = wi >> 4, cc = wi & 15;
            cpa16(sb + uoff * 2 + (kr * BST + cc * 8) * 2,
                  g + (size_t)(k0 + kr) * FourH + colBase + cc * 8);
        }
        CP_COMMIT();
    };

    float C[2][4][4];
    #pragma unroll
    for (int m = 0; m < 2; m++)
        #pragma unroll
        for (int n = 0; n < 4; n++)
            #pragma unroll
            for (int q = 0; q < 4; q++) C[m][n][q] = 0.f;

    load_chunk(0, 0);
    load_chunk(32, 1);

    #pragma unroll
    for (int ck = 0; ck < 4; ck++) {
        if (ck < 3) { CP_WAIT1(); } else { CP_WAIT0(); }
        __syncthreads();

        __nv_bfloat16* sAhi = sm + (ck & 1) * STAGE_UNITS + U_AHI;
        __nv_bfloat16* sAlo = sm + (ck & 1) * STAGE_UNITS + U_ALO;
        __nv_bfloat16* sBhi = sm + (ck & 1) * STAGE_UNITS + U_BHI;
        __nv_bfloat16* sBlo = sm + (ck & 1) * STAGE_UNITS + U_BLO;

        #pragma unroll
        for (int kk = 0; kk < 32; kk += 16) {
            uint32_t bH[4][2], bL[4][2];
            #pragma unroll
            for (int p = 0; p < 2; p++) {
                int kr = kk + (lane & 15);
                int nc = wn * 32 + p * 16 + 8 * (lane >> 4);
                uint32_t r[4];
                ldsm_x4_t(r, smem_u32(&sBhi[kr * BST + nc]));
                bH[2 * p][0] = r[0]; bH[2 * p][1] = r[1];
                bH[2 * p + 1][0] = r[2]; bH[2 * p + 1][1] = r[3];
                ldsm_x4_t(r, smem_u32(&sBlo[kr * BST + nc]));
                bL[2 * p][0] = r[0]; bL[2 * p][1] = r[1];
                bL[2 * p + 1][0] = r[2]; bL[2 * p + 1][1] = r[3];
            }
            #pragma unroll
            for (int m = 0; m < 2; m++) {
                uint32_t aH[4], aL[4];
                int row = wm * 32 + m * 16 + (lane & 15);
                int col = kk + 8 * (lane >> 4);
                ldsm_x4(aH, smem_u32(&sAhi[row * AST + col]));
                ldsm_x4(aL, smem_u32(&sAlo[row * AST + col]));
                #pragma unroll
                for (int n = 0; n < 4; n++) {
                    mma16816(C[m][n], aH, bH[n][0], bH[n][1]);
                    mma16816(C[m][n], aH, bL[n][0], bL[n][1]);
                    mma16816(C[m][n], aL, bH[n][0], bH[n][1]);
                }
            }
        }
        __syncthreads();
        if (ck < 2) load_chunk((ck + 2) * 32, ck & 1);
    }

    // ---------------- epilogue: stage C in smem, coalesced I/O ----------------
    float* sC = (float*)sm;       // 64 x CST fp32 = 33792 B (fits in 55296)
    int quad = lane >> 2, a4 = lane & 3;

    #pragma unroll
    for (int n = 0; n < 4; n++) {
        int col = wn * 32 + n * 8 + a4 * 2;
        #pragma unroll
        for (int m = 0; m < 2; m++) {
            int r0 = wm * 32 + m * 16 + quad;
            *(float2*)&sC[r0 * CST + col]       = make_float2(C[m][n][0], C[m][n][1]);
            *(float2*)&sC[(r0 + 8) * CST + col] = make_float2(C[m][n][2], C[m][n][3]);
        }
    }
    __syncthreads();

    int jl = tid & 31;                 // hidden unit within tile (const per thread)
    int j  = (colBase >> 2) + jl;
    bool hasX = (j < In);              // uniform per CTA

    float4 cfx = *(const float4*)(g_cfx  + (size_t)j * 4);
    float4 cfh = *(const float4*)(g_cfh  + (size_t)j * 4);
    float4 bs  = *(const float4*)(g_bias + (size_t)j * 4);
    float dxv = hasX ? dia_x[j] : 0.f;
    float dhv = dia_h[j];

    #pragma unroll
    for (int pass = 0; pass < 8; pass++) {
        int bl = pass * 8 + (tid >> 5);
        int b  = rowBase + bl;

        float4 g4 = *(const float4*)&sC[bl * CST + jl * 4];
        float xv = hasX ? x[(size_t)b * In + j] : 0.f;
        float hv = h[(size_t)b * Hn + j];
        float cv = c[(size_t)b * Hn + j];
        float z  = dxv * xv + dhv * hv;

        float gi = g4.x - xv * cfx.x - hv * cfh.x + bs.x + z;
        float gf = g4.y - xv * cfx.y - hv * cfh.y + bs.y + z;
        float go = g4.z - xv * cfx.z - hv * cfh.z + bs.z + z;
        float gn = g4.w - xv * cfx.w - hv * cfh.w + bs.w + z;

        float ig = 1.f / (1.f + expf(-gi));
        float fg = 1.f / (1.f + expf(-gf));
        float og = 1.f / (1.f + expf(-go));
        float ng = tanhf(gn);

        float cn = fg * cv + ig * ng;
        float hn = og * tanhf(cn);

        out[(size_t)b * Hn + j]                   = hn;
        out[(size_t)Bn * Hn + (size_t)b * Hn + j] = cn;
    }
}

// ------------------------------------------------------------------
extern "C" void kernel_launch(void* const* d_in, const int* in_sizes, int n_in,
                              void* d_out, int out_size) {
    const float* x     = (const float*)d_in[0];
    const float* h     = (const float*)d_in[1];
    const float* c     = (const float*)d_in[2];
    const float* u_x   = (const float*)d_in[3];
    const float* u_h   = (const float*)d_in[4];
    const float* v_x   = (const float*)d_in[5];
    const float* v_h   = (const float*)d_in[6];
    const float* b_x   = (const float*)d_in[7];
    const float* b_h   = (const float*)d_in[8];
    const float* dia_x = (const float*)d_in[9];
    const float* dia_h = (const float*)d_in[10];
    float* out = (float*)d_out;

    prep_coef_kernel<<<FourH / 256, 256>>>(u_x, u_h, v_x, v_h, b_x, b_h);
    prep_vt_kernel<<<(128 * FourH) / 256, 256>>>(v_x, v_h);

    proj_part_kernel<<<dim3(Bn / 64, 6), 256>>>(x, u_x, h, u_h);
    combine_kernel<<<(Bn * 32) / 256, 256>>>();

    cudaFuncSetAttribute(main_kernel,
                         cudaFuncAttributeMaxDynamicSharedMemorySize, SMEM_TOTAL);
    dim3 grid(FourH / 128, Bn / 64);
    main_kernel<<<grid, 256, SMEM_TOTAL>>>(x, h, c, dia_x, dia_h, out);
}

// round 7
// speedup vs baseline: 2.2946x; 1.0832x over previous
#include <cuda_runtime.h>
#include <cuda_bf16.h>
#include <cuda_fp16.h>
#include <math.h>
#include <stdint.h>

#define Bn   8192
#define In   512
#define Hn   1024
#define Rn   64
#define FourH 4096
#define SLAB (Bn * 64)

// ------------------------------------------------------------------
// Device scratch
// ------------------------------------------------------------------
__device__ __half g_Pf[Bn * 128];          // P fp16 [B][128]
__device__ __half g_Vthi[128 * FourH];     // Vt hi fp16 [k][4096], col = j*4+g
__device__ __half g_Vtlo[128 * FourH];     // Vt lo fp16
__device__ float g_Pp[6 * SLAB];           // proj partial slabs
__device__ float g_cfx[FourH];
__device__ float g_cfh[FourH];
__device__ float g_bias[FourH];

// ------------------------------------------------------------------
// PTX helpers
// ------------------------------------------------------------------
__device__ __forceinline__ uint32_t smem_u32(const void* p) {
    return (uint32_t)__cvta_generic_to_shared(p);
}
__device__ __forceinline__ void ldsm_x4(uint32_t* r, uint32_t a) {
    asm volatile("ldmatrix.sync.aligned.m8n8.x4.shared.b16 {%0,%1,%2,%3}, [%4];"
        : "=r"(r[0]), "=r"(r[1]), "=r"(r[2]), "=r"(r[3]) : "r"(a));
}
__device__ __forceinline__ void ldsm_x4_t(uint32_t* r, uint32_t a) {
    asm volatile("ldmatrix.sync.aligned.m8n8.x4.trans.shared.b16 {%0,%1,%2,%3}, [%4];"
        : "=r"(r[0]), "=r"(r[1]), "=r"(r[2]), "=r"(r[3]) : "r"(a));
}
// bf16 mma (proj)
__device__ __forceinline__ void mma16816(float* c, const uint32_t* a,
                                         uint32_t b0, uint32_t b1) {
    asm volatile("mma.sync.aligned.m16n8k16.row.col.f32.bf16.bf16.f32 "
        "{%0,%1,%2,%3}, {%4,%5,%6,%7}, {%8,%9}, {%0,%1,%2,%3};"
        : "+f"(c[0]), "+f"(c[1]), "+f"(c[2]), "+f"(c[3])
        : "r"(a[0]), "r"(a[1]), "r"(a[2]), "r"(a[3]), "r"(b0), "r"(b1));
}
// fp16 mma (main)
__device__ __forceinline__ void mma16816h(float* c, const uint32_t* a,
                                          uint32_t b0, uint32_t b1) {
    asm volatile("mma.sync.aligned.m16n8k16.row.col.f32.f16.f16.f32 "
        "{%0,%1,%2,%3}, {%4,%5,%6,%7}, {%8,%9}, {%0,%1,%2,%3};"
        : "+f"(c[0]), "+f"(c[1]), "+f"(c[2]), "+f"(c[3])
        : "r"(a[0]), "r"(a[1]), "r"(a[2]), "r"(a[3]), "r"(b0), "r"(b1));
}
__device__ __forceinline__ uint32_t pack_bf16(__nv_bfloat16 lo16, __nv_bfloat16 hi16) {
    return (uint32_t)__bfloat16_as_ushort(lo16) |
           ((uint32_t)__bfloat16_as_ushort(hi16) << 16);
}
__device__ __forceinline__ uint32_t pack_f16(__half lo16, __half hi16) {
    return (uint32_t)__half_as_ushort(lo16) |
           ((uint32_t)__half_as_ushort(hi16) << 16);
}
__device__ __forceinline__ void cpa16(uint32_t dst, const void* src) {
    asm volatile("cp.async.cg.shared.global [%0], [%1], 16;"
        :: "r"(dst), "l"(src) : "memory");
}
#define CP_COMMIT() asm volatile("cp.async.commit_group;" ::: "memory")
#define CP_WAIT1()  asm volatile("cp.async.wait_group 1;" ::: "memory")
#define CP_WAIT0()  asm volatile("cp.async.wait_group 0;" ::: "memory")

// ------------------------------------------------------------------
// Prep 1: coefficients + fused bias (fp32, exact)
// ------------------------------------------------------------------
__global__ void prep_coef_kernel(const float* __restrict__ u_x,
                                 const float* __restrict__ u_h,
                                 const float* __restrict__ v_x,
                                 const float* __restrict__ v_h,
                                 const float* __restrict__ b_x,
                                 const float* __restrict__ b_h) {
    int idx = blockIdx.x * blockDim.x + threadIdx.x;   // j*4+g
    if (idx >= FourH) return;
    int j = idx >> 2;
    int g = idx & 3;
    int row4h = g * Hn + j;

    float cx = 0.f;
    if (j < In) {
        const float* uxr = u_x + j * Rn;
        const float* vxr = v_x + row4h * Rn;
        #pragma unroll 8
        for (int r = 0; r < Rn; r++) cx += uxr[r] * vxr[r];
    }
    float ch = 0.f;
    {
        const float* uhr = u_h + j * Rn;
        const float* vhr = v_h + row4h * Rn;
        #pragma unroll 8
        for (int r = 0; r < Rn; r++) ch += uhr[r] * vhr[r];
    }
    g_cfx[idx]  = cx;
    g_cfh[idx]  = ch;
    g_bias[idx] = b_x[row4h] + b_h[row4h];
}

// ------------------------------------------------------------------
// Prep 2: Vt hi/lo fp16   [k=0..127][col=j*4+g]
// ------------------------------------------------------------------
__global__ void prep_vt_kernel(const float* __restrict__ v_x,
                               const float* __restrict__ v_h) {
    int idx = blockIdx.x * blockDim.x + threadIdx.x;
    int r   = idx >> 12;
    int col = idx & (FourH - 1);
    int j = col >> 2;
    int g = col & 3;
    int row4h = g * Hn + j;
    float v = (r < 64) ? v_x[row4h * Rn + r] : v_h[row4h * Rn + (r - 64)];
    __half hi = __float2half(v);
    g_Vthi[idx] = hi;
    g_Vtlo[idx] = __float2half(v - __half2float(hi));
}

// ------------------------------------------------------------------
// Projection split-K partials (bf16 3-pass HMMA, fp32 out) — as round 6.
// ------------------------------------------------------------------
__global__ __launch_bounds__(256)
void proj_part_kernel(const float* __restrict__ x, const float* __restrict__ u_x,
                      const float* __restrict__ h, const float* __restrict__ u_h) {
    __shared__ __nv_bfloat16 sA[2][64 * 72];
    __shared__ __nv_bfloat16 sB[2][64 * 72];

    int tid = threadIdx.x;
    int lane = tid & 31, w = tid >> 5;
    int wm = w >> 1, wn = w & 1;

    int slice = blockIdx.y;
    bool isX = (slice < 2);
    const float* A = isX ? x   : h;
    const float* U = isX ? u_x : u_h;
    int K      = isX ? In : Hn;
    int kBase  = (isX ? slice : (slice - 2)) * 256;
    int rowBase = blockIdx.x * 64;
    float* outSlab = g_Pp + (size_t)slice * SLAB;

    float C[4][4];
    #pragma unroll
    for (int n = 0; n < 4; n++)
        #pragma unroll
        for (int q = 0; q < 4; q++) C[n][q] = 0.f;

    #pragma unroll
    for (int kc = 0; kc < 4; kc++) {
        int k0 = kBase + kc * 64;
        #pragma unroll
        for (int p = 0; p < 4; p++) {
            int e = p * 256 + tid;
            int row = e >> 4, c4 = e & 15;
            float4 v = *(const float4*)(A + (size_t)(rowBase + row) * K + k0 + c4 * 4);
            __nv_bfloat16 h0 = __float2bfloat16(v.x), h1 = __float2bfloat16(v.y);
            __nv_bfloat16 h2 = __float2bfloat16(v.z), h3 = __float2bfloat16(v.w);
            uint2 hv; hv.x = pack_bf16(h0, h1); hv.y = pack_bf16(h2, h3);
            *(uint2*)&sA[0][row * 72 + c4 * 4] = hv;
            uint2 lv;
            lv.x = pack_bf16(__float2bfloat16(v.x - __bfloat162float(h0)),
                             __float2bfloat16(v.y - __bfloat162float(h1)));
            lv.y = pack_bf16(__float2bfloat16(v.z - __bfloat162float(h2)),
                             __float2bfloat16(v.w - __bfloat162float(h3)));
            *(uint2*)&sA[1][row * 72 + c4 * 4] = lv;
            float4 u = *(const float4*)(U + (size_t)(k0 + row) * 64 + c4 * 4);
            __nv_bfloat16 g0 = __float2bfloat16(u.x), g1 = __float2bfloat16(u.y);
            __nv_bfloat16 g2 = __float2bfloat16(u.z), g3 = __float2bfloat16(u.w);
            uint2 hu; hu.x = pack_bf16(g0, g1); hu.y = pack_bf16(g2, g3);
            *(uint2*)&sB[0][row * 72 + c4 * 4] = hu;
            uint2 lu;
            lu.x = pack_bf16(__float2bfloat16(u.x - __bfloat162float(g0)),
                             __float2bfloat16(u.y - __bfloat162float(g1)));
            lu.y = pack_bf16(__float2bfloat16(u.z - __bfloat162float(g2)),
                             __float2bfloat16(u.w - __bfloat162float(g3)));
            *(uint2*)&sB[1][row * 72 + c4 * 4] = lu;
        }
        __syncthreads();

        #pragma unroll
        for (int kk = 0; kk < 64; kk += 16) {
            uint32_t aH[4], aL[4];
            {
                int row = wm * 16 + (lane & 15);
                int col = kk + 8 * (lane >> 4);
                ldsm_x4(aH, smem_u32(&sA[0][row * 72 + col]));
                ldsm_x4(aL, smem_u32(&sA[1][row * 72 + col]));
            }
            uint32_t bH[4][2], bL[4][2];
            #pragma unroll
            for (int p = 0; p < 2; p++) {
                int kr = kk + (lane & 15);
                int nc = wn * 32 + p * 16 + 8 * (lane >> 4);
                uint32_t r[4];
                ldsm_x4_t(r, smem_u32(&sB[0][kr * 72 + nc]));
                bH[2 * p][0] = r[0]; bH[2 * p][1] = r[1];
                bH[2 * p + 1][0] = r[2]; bH[2 * p + 1][1] = r[3];
                ldsm_x4_t(r, smem_u32(&sB[1][kr * 72 + nc]));
                bL[2 * p][0] = r[0]; bL[2 * p][1] = r[1];
                bL[2 * p + 1][0] = r[2]; bL[2 * p + 1][1] = r[3];
            }
            #pragma unroll
            for (int n = 0; n < 4; n++) {
                mma16816(C[n], aH, bH[n][0], bH[n][1]);
                mma16816(C[n], aH, bL[n][0], bL[n][1]);
                mma16816(C[n], aL, bH[n][0], bH[n][1]);
            }
        }
        __syncthreads();
    }

    int quad = lane >> 2, a4 = lane & 3;
    #pragma unroll
    for (int n = 0; n < 4; n++) {
        int col = wn * 32 + n * 8 + a4 * 2;
        int r0  = rowBase + wm * 16 + quad;
        *(float2*)(outSlab + (size_t)r0 * 64 + col) = make_float2(C[n][0], C[n][1]);
        *(float2*)(outSlab + (size_t)(r0 + 8) * 64 + col) = make_float2(C[n][2], C[n][3]);
    }
}

// ------------------------------------------------------------------
// Combine: sum partial slabs, emit P fp16.
// ------------------------------------------------------------------
__global__ __launch_bounds__(256)
void combine_kernel() {
    int idx = blockIdx.x * 256 + threadIdx.x;     // 0 .. Bn*32-1
    int row = idx >> 5;
    int c4  = idx & 31;
    int col = c4 * 4;

    float4 v;
    if (col < 64) {
        const float* p = g_Pp + (size_t)row * 64 + col;
        float4 a = *(const float4*)p;
        float4 b = *(const float4*)(p + SLAB);
        v = make_float4(a.x + b.x, a.y + b.y, a.z + b.z, a.w + b.w);
    } else {
        const float* p = g_Pp + 2 * (size_t)SLAB + (size_t)row * 64 + (col - 64);
        float4 a = *(const float4*)p;
        float4 b = *(const float4*)(p + SLAB);
        float4 cc = *(const float4*)(p + 2 * (size_t)SLAB);
        float4 d = *(const float4*)(p + 3 * (size_t)SLAB);
        v = make_float4(a.x + b.x + cc.x + d.x, a.y + b.y + cc.y + d.y,
                        a.z + b.z + cc.z + d.z, a.w + b.w + cc.w + d.w);
    }

    uint2 w;
    w.x = pack_f16(__float2half(v.x), __float2half(v.y));
    w.y = pack_f16(__float2half(v.z), __float2half(v.w));
    *(uint2*)&g_Pf[(size_t)row * 128 + col] = w;
}

// ------------------------------------------------------------------
// Main GEMM (P @ Vt, K=128, fp16 2-pass) + smem-staged coalesced epilogue.
// CTA tile M=64 x N=128, 256 thr, 8 warps (2m x 4n), warp 32x32.
// Stage (half units): A[64][40], Bhi[32][136], Blo[32][136]
// ------------------------------------------------------------------
#define AST 40
#define BST 136
#define U_A   0
#define U_BHI (64 * AST)
#define U_BLO (64 * AST + 32 * BST)
#define STAGE_UNITS (64 * AST + 2 * 32 * BST)        // 11264 units = 22528 B
#define SMEM_TOTAL (2 * STAGE_UNITS * 2)             // 45056 B
#define CST 132

__global__ __launch_bounds__(256, 3)
void main_kernel(const float* __restrict__ x, const float* __restrict__ h,
                 const float* __restrict__ c,
                 const float* __restrict__ dia_x, const float* __restrict__ dia_h,
                 float* __restrict__ out) {
    extern __shared__ __half smh[];

    int tid = threadIdx.x;
    int lane = tid & 31, w = tid >> 5;
    int wm = w >> 2, wn = w & 3;
    int rowBase = blockIdx.y * 64;
    int colBase = blockIdx.x * 128;

    uint32_t sbase = smem_u32(smh);

    auto load_chunk = [&](int k0, int stage) {
        uint32_t sb = sbase + stage * STAGE_UNITS * 2;
        // A: 256 chunks
        {
            int e = tid;
            int r = e >> 2, cc = e & 3;
            cpa16(sb + U_A * 2 + (r * AST + cc * 8) * 2,
                  g_Pf + (size_t)(rowBase + r) * 128 + k0 + cc * 8);
        }
        // B: 1024 chunks (hi 512, lo 512)
        #pragma unroll
        for (int t = 0; t < 4; t++) {
            int e = t * 256 + tid;
            const __half* g = (e >> 9) ? g_Vtlo : g_Vthi;
            uint32_t uoff = (e >> 9) ? U_BLO : U_BHI;
            int wi = e & 511;
            int kr = wi >> 4, cc = wi & 15;
            cpa16(sb + uoff * 2 + (kr * BST + cc * 8) * 2,
                  g + (size_t)(k0 + kr) * FourH + colBase + cc * 8);
        }
        CP_COMMIT();
    };

    float C[2][4][4];
    #pragma unroll
    for (int m = 0; m < 2; m++)
        #pragma unroll
        for (int n = 0; n < 4; n++)
            #pragma unroll
            for (int q = 0; q < 4; q++) C[m][n][q] = 0.f;

    load_chunk(0, 0);
    load_chunk(32, 1);

    #pragma unroll
    for (int ck = 0; ck < 4; ck++) {
        if (ck < 3) { CP_WAIT1(); } else { CP_WAIT0(); }
        __syncthreads();

        __half* sA   = smh + (ck & 1) * STAGE_UNITS + U_A;
        __half* sBhi = smh + (ck & 1) * STAGE_UNITS + U_BHI;
        __half* sBlo = smh + (ck & 1) * STAGE_UNITS + U_BLO;

        #pragma unroll
        for (int kk = 0; kk < 32; kk += 16) {
            uint32_t bH[4][2], bL[4][2];
            #pragma unroll
            for (int p = 0; p < 2; p++) {
                int kr = kk + (lane & 15);
                int nc = wn * 32 + p * 16 + 8 * (lane >> 4);
                uint32_t r[4];
                ldsm_x4_t(r, smem_u32(&sBhi[kr * BST + nc]));
                bH[2 * p][0] = r[0]; bH[2 * p][1] = r[1];
                bH[2 * p + 1][0] = r[2]; bH[2 * p + 1][1] = r[3];
                ldsm_x4_t(r, smem_u32(&sBlo[kr * BST + nc]));
                bL[2 * p][0] = r[0]; bL[2 * p][1] = r[1];
                bL[2 * p + 1][0] = r[2]; bL[2 * p + 1][1] = r[3];
            }
            #pragma unroll
            for (int m = 0; m < 2; m++) {
                uint32_t aF[4];
                int row = wm * 32 + m * 16 + (lane & 15);
                int col = kk + 8 * (lane >> 4);
                ldsm_x4(aF, smem_u32(&sA[row * AST + col]));
                #pragma unroll
                for (int n = 0; n < 4; n++) {
                    mma16816h(C[m][n], aF, bH[n][0], bH[n][1]);
                    mma16816h(C[m][n], aF, bL[n][0], bL[n][1]);
                }
            }
        }
        __syncthreads();
        if (ck < 2) load_chunk((ck + 2) * 32, ck & 1);
    }

    // ---------------- epilogue: stage C in smem, coalesced I/O ----------------
    float* sC = (float*)smh;      // 64 x CST fp32 = 33792 B (fits in 45056)
    int quad = lane >> 2, a4 = lane & 3;

    #pragma unroll
    for (int n = 0; n < 4; n++) {
        int col = wn * 32 + n * 8 + a4 * 2;
        #pragma unroll
        for (int m = 0; m < 2; m++) {
            int r0 = wm * 32 + m * 16 + quad;
            *(float2*)&sC[r0 * CST + col]       = make_float2(C[m][n][0], C[m][n][1]);
            *(float2*)&sC[(r0 + 8) * CST + col] = make_float2(C[m][n][2], C[m][n][3]);
        }
    }
    __syncthreads();

    int jl = tid & 31;
    int j  = (colBase >> 2) + jl;
    bool hasX = (j < In);

    float4 cfx = *(const float4*)(g_cfx  + (size_t)j * 4);
    float4 cfh = *(const float4*)(g_cfh  + (size_t)j * 4);
    float4 bs  = *(const float4*)(g_bias + (size_t)j * 4);
    float dxv = hasX ? dia_x[j] : 0.f;
    float dhv = dia_h[j];

    #pragma unroll
    for (int pass = 0; pass < 8; pass++) {
        int bl = pass * 8 + (tid >> 5);
        int b  = rowBase + bl;

        float4 g4 = *(const float4*)&sC[bl * CST + jl * 4];
        float xv = hasX ? x[(size_t)b * In + j] : 0.f;
        float hv = h[(size_t)b * Hn + j];
        float cv = c[(size_t)b * Hn + j];
        float z  = dxv * xv + dhv * hv;

        float gi = g4.x - xv * cfx.x - hv * cfh.x + bs.x + z;
        float gf = g4.y - xv * cfx.y - hv * cfh.y + bs.y + z;
        float go = g4.z - xv * cfx.z - hv * cfh.z + bs.z + z;
        float gn = g4.w - xv * cfx.w - hv * cfh.w + bs.w + z;

        float ig = 1.f / (1.f + expf(-gi));
        float fg = 1.f / (1.f + expf(-gf));
        float og = 1.f / (1.f + expf(-go));
        float ng = tanhf(gn);

        float cn = fg * cv + ig * ng;
        float hn = og * tanhf(cn);

        out[(size_t)b * Hn + j]                   = hn;
        out[(size_t)Bn * Hn + (size_t)b * Hn + j] = cn;
    }
}

// ------------------------------------------------------------------
extern "C" void kernel_launch(void* const* d_in, const int* in_sizes, int n_in,
                              void* d_out, int out_size) {
    const float* x     = (const float*)d_in[0];
    const float* h     = (const float*)d_in[1];
    const float* c     = (const float*)d_in[2];
    const float* u_x   = (const float*)d_in[3];
    const float* u_h   = (const float*)d_in[4];
    const float* v_x   = (const float*)d_in[5];
    const float* v_h   = (const float*)d_in[6];
    const float* b_x   = (const float*)d_in[7];
    const float* b_h   = (const float*)d_in[8];
    const float* dia_x = (const float*)d_in[9];
    const float* dia_h = (const float*)d_in[10];
    float* out = (float*)d_out;

    prep_coef_kernel<<<FourH / 256, 256>>>(u_x, u_h, v_x, v_h, b_x, b_h);
    prep_vt_kernel<<<(128 * FourH) / 256, 256>>>(v_x, v_h);

    proj_part_kernel<<<dim3(Bn / 64, 6), 256>>>(x, u_x, h, u_h);
    combine_kernel<<<(Bn * 32) / 256, 256>>>();

    cudaFuncSetAttribute(main_kernel,
                         cudaFuncAttributeMaxDynamicSharedMemorySize, SMEM_TOTAL);
    dim3 grid(FourH / 128, Bn / 64);
    main_kernel<<<grid, 256, SMEM_TOTAL>>>(x, h, c, dia_x, dia_h, out);
}

// round 8
// speedup vs baseline: 2.4484x; 1.0670x over previous
#include <cuda_runtime.h>
#include <cuda_bf16.h>
#include <cuda_fp16.h>
#include <math.h>
#include <stdint.h>

#define Bn   8192
#define In   512
#define Hn   1024
#define Rn   64
#define FourH 4096
#define SLAB (Bn * 64)

// ------------------------------------------------------------------
// Device scratch
// ------------------------------------------------------------------
__device__ __half g_Pf[Bn * 128];          // P fp16 [B][128]
__device__ __half g_Vt[128 * FourH];       // Vt fp16 [k][4096], col = j*4+g
__device__ float g_Pp[6 * SLAB];           // proj partial slabs
__device__ float g_cfx[FourH];
__device__ float g_cfh[FourH];
__device__ float g_bias[FourH];

// ------------------------------------------------------------------
// PTX helpers
// ------------------------------------------------------------------
__device__ __forceinline__ uint32_t smem_u32(const void* p) {
    return (uint32_t)__cvta_generic_to_shared(p);
}
__device__ __forceinline__ void ldsm_x4(uint32_t* r, uint32_t a) {
    asm volatile("ldmatrix.sync.aligned.m8n8.x4.shared.b16 {%0,%1,%2,%3}, [%4];"
        : "=r"(r[0]), "=r"(r[1]), "=r"(r[2]), "=r"(r[3]) : "r"(a));
}
__device__ __forceinline__ void ldsm_x4_t(uint32_t* r, uint32_t a) {
    asm volatile("ldmatrix.sync.aligned.m8n8.x4.trans.shared.b16 {%0,%1,%2,%3}, [%4];"
        : "=r"(r[0]), "=r"(r[1]), "=r"(r[2]), "=r"(r[3]) : "r"(a));
}
// bf16 mma (proj)
__device__ __forceinline__ void mma16816(float* c, const uint32_t* a,
                                         uint32_t b0, uint32_t b1) {
    asm volatile("mma.sync.aligned.m16n8k16.row.col.f32.bf16.bf16.f32 "
        "{%0,%1,%2,%3}, {%4,%5,%6,%7}, {%8,%9}, {%0,%1,%2,%3};"
        : "+f"(c[0]), "+f"(c[1]), "+f"(c[2]), "+f"(c[3])
        : "r"(a[0]), "r"(a[1]), "r"(a[2]), "r"(a[3]), "r"(b0), "r"(b1));
}
// fp16 mma (main)
__device__ __forceinline__ void mma16816h(float* c, const uint32_t* a,
                                          uint32_t b0, uint32_t b1) {
    asm volatile("mma.sync.aligned.m16n8k16.row.col.f32.f16.f16.f32 "
        "{%0,%1,%2,%3}, {%4,%5,%6,%7}, {%8,%9}, {%0,%1,%2,%3};"
        : "+f"(c[0]), "+f"(c[1]), "+f"(c[2]), "+f"(c[3])
        : "r"(a[0]), "r"(a[1]), "r"(a[2]), "r"(a[3]), "r"(b0), "r"(b1));
}
__device__ __forceinline__ uint32_t pack_bf16(__nv_bfloat16 lo16, __nv_bfloat16 hi16) {
    return (uint32_t)__bfloat16_as_ushort(lo16) |
           ((uint32_t)__bfloat16_as_ushort(hi16) << 16);
}
__device__ __forceinline__ uint32_t pack_f16(__half lo16, __half hi16) {
    return (uint32_t)__half_as_ushort(lo16) |
           ((uint32_t)__half_as_ushort(hi16) << 16);
}
__device__ __forceinline__ void cpa16(uint32_t dst, const void* src) {
    asm volatile("cp.async.cg.shared.global [%0], [%1], 16;"
        :: "r"(dst), "l"(src) : "memory");
}
#define CP_COMMIT() asm volatile("cp.async.commit_group;" ::: "memory")
#define CP_WAIT1()  asm volatile("cp.async.wait_group 1;" ::: "memory")
#define CP_WAIT0()  asm volatile("cp.async.wait_group 0;" ::: "memory")

// ------------------------------------------------------------------
// Prep 1: coefficients + fused bias (fp32, exact)
// ------------------------------------------------------------------
__global__ void prep_coef_kernel(const float* __restrict__ u_x,
                                 const float* __restrict__ u_h,
                                 const float* __restrict__ v_x,
                                 const float* __restrict__ v_h,
                                 const float* __restrict__ b_x,
                                 const float* __restrict__ b_h) {
    int idx = blockIdx.x * blockDim.x + threadIdx.x;   // j*4+g
    if (idx >= FourH) return;
    int j = idx >> 2;
    int g = idx & 3;
    int row4h = g * Hn + j;

    float cx = 0.f;
    if (j < In) {
        const float* uxr = u_x + j * Rn;
        const float* vxr = v_x + row4h * Rn;
        #pragma unroll 8
        for (int r = 0; r < Rn; r++) cx += uxr[r] * vxr[r];
    }
    float ch = 0.f;
    {
        const float* uhr = u_h + j * Rn;
        const float* vhr = v_h + row4h * Rn;
        #pragma unroll 8
        for (int r = 0; r < Rn; r++) ch += uhr[r] * vhr[r];
    }
    g_cfx[idx]  = cx;
    g_cfh[idx]  = ch;
    g_bias[idx] = b_x[row4h] + b_h[row4h];
}

// ------------------------------------------------------------------
// Prep 2: Vt fp16   [k=0..127][col=j*4+g]
// ------------------------------------------------------------------
__global__ void prep_vt_kernel(const float* __restrict__ v_x,
                               const float* __restrict__ v_h) {
    int idx = blockIdx.x * blockDim.x + threadIdx.x;
    int r   = idx >> 12;
    int col = idx & (FourH - 1);
    int j = col >> 2;
    int g = col & 3;
    int row4h = g * Hn + j;
    float v = (r < 64) ? v_x[row4h * Rn + r] : v_h[row4h * Rn + (r - 64)];
    g_Vt[idx] = __float2half(v);
}

// ------------------------------------------------------------------
// Projection split-K partials (bf16 3-pass HMMA, fp32 out).
// ------------------------------------------------------------------
__global__ __launch_bounds__(256)
void proj_part_kernel(const float* __restrict__ x, const float* __restrict__ u_x,
                      const float* __restrict__ h, const float* __restrict__ u_h) {
    __shared__ __nv_bfloat16 sA[2][64 * 72];
    __shared__ __nv_bfloat16 sB[2][64 * 72];

    int tid = threadIdx.x;
    int lane = tid & 31, w = tid >> 5;
    int wm = w >> 1, wn = w & 1;

    int slice = blockIdx.y;
    bool isX = (slice < 2);
    const float* A = isX ? x   : h;
    const float* U = isX ? u_x : u_h;
    int K      = isX ? In : Hn;
    int kBase  = (isX ? slice : (slice - 2)) * 256;
    int rowBase = blockIdx.x * 64;
    float* outSlab = g_Pp + (size_t)slice * SLAB;

    float C[4][4];
    #pragma unroll
    for (int n = 0; n < 4; n++)
        #pragma unroll
        for (int q = 0; q < 4; q++) C[n][q] = 0.f;

    #pragma unroll
    for (int kc = 0; kc < 4; kc++) {
        int k0 = kBase + kc * 64;
        #pragma unroll
        for (int p = 0; p < 4; p++) {
            int e = p * 256 + tid;
            int row = e >> 4, c4 = e & 15;
            float4 v = *(const float4*)(A + (size_t)(rowBase + row) * K + k0 + c4 * 4);
            __nv_bfloat16 h0 = __float2bfloat16(v.x), h1 = __float2bfloat16(v.y);
            __nv_bfloat16 h2 = __float2bfloat16(v.z), h3 = __float2bfloat16(v.w);
            uint2 hv; hv.x = pack_bf16(h0, h1); hv.y = pack_bf16(h2, h3);
            *(uint2*)&sA[0][row * 72 + c4 * 4] = hv;
            uint2 lv;
            lv.x = pack_bf16(__float2bfloat16(v.x - __bfloat162float(h0)),
                             __float2bfloat16(v.y - __bfloat162float(h1)));
            lv.y = pack_bf16(__float2bfloat16(v.z - __bfloat162float(h2)),
                             __float2bfloat16(v.w - __bfloat162float(h3)));
            *(uint2*)&sA[1][row * 72 + c4 * 4] = lv;
            float4 u = *(const float4*)(U + (size_t)(k0 + row) * 64 + c4 * 4);
            __nv_bfloat16 g0 = __float2bfloat16(u.x), g1 = __float2bfloat16(u.y);
            __nv_bfloat16 g2 = __float2bfloat16(u.z), g3 = __float2bfloat16(u.w);
            uint2 hu; hu.x = pack_bf16(g0, g1); hu.y = pack_bf16(g2, g3);
            *(uint2*)&sB[0][row * 72 + c4 * 4] = hu;
            uint2 lu;
            lu.x = pack_bf16(__float2bfloat16(u.x - __bfloat162float(g0)),
                             __float2bfloat16(u.y - __bfloat162float(g1)));
            lu.y = pack_bf16(__float2bfloat16(u.z - __bfloat162float(g2)),
                             __float2bfloat16(u.w - __bfloat162float(g3)));
            *(uint2*)&sB[1][row * 72 + c4 * 4] = lu;
        }
        __syncthreads();

        #pragma unroll
        for (int kk = 0; kk < 64; kk += 16) {
            uint32_t aH[4], aL[4];
            {
                int row = wm * 16 + (lane & 15);
                int col = kk + 8 * (lane >> 4);
                ldsm_x4(aH, smem_u32(&sA[0][row * 72 + col]));
                ldsm_x4(aL, smem_u32(&sA[1][row * 72 + col]));
            }
            uint32_t bH[4][2], bL[4][2];
            #pragma unroll
            for (int p = 0; p < 2; p++) {
                int kr = kk + (lane & 15);
                int nc = wn * 32 + p * 16 + 8 * (lane >> 4);
                uint32_t r[4];
                ldsm_x4_t(r, smem_u32(&sB[0][kr * 72 + nc]));
                bH[2 * p][0] = r[0]; bH[2 * p][1] = r[1];
                bH[2 * p + 1][0] = r[2]; bH[2 * p + 1][1] = r[3];
                ldsm_x4_t(r, smem_u32(&sB[1][kr * 72 + nc]));
                bL[2 * p][0] = r[0]; bL[2 * p][1] = r[1];
                bL[2 * p + 1][0] = r[2]; bL[2 * p + 1][1] = r[3];
            }
            #pragma unroll
            for (int n = 0; n < 4; n++) {
                mma16816(C[n], aH, bH[n][0], bH[n][1]);
                mma16816(C[n], aH, bL[n][0], bL[n][1]);
                mma16816(C[n], aL, bH[n][0], bH[n][1]);
            }
        }
        __syncthreads();
    }

    int quad = lane >> 2, a4 = lane & 3;
    #pragma unroll
    for (int n = 0; n < 4; n++) {
        int col = wn * 32 + n * 8 + a4 * 2;
        int r0  = rowBase + wm * 16 + quad;
        *(float2*)(outSlab + (size_t)r0 * 64 + col) = make_float2(C[n][0], C[n][1]);
        *(float2*)(outSlab + (size_t)(r0 + 8) * 64 + col) = make_float2(C[n][2], C[n][3]);
    }
}

// ------------------------------------------------------------------
// Combine: sum partial slabs, emit P fp16.
// ------------------------------------------------------------------
__global__ __launch_bounds__(256)
void combine_kernel() {
    int idx = blockIdx.x * 256 + threadIdx.x;     // 0 .. Bn*32-1
    int row = idx >> 5;
    int c4  = idx & 31;
    int col = c4 * 4;

    float4 v;
    if (col < 64) {
        const float* p = g_Pp + (size_t)row * 64 + col;
        float4 a = *(const float4*)p;
        float4 b = *(const float4*)(p + SLAB);
        v = make_float4(a.x + b.x, a.y + b.y, a.z + b.z, a.w + b.w);
    } else {
        const float* p = g_Pp + 2 * (size_t)SLAB + (size_t)row * 64 + (col - 64);
        float4 a = *(const float4*)p;
        float4 b = *(const float4*)(p + SLAB);
        float4 cc = *(const float4*)(p + 2 * (size_t)SLAB);
        float4 d = *(const float4*)(p + 3 * (size_t)SLAB);
        v = make_float4(a.x + b.x + cc.x + d.x, a.y + b.y + cc.y + d.y,
                        a.z + b.z + cc.z + d.z, a.w + b.w + cc.w + d.w);
    }

    uint2 w;
    w.x = pack_f16(__float2half(v.x), __float2half(v.y));
    w.y = pack_f16(__float2half(v.z), __float2half(v.w));
    *(uint2*)&g_Pf[(size_t)row * 128 + col] = w;
}

// ------------------------------------------------------------------
// Main GEMM (P @ Vt, K=128, fp16 single-pass) + coalesced epilogue.
// CTA tile M=64 x N=128, 256 thr, 8 warps (2m x 4n), warp 32x32.
// Stage (half units): A[64][40], B[32][136]
// ------------------------------------------------------------------
#define AST 40
#define BST 136
#define U_A  0
#define U_B  (64 * AST)
#define STAGE_UNITS (64 * AST + 32 * BST)            // 6912 units = 13824 B
#define CST 132
#define SC_BYTES (64 * CST * 4)                      // 33792 B
#define SMEM_TOTAL (SC_BYTES)                        // > 2*STAGE_UNITS*2 = 27648

__global__ __launch_bounds__(256, 3)
void main_kernel(const float* __restrict__ x, const float* __restrict__ h,
                 const float* __restrict__ c,
                 const float* __restrict__ dia_x, const float* __restrict__ dia_h,
                 float* __restrict__ out) {
    extern __shared__ __half smh[];

    int tid = threadIdx.x;
    int lane = tid & 31, w = tid >> 5;
    int wm = w >> 2, wn = w & 3;
    int rowBase = blockIdx.y * 64;
    int colBase = blockIdx.x * 128;

    uint32_t sbase = smem_u32(smh);

    auto load_chunk = [&](int k0, int stage) {
        uint32_t sb = sbase + stage * STAGE_UNITS * 2;
        // A: 256 chunks
        {
            int e = tid;
            int r = e >> 2, cc = e & 3;
            cpa16(sb + U_A * 2 + (r * AST + cc * 8) * 2,
                  g_Pf + (size_t)(rowBase + r) * 128 + k0 + cc * 8);
        }
        // B: 512 chunks
        #pragma unroll
        for (int t = 0; t < 2; t++) {
            int e = t * 256 + tid;
            int kr = e >> 4, cc = e & 15;
            cpa16(sb + U_B * 2 + (kr * BST + cc * 8) * 2,
                  g_Vt + (size_t)(k0 + kr) * FourH + colBase + cc * 8);
        }
        CP_COMMIT();
    };

    float C[2][4][4];
    #pragma unroll
    for (int m = 0; m < 2; m++)
        #pragma unroll
        for (int n = 0; n < 4; n++)
            #pragma unroll
            for (int q = 0; q < 4; q++) C[m][n][q] = 0.f;

    load_chunk(0, 0);
    load_chunk(32, 1);

    #pragma unroll
    for (int ck = 0; ck < 4; ck++) {
        if (ck < 3) { CP_WAIT1(); } else { CP_WAIT0(); }
        __syncthreads();

        __half* sA = smh + (ck & 1) * STAGE_UNITS + U_A;
        __half* sB = smh + (ck & 1) * STAGE_UNITS + U_B;

        #pragma unroll
        for (int kk = 0; kk < 32; kk += 16) {
            uint32_t bF[4][2];
            #pragma unroll
            for (int p = 0; p < 2; p++) {
                int kr = kk + (lane & 15);
                int nc = wn * 32 + p * 16 + 8 * (lane >> 4);
                uint32_t r[4];
                ldsm_x4_t(r, smem_u32(&sB[kr * BST + nc]));
                bF[2 * p][0] = r[0]; bF[2 * p][1] = r[1];
                bF[2 * p + 1][0] = r[2]; bF[2 * p + 1][1] = r[3];
            }
            #pragma unroll
            for (int m = 0; m < 2; m++) {
                uint32_t aF[4];
                int row = wm * 32 + m * 16 + (lane & 15);
                int col = kk + 8 * (lane >> 4);
                ldsm_x4(aF, smem_u32(&sA[row * AST + col]));
                #pragma unroll
                for (int n = 0; n < 4; n++)
                    mma16816h(C[m][n], aF, bF[n][0], bF[n][1]);
            }
        }
        __syncthreads();
        if (ck < 2) load_chunk((ck + 2) * 32, ck & 1);
    }

    // ---------------- epilogue: stage C in smem, coalesced I/O ----------------
    float* sC = (float*)smh;
    int quad = lane >> 2, a4 = lane & 3;

    #pragma unroll
    for (int n = 0; n < 4; n++) {
        int col = wn * 32 + n * 8 + a4 * 2;
        #pragma unroll
        for (int m = 0; m < 2; m++) {
            int r0 = wm * 32 + m * 16 + quad;
            *(float2*)&sC[r0 * CST + col]       = make_float2(C[m][n][0], C[m][n][1]);
            *(float2*)&sC[(r0 + 8) * CST + col] = make_float2(C[m][n][2], C[m][n][3]);
        }
    }
    __syncthreads();

    int jl = tid & 31;
    int j  = (colBase >> 2) + jl;
    bool hasX = (j < In);

    float4 cfx = *(const float4*)(g_cfx  + (size_t)j * 4);
    float4 cfh = *(const float4*)(g_cfh  + (size_t)j * 4);
    float4 bs  = *(const float4*)(g_bias + (size_t)j * 4);
    float dxv = hasX ? dia_x[j] : 0.f;
    float dhv = dia_h[j];

    #pragma unroll
    for (int pass = 0; pass < 8; pass++) {
        int bl = pass * 8 + (tid >> 5);
        int b  = rowBase + bl;

        float4 g4 = *(const float4*)&sC[bl * CST + jl * 4];
        float xv = hasX ? x[(size_t)b * In + j] : 0.f;
        float hv = h[(size_t)b * Hn + j];
        float cv = c[(size_t)b * Hn + j];
        float z  = dxv * xv + dhv * hv;

        float gi = g4.x - xv * cfx.x - hv * cfh.x + bs.x + z;
        float gf = g4.y - xv * cfx.y - hv * cfh.y + bs.y + z;
        float go = g4.z - xv * cfx.z - hv * cfh.z + bs.z + z;
        float gn = g4.w - xv * cfx.w - hv * cfh.w + bs.w + z;

        float ig = 1.f / (1.f + expf(-gi));
        float fg = 1.f / (1.f + expf(-gf));
        float og = 1.f / (1.f + expf(-go));
        float ng = tanhf(gn);

        float cn = fg * cv + ig * ng;
        float hn = og * tanhf(cn);

        out[(size_t)b * Hn + j]                   = hn;
        out[(size_t)Bn * Hn + (size_t)b * Hn + j] = cn;
    }
}

// ------------------------------------------------------------------
extern "C" void kernel_launch(void* const* d_in, const int* in_sizes, int n_in,
                              void* d_out, int out_size) {
    const float* x     = (const float*)d_in[0];
    const float* h     = (const float*)d_in[1];
    const float* c     = (const float*)d_in[2];
    const float* u_x   = (const float*)d_in[3];
    const float* u_h   = (const float*)d_in[4];
    const float* v_x   = (const float*)d_in[5];
    const float* v_h   = (const float*)d_in[6];
    const float* b_x   = (const float*)d_in[7];
    const float* b_h   = (const float*)d_in[8];
    const float* dia_x = (const float*)d_in[9];
    const float* dia_h = (const float*)d_in[10];
    float* out = (float*)d_out;

    prep_coef_kernel<<<FourH / 256, 256>>>(u_x, u_h, v_x, v_h, b_x, b_h);
    prep_vt_kernel<<<(128 * FourH) / 256, 256>>>(v_x, v_h);

    proj_part_kernel<<<dim3(Bn / 64, 6), 256>>>(x, u_x, h, u_h);
    combine_kernel<<<(Bn * 32) / 256, 256>>>();

    cudaFuncSetAttribute(main_kernel,
                         cudaFuncAttributeMaxDynamicSharedMemorySize, SMEM_TOTAL);
    dim3 grid(FourH / 128, Bn / 64);
    main_kernel<<<grid, 256, SMEM_TOTAL>>>(x, h, c, dia_x, dia_h, out);
}

// round 9
// speedup vs baseline: 3.2176x; 1.3142x over previous
#include <cuda_runtime.h>
#include <cuda_bf16.h>
#include <cuda_fp16.h>
#include <math.h>
#include <stdint.h>

#define Bn   8192
#define In   512
#define Hn   1024
#define Rn   64
#define FourH 4096
#define SLAB (Bn * 64)

// ------------------------------------------------------------------
// Device scratch
// ------------------------------------------------------------------
__device__ __half g_Pf[Bn * 128];          // P fp16 [B][128]
__device__ __half g_Vt[128 * FourH];       // Vt fp16 [k][4096], col = j*4+g
__device__ float g_Pp[12 * SLAB];          // proj partial slabs
__device__ float g_cfx[FourH];
__device__ float g_cfh[FourH];
__device__ float g_bias[FourH];

// ------------------------------------------------------------------
// PTX helpers
// ------------------------------------------------------------------
__device__ __forceinline__ uint32_t smem_u32(const void* p) {
    return (uint32_t)__cvta_generic_to_shared(p);
}
__device__ __forceinline__ void ldsm_x4(uint32_t* r, uint32_t a) {
    asm volatile("ldmatrix.sync.aligned.m8n8.x4.shared.b16 {%0,%1,%2,%3}, [%4];"
        : "=r"(r[0]), "=r"(r[1]), "=r"(r[2]), "=r"(r[3]) : "r"(a));
}
__device__ __forceinline__ void ldsm_x4_t(uint32_t* r, uint32_t a) {
    asm volatile("ldmatrix.sync.aligned.m8n8.x4.trans.shared.b16 {%0,%1,%2,%3}, [%4];"
        : "=r"(r[0]), "=r"(r[1]), "=r"(r[2]), "=r"(r[3]) : "r"(a));
}
// bf16 mma (proj)
__device__ __forceinline__ void mma16816(float* c, const uint32_t* a,
                                         uint32_t b0, uint32_t b1) {
    asm volatile("mma.sync.aligned.m16n8k16.row.col.f32.bf16.bf16.f32 "
        "{%0,%1,%2,%3}, {%4,%5,%6,%7}, {%8,%9}, {%0,%1,%2,%3};"
        : "+f"(c[0]), "+f"(c[1]), "+f"(c[2]), "+f"(c[3])
        : "r"(a[0]), "r"(a[1]), "r"(a[2]), "r"(a[3]), "r"(b0), "r"(b1));
}
// fp16 mma (main)
__device__ __forceinline__ void mma16816h(float* c, const uint32_t* a,
                                          uint32_t b0, uint32_t b1) {
    asm volatile("mma.sync.aligned.m16n8k16.row.col.f32.f16.f16.f32 "
        "{%0,%1,%2,%3}, {%4,%5,%6,%7}, {%8,%9}, {%0,%1,%2,%3};"
        : "+f"(c[0]), "+f"(c[1]), "+f"(c[2]), "+f"(c[3])
        : "r"(a[0]), "r"(a[1]), "r"(a[2]), "r"(a[3]), "r"(b0), "r"(b1));
}
__device__ __forceinline__ uint32_t pack_bf16(__nv_bfloat16 lo16, __nv_bfloat16 hi16) {
    return (uint32_t)__bfloat16_as_ushort(lo16) |
           ((uint32_t)__bfloat16_as_ushort(hi16) << 16);
}
__device__ __forceinline__ uint32_t pack_f16(__half lo16, __half hi16) {
    return (uint32_t)__half_as_ushort(lo16) |
           ((uint32_t)__half_as_ushort(hi16) << 16);
}
__device__ __forceinline__ void cpa16(uint32_t dst, const void* src) {
    asm volatile("cp.async.cg.shared.global [%0], [%1], 16;"
        :: "r"(dst), "l"(src) : "memory");
}
#define CP_COMMIT() asm volatile("cp.async.commit_group;" ::: "memory")
#define CP_WAIT1()  asm volatile("cp.async.wait_group 1;" ::: "memory")
#define CP_WAIT0()  asm volatile("cp.async.wait_group 0;" ::: "memory")

// fast activations (MUFU-based; rel err ~1e-6, inf-safe)
__device__ __forceinline__ float fsigmoid(float v) {
    return __fdividef(1.f, 1.f + __expf(-v));
}
__device__ __forceinline__ float ftanh(float v) {
    float a = fabsf(v);
    float t = 1.f - __fdividef(2.f, __expf(2.f * a) + 1.f);
    return copysignf(t, v);
}

// ------------------------------------------------------------------
// Prep 1: coefficients + fused bias (fp32, exact)
// ------------------------------------------------------------------
__global__ void prep_coef_kernel(const float* __restrict__ u_x,
                                 const float* __restrict__ u_h,
                                 const float* __restrict__ v_x,
                                 const float* __restrict__ v_h,
                                 const float* __restrict__ b_x,
                                 const float* __restrict__ b_h) {
    int idx = blockIdx.x * blockDim.x + threadIdx.x;   // j*4+g
    if (idx >= FourH) return;
    int j = idx >> 2;
    int g = idx & 3;
    int row4h = g * Hn + j;

    float cx = 0.f;
    if (j < In) {
        const float* uxr = u_x + j * Rn;
        const float* vxr = v_x + row4h * Rn;
        #pragma unroll 8
        for (int r = 0; r < Rn; r++) cx += uxr[r] * vxr[r];
    }
    float ch = 0.f;
    {
        const float* uhr = u_h + j * Rn;
        const float* vhr = v_h + row4h * Rn;
        #pragma unroll 8
        for (int r = 0; r < Rn; r++) ch += uhr[r] * vhr[r];
    }
    g_cfx[idx]  = cx;
    g_cfh[idx]  = ch;
    g_bias[idx] = b_x[row4h] + b_h[row4h];
}

// ------------------------------------------------------------------
// Prep 2: Vt fp16   [k=0..127][col=j*4+g]
// ------------------------------------------------------------------
__global__ void prep_vt_kernel(const float* __restrict__ v_x,
                               const float* __restrict__ v_h) {
    int idx = blockIdx.x * blockDim.x + threadIdx.x;
    int r   = idx >> 12;
    int col = idx & (FourH - 1);
    int j = col >> 2;
    int g = col & 3;
    int row4h = g * Hn + j;
    float v = (r < 64) ? v_x[row4h * Rn + r] : v_h[row4h * Rn + (r - 64)];
    g_Vt[idx] = __float2half(v);
}

// ------------------------------------------------------------------
// Projection split-K partials (bf16 3-pass HMMA, fp32 out).
// 12 slices of K=128: slices 0-3 = x@u_x, slices 4-11 = h@u_h.
// CTA: 64 rows x 64 cols, 2 serial k-chunks of 64.
// ------------------------------------------------------------------
__global__ __launch_bounds__(256)
void proj_part_kernel(const float* __restrict__ x, const float* __restrict__ u_x,
                      const float* __restrict__ h, const float* __restrict__ u_h) {
    __shared__ __nv_bfloat16 sA[2][64 * 72];
    __shared__ __nv_bfloat16 sB[2][64 * 72];

    int tid = threadIdx.x;
    int lane = tid & 31, w = tid >> 5;
    int wm = w >> 1, wn = w & 1;

    int slice = blockIdx.y;
    bool isX = (slice < 4);
    const float* A = isX ? x   : h;
    const float* U = isX ? u_x : u_h;
    int K      = isX ? In : Hn;
    int kBase  = (isX ? slice : (slice - 4)) * 128;
    int rowBase = blockIdx.x * 64;
    float* outSlab = g_Pp + (size_t)slice * SLAB;

    float C[4][4];
    #pragma unroll
    for (int n = 0; n < 4; n++)
        #pragma unroll
        for (int q = 0; q < 4; q++) C[n][q] = 0.f;

    #pragma unroll
    for (int kc = 0; kc < 2; kc++) {
        int k0 = kBase + kc * 64;
        #pragma unroll
        for (int p = 0; p < 4; p++) {
            int e = p * 256 + tid;
            int row = e >> 4, c4 = e & 15;
            float4 v = *(const float4*)(A + (size_t)(rowBase + row) * K + k0 + c4 * 4);
            __nv_bfloat16 h0 = __float2bfloat16(v.x), h1 = __float2bfloat16(v.y);
            __nv_bfloat16 h2 = __float2bfloat16(v.z), h3 = __float2bfloat16(v.w);
            uint2 hv; hv.x = pack_bf16(h0, h1); hv.y = pack_bf16(h2, h3);
            *(uint2*)&sA[0][row * 72 + c4 * 4] = hv;
            uint2 lv;
            lv.x = pack_bf16(__float2bfloat16(v.x - __bfloat162float(h0)),
                             __float2bfloat16(v.y - __bfloat162float(h1)));
            lv.y = pack_bf16(__float2bfloat16(v.z - __bfloat162float(h2)),
                             __float2bfloat16(v.w - __bfloat162float(h3)));
            *(uint2*)&sA[1][row * 72 + c4 * 4] = lv;
            float4 u = *(const float4*)(U + (size_t)(k0 + row) * 64 + c4 * 4);
            __nv_bfloat16 g0 = __float2bfloat16(u.x), g1 = __float2bfloat16(u.y);
            __nv_bfloat16 g2 = __float2bfloat16(u.z), g3 = __float2bfloat16(u.w);
            uint2 hu; hu.x = pack_bf16(g0, g1); hu.y = pack_bf16(g2, g3);
            *(uint2*)&sB[0][row * 72 + c4 * 4] = hu;
            uint2 lu;
            lu.x = pack_bf16(__float2bfloat16(u.x - __bfloat162float(g0)),
                             __float2bfloat16(u.y - __bfloat162float(g1)));
            lu.y = pack_bf16(__float2bfloat16(u.z - __bfloat162float(g2)),
                             __float2bfloat16(u.w - __bfloat162float(g3)));
            *(uint2*)&sB[1][row * 72 + c4 * 4] = lu;
        }
        __syncthreads();

        #pragma unroll
        for (int kk = 0; kk < 64; kk += 16) {
            uint32_t aH[4], aL[4];
            {
                int row = wm * 16 + (lane & 15);
                int col = kk + 8 * (lane >> 4);
                ldsm_x4(aH, smem_u32(&sA[0][row * 72 + col]));
                ldsm_x4(aL, smem_u32(&sA[1][row * 72 + col]));
            }
            uint32_t bH[4][2], bL[4][2];
            #pragma unroll
            for (int p = 0; p < 2; p++) {
                int kr = kk + (lane & 15);
                int nc = wn * 32 + p * 16 + 8 * (lane >> 4);
                uint32_t r[4];
                ldsm_x4_t(r, smem_u32(&sB[0][kr * 72 + nc]));
                bH[2 * p][0] = r[0]; bH[2 * p][1] = r[1];
                bH[2 * p + 1][0] = r[2]; bH[2 * p + 1][1] = r[3];
                ldsm_x4_t(r, smem_u32(&sB[1][kr * 72 + nc]));
                bL[2 * p][0] = r[0]; bL[2 * p][1] = r[1];
                bL[2 * p + 1][0] = r[2]; bL[2 * p + 1][1] = r[3];
            }
            #pragma unroll
            for (int n = 0; n < 4; n++) {
                mma16816(C[n], aH, bH[n][0], bH[n][1]);
                mma16816(C[n], aH, bL[n][0], bL[n][1]);
                mma16816(C[n], aL, bH[n][0], bH[n][1]);
            }
        }
        __syncthreads();
    }

    int quad = lane >> 2, a4 = lane & 3;
    #pragma unroll
    for (int n = 0; n < 4; n++) {
        int col = wn * 32 + n * 8 + a4 * 2;
        int r0  = rowBase + wm * 16 + quad;
        *(float2*)(outSlab + (size_t)r0 * 64 + col) = make_float2(C[n][0], C[n][1]);
        *(float2*)(outSlab + (size_t)(r0 + 8) * 64 + col) = make_float2(C[n][2], C[n][3]);
    }
}

// ------------------------------------------------------------------
// Combine: sum partial slabs (4 for x-cols, 8 for h-cols), emit P fp16.
// ------------------------------------------------------------------
__global__ __launch_bounds__(256)
void combine_kernel() {
    int idx = blockIdx.x * 256 + threadIdx.x;     // 0 .. Bn*32-1
    int row = idx >> 5;
    int c4  = idx & 31;
    int col = c4 * 4;

    float4 v = make_float4(0.f, 0.f, 0.f, 0.f);
    if (col < 64) {
        const float* p = g_Pp + (size_t)row * 64 + col;
        #pragma unroll
        for (int s = 0; s < 4; s++) {
            float4 a = *(const float4*)(p + (size_t)s * SLAB);
            v.x += a.x; v.y += a.y; v.z += a.z; v.w += a.w;
        }
    } else {
        const float* p = g_Pp + 4 * (size_t)SLAB + (size_t)row * 64 + (col - 64);
        #pragma unroll
        for (int s = 0; s < 8; s++) {
            float4 a = *(const float4*)(p + (size_t)s * SLAB);
            v.x += a.x; v.y += a.y; v.z += a.z; v.w += a.w;
        }
    }

    uint2 w;
    w.x = pack_f16(__float2half(v.x), __float2half(v.y));
    w.y = pack_f16(__float2half(v.z), __float2half(v.w));
    *(uint2*)&g_Pf[(size_t)row * 128 + col] = w;
}

// ------------------------------------------------------------------
// Main GEMM (P @ Vt, K=128, fp16 single-pass) + coalesced epilogue.
// CTA tile M=64 x N=128, 256 thr, 8 warps (2m x 4n), warp 32x32.
// Two K=64 chunks, double-buffered, 3 barriers total.
// Stage (half units): A[64][72], B[64][136]
// ------------------------------------------------------------------
#define AST 72
#define BST 136
#define U_A  0
#define U_B  (64 * AST)
#define STAGE_UNITS (64 * AST + 64 * BST)            // 13312 units = 26624 B
#define CST 132
#define SMEM_TOTAL (2 * STAGE_UNITS * 2)             // 53248 B (sC 33792 fits)

__global__ __launch_bounds__(256, 3)
void main_kernel(const float* __restrict__ x, const float* __restrict__ h,
                 const float* __restrict__ c,
                 const float* __restrict__ dia_x, const float* __restrict__ dia_h,
                 float* __restrict__ out) {
    extern __shared__ __half smh[];

    int tid = threadIdx.x;
    int lane = tid & 31, w = tid >> 5;
    int wm = w >> 2, wn = w & 3;
    int rowBase = blockIdx.y * 64;
    int colBase = blockIdx.x * 128;

    uint32_t sbase = smem_u32(smh);

    auto load_chunk = [&](int k0, int stage) {
        uint32_t sb = sbase + stage * STAGE_UNITS * 2;
        // A: 64 rows x 64 k = 512 x 16B chunks
        #pragma unroll
        for (int t = 0; t < 2; t++) {
            int e = t * 256 + tid;
            int r = e >> 3, cc = e & 7;
            cpa16(sb + U_A * 2 + (r * AST + cc * 8) * 2,
                  g_Pf + (size_t)(rowBase + r) * 128 + k0 + cc * 8);
        }
        // B: 64 k x 128 n = 1024 x 16B chunks
        #pragma unroll
        for (int t = 0; t < 4; t++) {
            int e = t * 256 + tid;
            int kr = e >> 4, cc = e & 15;
            cpa16(sb + U_B * 2 + (kr * BST + cc * 8) * 2,
                  g_Vt + (size_t)(k0 + kr) * FourH + colBase + cc * 8);
        }
        CP_COMMIT();
    };

    float C[2][4][4];
    #pragma unroll
    for (int m = 0; m < 2; m++)
        #pragma unroll
        for (int n = 0; n < 4; n++)
            #pragma unroll
            for (int q = 0; q < 4; q++) C[m][n][q] = 0.f;

    load_chunk(0, 0);
    load_chunk(64, 1);

    #pragma unroll
    for (int ck = 0; ck < 2; ck++) {
        if (ck == 0) { CP_WAIT1(); } else { CP_WAIT0(); }
        __syncthreads();

        __half* sA = smh + ck * STAGE_UNITS + U_A;
        __half* sB = smh + ck * STAGE_UNITS + U_B;

        #pragma unroll
        for (int kk = 0; kk < 64; kk += 16) {
            uint32_t bF[4][2];
            #pragma unroll
            for (int p = 0; p < 2; p++) {
                int kr = kk + (lane & 15);
                int nc = wn * 32 + p * 16 + 8 * (lane >> 4);
                uint32_t r[4];
                ldsm_x4_t(r, smem_u32(&sB[kr * BST + nc]));
                bF[2 * p][0] = r[0]; bF[2 * p][1] = r[1];
                bF[2 * p + 1][0] = r[2]; bF[2 * p + 1][1] = r[3];
            }
            #pragma unroll
            for (int m = 0; m < 2; m++) {
                uint32_t aF[4];
                int row = wm * 32 + m * 16 + (lane & 15);
                int col = kk + 8 * (lane >> 4);
                ldsm_x4(aF, smem_u32(&sA[row * AST + col]));
                #pragma unroll
                for (int n = 0; n < 4; n++)
                    mma16816h(C[m][n], aF, bF[n][0], bF[n][1]);
            }
        }
    }
    __syncthreads();

    // ---------------- epilogue: stage C in smem, coalesced I/O ----------------
    float* sC = (float*)smh;
    int quad = lane >> 2, a4 = lane & 3;

    #pragma unroll
    for (int n = 0; n < 4; n++) {
        int col = wn * 32 + n * 8 + a4 * 2;
        #pragma unroll
        for (int m = 0; m < 2; m++) {
            int r0 = wm * 32 + m * 16 + quad;
            *(float2*)&sC[r0 * CST + col]       = make_float2(C[m][n][0], C[m][n][1]);
            *(float2*)&sC[(r0 + 8) * CST + col] = make_float2(C[m][n][2], C[m][n][3]);
        }
    }
    __syncthreads();

    int jl = tid & 31;
    int j  = (colBase >> 2) + jl;
    bool hasX = (j < In);

    float4 cfx = *(const float4*)(g_cfx  + (size_t)j * 4);
    float4 cfh = *(const float4*)(g_cfh  + (size_t)j * 4);
    float4 bs  = *(const float4*)(g_bias + (size_t)j * 4);
    float dxv = hasX ? dia_x[j] : 0.f;
    float dhv = dia_h[j];

    #pragma unroll
    for (int pass = 0; pass < 8; pass++) {
        int bl = pass * 8 + (tid >> 5);
        int b  = rowBase + bl;

        float4 g4 = *(const float4*)&sC[bl * CST + jl * 4];
        float xv = hasX ? x[(size_t)b * In + j] : 0.f;
        float hv = h[(size_t)b * Hn + j];
        float cv = c[(size_t)b * Hn + j];
        float z  = dxv * xv + dhv * hv;

        float gi = g4.x - xv * cfx.x - hv * cfh.x + bs.x + z;
        float gf = g4.y - xv * cfx.y - hv * cfh.y + bs.y + z;
        float go = g4.z - xv * cfx.z - hv * cfh.z + bs.z + z;
        float gn = g4.w - xv * cfx.w - hv * cfh.w + bs.w + z;

        float ig = fsigmoid(gi);
        float fg = fsigmoid(gf);
        float og = fsigmoid(go);
        float ng = ftanh(gn);

        float cn = fg * cv + ig * ng;
        float hn = og * ftanh(cn);

        out[(size_t)b * Hn + j]                   = hn;
        out[(size_t)Bn * Hn + (size_t)b * Hn + j] = cn;
    }
}

// ------------------------------------------------------------------
extern "C" void kernel_launch(void* const* d_in, const int* in_sizes, int n_in,
                              void* d_out, int out_size) {
    const float* x     = (const float*)d_in[0];
    const float* h     = (const float*)d_in[1];
    const float* c     = (const float*)d_in[2];
    const float* u_x   = (const float*)d_in[3];
    const float* u_h   = (const float*)d_in[4];
    const float* v_x   = (const float*)d_in[5];
    const float* v_h   = (const float*)d_in[6];
    const float* b_x   = (const float*)d_in[7];
    const float* b_h   = (const float*)d_in[8];
    const float* dia_x = (const float*)d_in[9];
    const float* dia_h = (const float*)d_in[10];
    float* out = (float*)d_out;

    prep_coef_kernel<<<FourH / 256, 256>>>(u_x, u_h, v_x, v_h, b_x, b_h);
    prep_vt_kernel<<<(128 * FourH) / 256, 256>>>(v_x, v_h);

    proj_part_kernel<<<dim3(Bn / 64, 12), 256>>>(x, u_x, h, u_h);
    combine_kernel<<<(Bn * 32) / 256, 256>>>();

    cudaFuncSetAttribute(main_kernel,
                         cudaFuncAttributeMaxDynamicSharedMemorySize, SMEM_TOTAL);
    dim3 grid(FourH / 128, Bn / 64);
    main_kernel<<<grid, 256, SMEM_TOTAL>>>(x, h, c, dia_x, dia_h, out);
}

// round 10
// speedup vs baseline: 3.4621x; 1.0760x over previous
#include <cuda_runtime.h>
#include <cuda_bf16.h>
#include <cuda_fp16.h>
#include <math.h>
#include <stdint.h>

#define Bn   8192
#define In   512
#define Hn   1024
#define Rn   64
#define FourH 4096
#define SLAB (Bn * 64)

// ------------------------------------------------------------------
// Device scratch
// ------------------------------------------------------------------
__device__ __half g_Pf[Bn * 128];          // P fp16 [B][128]
__device__ __half g_Vt[128 * FourH];       // Vt fp16 [k][4096], col = j*4+g
__device__ float g_Pp[12 * SLAB];          // proj partial slabs
__device__ float g_cfx[FourH];
__device__ float g_cfh[FourH];
__device__ float g_bias[FourH];

// ------------------------------------------------------------------
// PTX helpers
// ------------------------------------------------------------------
__device__ __forceinline__ uint32_t smem_u32(const void* p) {
    return (uint32_t)__cvta_generic_to_shared(p);
}
__device__ __forceinline__ void ldsm_x4(uint32_t* r, uint32_t a) {
    asm volatile("ldmatrix.sync.aligned.m8n8.x4.shared.b16 {%0,%1,%2,%3}, [%4];"
        : "=r"(r[0]), "=r"(r[1]), "=r"(r[2]), "=r"(r[3]) : "r"(a));
}
__device__ __forceinline__ void ldsm_x4_t(uint32_t* r, uint32_t a) {
    asm volatile("ldmatrix.sync.aligned.m8n8.x4.trans.shared.b16 {%0,%1,%2,%3}, [%4];"
        : "=r"(r[0]), "=r"(r[1]), "=r"(r[2]), "=r"(r[3]) : "r"(a));
}
// bf16 mma (proj)
__device__ __forceinline__ void mma16816(float* c, const uint32_t* a,
                                         uint32_t b0, uint32_t b1) {
    asm volatile("mma.sync.aligned.m16n8k16.row.col.f32.bf16.bf16.f32 "
        "{%0,%1,%2,%3}, {%4,%5,%6,%7}, {%8,%9}, {%0,%1,%2,%3};"
        : "+f"(c[0]), "+f"(c[1]), "+f"(c[2]), "+f"(c[3])
        : "r"(a[0]), "r"(a[1]), "r"(a[2]), "r"(a[3]), "r"(b0), "r"(b1));
}
// fp16 mma (main)
__device__ __forceinline__ void mma16816h(float* c, const uint32_t* a,
                                          uint32_t b0, uint32_t b1) {
    asm volatile("mma.sync.aligned.m16n8k16.row.col.f32.f16.f16.f32 "
        "{%0,%1,%2,%3}, {%4,%5,%6,%7}, {%8,%9}, {%0,%1,%2,%3};"
        : "+f"(c[0]), "+f"(c[1]), "+f"(c[2]), "+f"(c[3])
        : "r"(a[0]), "r"(a[1]), "r"(a[2]), "r"(a[3]), "r"(b0), "r"(b1));
}
__device__ __forceinline__ uint32_t pack_bf16(__nv_bfloat16 lo16, __nv_bfloat16 hi16) {
    return (uint32_t)__bfloat16_as_ushort(lo16) |
           ((uint32_t)__bfloat16_as_ushort(hi16) << 16);
}
__device__ __forceinline__ uint32_t pack_f16(__half lo16, __half hi16) {
    return (uint32_t)__half_as_ushort(lo16) |
           ((uint32_t)__half_as_ushort(hi16) << 16);
}
__device__ __forceinline__ void cpa16(uint32_t dst, const void* src) {
    asm volatile("cp.async.cg.shared.global [%0], [%1], 16;"
        :: "r"(dst), "l"(src) : "memory");
}
#define CP_COMMIT() asm volatile("cp.async.commit_group;" ::: "memory")
#define CP_WAIT1()  asm volatile("cp.async.wait_group 1;" ::: "memory")
#define CP_WAIT0()  asm volatile("cp.async.wait_group 0;" ::: "memory")

// fast activations via MUFU.TANH (sm_75+): 1 MUFU each
__device__ __forceinline__ float tanha(float v) {
    float r;
    asm("tanh.approx.f32 %0, %1;" : "=f"(r) : "f"(v));
    return r;
}
__device__ __forceinline__ float fsigmoid(float v) {
    return fmaf(0.5f, tanha(0.5f * v), 0.5f);
}

// ------------------------------------------------------------------
// Prep 1: coefficients + fused bias (fp32, exact)
// ------------------------------------------------------------------
__global__ void prep_coef_kernel(const float* __restrict__ u_x,
                                 const float* __restrict__ u_h,
                                 const float* __restrict__ v_x,
                                 const float* __restrict__ v_h,
                                 const float* __restrict__ b_x,
                                 const float* __restrict__ b_h) {
    int idx = blockIdx.x * blockDim.x + threadIdx.x;   // j*4+g
    if (idx >= FourH) return;
    int j = idx >> 2;
    int g = idx & 3;
    int row4h = g * Hn + j;

    float cx = 0.f;
    if (j < In) {
        const float* uxr = u_x + j * Rn;
        const float* vxr = v_x + row4h * Rn;
        #pragma unroll 8
        for (int r = 0; r < Rn; r++) cx += uxr[r] * vxr[r];
    }
    float ch = 0.f;
    {
        const float* uhr = u_h + j * Rn;
        const float* vhr = v_h + row4h * Rn;
        #pragma unroll 8
        for (int r = 0; r < Rn; r++) ch += uhr[r] * vhr[r];
    }
    g_cfx[idx]  = cx;
    g_cfh[idx]  = ch;
    g_bias[idx] = b_x[row4h] + b_h[row4h];
}

// ------------------------------------------------------------------
// Prep 2: Vt fp16   [k=0..127][col=j*4+g]
// ------------------------------------------------------------------
__global__ void prep_vt_kernel(const float* __restrict__ v_x,
                               const float* __restrict__ v_h) {
    int idx = blockIdx.x * blockDim.x + threadIdx.x;
    int r   = idx >> 12;
    int col = idx & (FourH - 1);
    int j = col >> 2;
    int g = col & 3;
    int row4h = g * Hn + j;
    float v = (r < 64) ? v_x[row4h * Rn + r] : v_h[row4h * Rn + (r - 64)];
    g_Vt[idx] = __float2half(v);
}

// ------------------------------------------------------------------
// Projection split-K partials (bf16 3-pass HMMA, fp32 out).
// 12 slices of K=128: slices 0-3 = x@u_x, slices 4-11 = h@u_h.
// ------------------------------------------------------------------
__global__ __launch_bounds__(256)
void proj_part_kernel(const float* __restrict__ x, const float* __restrict__ u_x,
                      const float* __restrict__ h, const float* __restrict__ u_h) {
    __shared__ __nv_bfloat16 sA[2][64 * 72];
    __shared__ __nv_bfloat16 sB[2][64 * 72];

    int tid = threadIdx.x;
    int lane = tid & 31, w = tid >> 5;
    int wm = w >> 1, wn = w & 1;

    int slice = blockIdx.y;
    bool isX = (slice < 4);
    const float* A = isX ? x   : h;
    const float* U = isX ? u_x : u_h;
    int K      = isX ? In : Hn;
    int kBase  = (isX ? slice : (slice - 4)) * 128;
    int rowBase = blockIdx.x * 64;
    float* outSlab = g_Pp + (size_t)slice * SLAB;

    float C[4][4];
    #pragma unroll
    for (int n = 0; n < 4; n++)
        #pragma unroll
        for (int q = 0; q < 4; q++) C[n][q] = 0.f;

    #pragma unroll
    for (int kc = 0; kc < 2; kc++) {
        int k0 = kBase + kc * 64;
        #pragma unroll
        for (int p = 0; p < 4; p++) {
            int e = p * 256 + tid;
            int row = e >> 4, c4 = e & 15;
            float4 v = *(const float4*)(A + (size_t)(rowBase + row) * K + k0 + c4 * 4);
            __nv_bfloat16 h0 = __float2bfloat16(v.x), h1 = __float2bfloat16(v.y);
            __nv_bfloat16 h2 = __float2bfloat16(v.z), h3 = __float2bfloat16(v.w);
            uint2 hv; hv.x = pack_bf16(h0, h1); hv.y = pack_bf16(h2, h3);
            *(uint2*)&sA[0][row * 72 + c4 * 4] = hv;
            uint2 lv;
            lv.x = pack_bf16(__float2bfloat16(v.x - __bfloat162float(h0)),
                             __float2bfloat16(v.y - __bfloat162float(h1)));
            lv.y = pack_bf16(__float2bfloat16(v.z - __bfloat162float(h2)),
                             __float2bfloat16(v.w - __bfloat162float(h3)));
            *(uint2*)&sA[1][row * 72 + c4 * 4] = lv;
            float4 u = *(const float4*)(U + (size_t)(k0 + row) * 64 + c4 * 4);
            __nv_bfloat16 g0 = __float2bfloat16(u.x), g1 = __float2bfloat16(u.y);
            __nv_bfloat16 g2 = __float2bfloat16(u.z), g3 = __float2bfloat16(u.w);
            uint2 hu; hu.x = pack_bf16(g0, g1); hu.y = pack_bf16(g2, g3);
            *(uint2*)&sB[0][row * 72 + c4 * 4] = hu;
            uint2 lu;
            lu.x = pack_bf16(__float2bfloat16(u.x - __bfloat162float(g0)),
                             __float2bfloat16(u.y - __bfloat162float(g1)));
            lu.y = pack_bf16(__float2bfloat16(u.z - __bfloat162float(g2)),
                             __float2bfloat16(u.w - __bfloat162float(g3)));
            *(uint2*)&sB[1][row * 72 + c4 * 4] = lu;
        }
        __syncthreads();

        #pragma unroll
        for (int kk = 0; kk < 64; kk += 16) {
            uint32_t aH[4], aL[4];
            {
                int row = wm * 16 + (lane & 15);
                int col = kk + 8 * (lane >> 4);
                ldsm_x4(aH, smem_u32(&sA[0][row * 72 + col]));
                ldsm_x4(aL, smem_u32(&sA[1][row * 72 + col]));
            }
            uint32_t bH[4][2], bL[4][2];
            #pragma unroll
            for (int p = 0; p < 2; p++) {
                int kr = kk + (lane & 15);
                int nc = wn * 32 + p * 16 + 8 * (lane >> 4);
                uint32_t r[4];
                ldsm_x4_t(r, smem_u32(&sB[0][kr * 72 + nc]));
                bH[2 * p][0] = r[0]; bH[2 * p][1] = r[1];
                bH[2 * p + 1][0] = r[2]; bH[2 * p + 1][1] = r[3];
                ldsm_x4_t(r, smem_u32(&sB[1][kr * 72 + nc]));
                bL[2 * p][0] = r[0]; bL[2 * p][1] = r[1];
                bL[2 * p + 1][0] = r[2]; bL[2 * p + 1][1] = r[3];
            }
            #pragma unroll
            for (int n = 0; n < 4; n++) {
                mma16816(C[n], aH, bH[n][0], bH[n][1]);
                mma16816(C[n], aH, bL[n][0], bL[n][1]);
                mma16816(C[n], aL, bH[n][0], bH[n][1]);
            }
        }
        __syncthreads();
    }

    int quad = lane >> 2, a4 = lane & 3;
    #pragma unroll
    for (int n = 0; n < 4; n++) {
        int col = wn * 32 + n * 8 + a4 * 2;
        int r0  = rowBase + wm * 16 + quad;
        *(float2*)(outSlab + (size_t)r0 * 64 + col) = make_float2(C[n][0], C[n][1]);
        *(float2*)(outSlab + (size_t)(r0 + 8) * 64 + col) = make_float2(C[n][2], C[n][3]);
    }
}

// ------------------------------------------------------------------
// Combine: sum partial slabs (4 for x-cols, 8 for h-cols), emit P fp16.
// ------------------------------------------------------------------
__global__ __launch_bounds__(256)
void combine_kernel() {
    int idx = blockIdx.x * 256 + threadIdx.x;     // 0 .. Bn*32-1
    int row = idx >> 5;
    int c4  = idx & 31;
    int col = c4 * 4;

    float4 v = make_float4(0.f, 0.f, 0.f, 0.f);
    if (col < 64) {
        const float* p = g_Pp + (size_t)row * 64 + col;
        #pragma unroll
        for (int s = 0; s < 4; s++) {
            float4 a = *(const float4*)(p + (size_t)s * SLAB);
            v.x += a.x; v.y += a.y; v.z += a.z; v.w += a.w;
        }
    } else {
        const float* p = g_Pp + 4 * (size_t)SLAB + (size_t)row * 64 + (col - 64);
        #pragma unroll
        for (int s = 0; s < 8; s++) {
            float4 a = *(const float4*)(p + (size_t)s * SLAB);
            v.x += a.x; v.y += a.y; v.z += a.z; v.w += a.w;
        }
    }

    uint2 w;
    w.x = pack_f16(__float2half(v.x), __float2half(v.y));
    w.y = pack_f16(__float2half(v.z), __float2half(v.w));
    *(uint2*)&g_Pf[(size_t)row * 128 + col] = w;
}

// ------------------------------------------------------------------
// Main GEMM (P @ Vt, K=128, fp16 single-pass) + coalesced epilogue.
// CTA tile M=64 x N=128, 256 thr, 8 warps (2m x 4n), warp 32x32.
// Two K=64 chunks, double-buffered, 3 barriers. Target 4 CTAs/SM.
// ------------------------------------------------------------------
#define AST 72
#define BST 136
#define U_A  0
#define U_B  (64 * AST)
#define STAGE_UNITS (64 * AST + 64 * BST)            // 13312 units = 26624 B
#define CST 132
#define SMEM_TOTAL (2 * STAGE_UNITS * 2)             // 53248 B (sC 33792 fits)

__global__ __launch_bounds__(256, 4)
void main_kernel(const float* __restrict__ x, const float* __restrict__ h,
                 const float* __restrict__ c,
                 const float* __restrict__ dia_x, const float* __restrict__ dia_h,
                 float* __restrict__ out) {
    extern __shared__ __half smh[];

    int tid = threadIdx.x;
    int lane = tid & 31, w = tid >> 5;
    int wm = w >> 2, wn = w & 3;
    int rowBase = blockIdx.y * 64;
    int colBase = blockIdx.x * 128;

    uint32_t sbase = smem_u32(smh);

    auto load_chunk = [&](int k0, int stage) {
        uint32_t sb = sbase + stage * STAGE_UNITS * 2;
        #pragma unroll
        for (int t = 0; t < 2; t++) {
            int e = t * 256 + tid;
            int r = e >> 3, cc = e & 7;
            cpa16(sb + U_A * 2 + (r * AST + cc * 8) * 2,
                  g_Pf + (size_t)(rowBase + r) * 128 + k0 + cc * 8);
        }
        #pragma unroll
        for (int t = 0; t < 4; t++) {
            int e = t * 256 + tid;
            int kr = e >> 4, cc = e & 15;
            cpa16(sb + U_B * 2 + (kr * BST + cc * 8) * 2,
                  g_Vt + (size_t)(k0 + kr) * FourH + colBase + cc * 8);
        }
        CP_COMMIT();
    };

    float C[2][4][4];
    #pragma unroll
    for (int m = 0; m < 2; m++)
        #pragma unroll
        for (int n = 0; n < 4; n++)
            #pragma unroll
            for (int q = 0; q < 4; q++) C[m][n][q] = 0.f;

    load_chunk(0, 0);
    load_chunk(64, 1);

    #pragma unroll
    for (int ck = 0; ck < 2; ck++) {
        if (ck == 0) { CP_WAIT1(); } else { CP_WAIT0(); }
        __syncthreads();

        __half* sA = smh + ck * STAGE_UNITS + U_A;
        __half* sB = smh + ck * STAGE_UNITS + U_B;

        #pragma unroll
        for (int kk = 0; kk < 64; kk += 16) {
            uint32_t bF[4][2];
            #pragma unroll
            for (int p = 0; p < 2; p++) {
                int kr = kk + (lane & 15);
                int nc = wn * 32 + p * 16 + 8 * (lane >> 4);
                uint32_t r[4];
                ldsm_x4_t(r, smem_u32(&sB[kr * BST + nc]));
                bF[2 * p][0] = r[0]; bF[2 * p][1] = r[1];
                bF[2 * p + 1][0] = r[2]; bF[2 * p + 1][1] = r[3];
            }
            #pragma unroll
            for (int m = 0; m < 2; m++) {
                uint32_t aF[4];
                int row = wm * 32 + m * 16 + (lane & 15);
                int col = kk + 8 * (lane >> 4);
                ldsm_x4(aF, smem_u32(&sA[row * AST + col]));
                #pragma unroll
                for (int n = 0; n < 4; n++)
                    mma16816h(C[m][n], aF, bF[n][0], bF[n][1]);
            }
        }
    }
    __syncthreads();

    // ---------------- epilogue: stage C in smem, coalesced I/O ----------------
    float* sC = (float*)smh;
    int quad = lane >> 2, a4 = lane & 3;

    #pragma unroll
    for (int n = 0; n < 4; n++) {
        int col = wn * 32 + n * 8 + a4 * 2;
        #pragma unroll
        for (int m = 0; m < 2; m++) {
            int r0 = wm * 32 + m * 16 + quad;
            *(float2*)&sC[r0 * CST + col]       = make_float2(C[m][n][0], C[m][n][1]);
            *(float2*)&sC[(r0 + 8) * CST + col] = make_float2(C[m][n][2], C[m][n][3]);
        }
    }
    __syncthreads();

    int jl = tid & 31;
    int j  = (colBase >> 2) + jl;
    bool hasX = (j < In);

    float4 cfx = *(const float4*)(g_cfx  + (size_t)j * 4);
    float4 cfh = *(const float4*)(g_cfh  + (size_t)j * 4);
    float4 bs  = *(const float4*)(g_bias + (size_t)j * 4);
    float dxv = hasX ? dia_x[j] : 0.f;
    float dhv = dia_h[j];

    #pragma unroll
    for (int pass = 0; pass < 8; pass++) {
        int bl = pass * 8 + (tid >> 5);
        int b  = rowBase + bl;

        float4 g4 = *(const float4*)&sC[bl * CST + jl * 4];
        float xv = hasX ? x[(size_t)b * In + j] : 0.f;
        float hv = h[(size_t)b * Hn + j];
        float cv = c[(size_t)b * Hn + j];
        float z  = dxv * xv + dhv * hv;

        float gi = g4.x - xv * cfx.x - hv * cfh.x + bs.x + z;
        float gf = g4.y - xv * cfx.y - hv * cfh.y + bs.y + z;
        float go = g4.z - xv * cfx.z - hv * cfh.z + bs.z + z;
        float gn = g4.w - xv * cfx.w - hv * cfh.w + bs.w + z;

        float ig = fsigmoid(gi);
        float fg = fsigmoid(gf);
        float og = fsigmoid(go);
        float ng = tanha(gn);

        float cn = fg * cv + ig * ng;
        float hn = og * tanha(cn);

        out[(size_t)b * Hn + j]                   = hn;
        out[(size_t)Bn * Hn + (size_t)b * Hn + j] = cn;
    }
}

// ------------------------------------------------------------------
extern "C" void kernel_launch(void* const* d_in, const int* in_sizes, int n_in,
                              void* d_out, int out_size) {
    const float* x     = (const float*)d_in[0];
    const float* h     = (const float*)d_in[1];
    const float* c     = (const float*)d_in[2];
    const float* u_x   = (const float*)d_in[3];
    const float* u_h   = (const float*)d_in[4];
    const float* v_x   = (const float*)d_in[5];
    const float* v_h   = (const float*)d_in[6];
    const float* b_x   = (const float*)d_in[7];
    const float* b_h   = (const float*)d_in[8];
    const float* dia_x = (const float*)d_in[9];
    const float* dia_h = (const float*)d_in[10];
    float* out = (float*)d_out;

    prep_coef_kernel<<<FourH / 256, 256>>>(u_x, u_h, v_x, v_h, b_x, b_h);
    prep_vt_kernel<<<(128 * FourH) / 256, 256>>>(v_x, v_h);

    proj_part_kernel<<<dim3(Bn / 64, 12), 256>>>(x, u_x, h, u_h);
    combine_kernel<<<(Bn * 32) / 256, 256>>>();

    cudaFuncSetAttribute(main_kernel,
                         cudaFuncAttributeMaxDynamicSharedMemorySize, SMEM_TOTAL);
    dim3 grid(FourH / 128, Bn / 64);
    main_kernel<<<grid, 256, SMEM_TOTAL>>>(x, h, c, dia_x, dia_h, out);
}

// round 12
// speedup vs baseline: 3.4764x; 1.0041x over previous
#include <cuda_runtime.h>
#include <cuda_bf16.h>
#include <cuda_fp16.h>
#include <math.h>
#include <stdint.h>

#define Bn   8192
#define In   512
#define Hn   1024
#define Rn   64
#define FourH 4096
#define SLAB (Bn * 64)

// ------------------------------------------------------------------
// Device scratch
// ------------------------------------------------------------------
__device__ __half g_Pf[Bn * 128];          // P fp16 [B][128]
__device__ __half g_Vt[128 * FourH];       // Vt fp16 [k][4096], col = j*4+g
__device__ float g_Pp[12 * SLAB];          // proj partial slabs
__device__ float g_cfx[FourH];
__device__ float g_cfh[FourH];
__device__ float g_bias[FourH];

// ------------------------------------------------------------------
// PTX helpers
// ------------------------------------------------------------------
__device__ __forceinline__ uint32_t smem_u32(const void* p) {
    return (uint32_t)__cvta_generic_to_shared(p);
}
__device__ __forceinline__ void ldsm_x4(uint32_t* r, uint32_t a) {
    asm volatile("ldmatrix.sync.aligned.m8n8.x4.shared.b16 {%0,%1,%2,%3}, [%4];"
        : "=r"(r[0]), "=r"(r[1]), "=r"(r[2]), "=r"(r[3]) : "r"(a));
}
__device__ __forceinline__ void ldsm_x4_t(uint32_t* r, uint32_t a) {
    asm volatile("ldmatrix.sync.aligned.m8n8.x4.trans.shared.b16 {%0,%1,%2,%3}, [%4];"
        : "=r"(r[0]), "=r"(r[1]), "=r"(r[2]), "=r"(r[3]) : "r"(a));
}
// fp16 mma
__device__ __forceinline__ void mma16816h(float* c, const uint32_t* a,
                                          uint32_t b0, uint32_t b1) {
    asm volatile("mma.sync.aligned.m16n8k16.row.col.f32.f16.f16.f32 "
        "{%0,%1,%2,%3}, {%4,%5,%6,%7}, {%8,%9}, {%0,%1,%2,%3};"
        : "+f"(c[0]), "+f"(c[1]), "+f"(c[2]), "+f"(c[3])
        : "r"(a[0]), "r"(a[1]), "r"(a[2]), "r"(a[3]), "r"(b0), "r"(b1));
}
__device__ __forceinline__ uint32_t pack_f16(__half lo16, __half hi16) {
    return (uint32_t)__half_as_ushort(lo16) |
           ((uint32_t)__half_as_ushort(hi16) << 16);
}
__device__ __forceinline__ void cpa16(uint32_t dst, const void* src) {
    asm volatile("cp.async.cg.shared.global [%0], [%1], 16;"
        :: "r"(dst), "l"(src) : "memory");
}
__device__ __forceinline__ void prefetchL2(const void* p) {
    asm volatile("prefetch.global.L2 [%0];" :: "l"(p));
}
#define CP_COMMIT() asm volatile("cp.async.commit_group;" ::: "memory")
#define CP_WAIT1()  asm volatile("cp.async.wait_group 1;" ::: "memory")
#define CP_WAIT0()  asm volatile("cp.async.wait_group 0;" ::: "memory")

// fast activations via MUFU.TANH (sm_75+): 1 MUFU each
__device__ __forceinline__ float tanha(float v) {
    float r;
    asm("tanh.approx.f32 %0, %1;" : "=f"(r) : "f"(v));
    return r;
}
__device__ __forceinline__ float fsigmoid(float v) {
    return fmaf(0.5f, tanha(0.5f * v), 0.5f);
}

// ------------------------------------------------------------------
// Prep 1: coefficients + fused bias (fp32, exact)
// ------------------------------------------------------------------
__global__ void prep_coef_kernel(const float* __restrict__ u_x,
                                 const float* __restrict__ u_h,
                                 const float* __restrict__ v_x,
                                 const float* __restrict__ v_h,
                                 const float* __restrict__ b_x,
                                 const float* __restrict__ b_h) {
    int idx = blockIdx.x * blockDim.x + threadIdx.x;   // j*4+g
    if (idx >= FourH) return;
    int j = idx >> 2;
    int g = idx & 3;
    int row4h = g * Hn + j;

    float cx = 0.f;
    if (j < In) {
        const float* uxr = u_x + j * Rn;
        const float* vxr = v_x + row4h * Rn;
        #pragma unroll 8
        for (int r = 0; r < Rn; r++) cx += uxr[r] * vxr[r];
    }
    float ch = 0.f;
    {
        const float* uhr = u_h + j * Rn;
        const float* vhr = v_h + row4h * Rn;
        #pragma unroll 8
        for (int r = 0; r < Rn; r++) ch += uhr[r] * vhr[r];
    }
    g_cfx[idx]  = cx;
    g_cfh[idx]  = ch;
    g_bias[idx] = b_x[row4h] + b_h[row4h];
}

// ------------------------------------------------------------------
// Prep 2: Vt fp16   [k=0..127][col=j*4+g]
// ------------------------------------------------------------------
__global__ void prep_vt_kernel(const float* __restrict__ v_x,
                               const float* __restrict__ v_h) {
    int idx = blockIdx.x * blockDim.x + threadIdx.x;
    int r   = idx >> 12;
    int col = idx & (FourH - 1);
    int j = col >> 2;
    int g = col & 3;
    int row4h = g * Hn + j;
    float v = (r < 64) ? v_x[row4h * Rn + r] : v_h[row4h * Rn + (r - 64)];
    g_Vt[idx] = __float2half(v);
}

// ------------------------------------------------------------------
// Projection split-K partials (fp16 single-pass HMMA, fp32 out).
// 12 slices of K=128: slices 0-3 = x@u_x, slices 4-11 = h@u_h.
// CTA: 64 rows x 64 cols, 2 serial k-chunks of 64. Warps 4m x 2n, warp 16x32.
// ------------------------------------------------------------------
__global__ __launch_bounds__(256)
void proj_part_kernel(const float* __restrict__ x, const float* __restrict__ u_x,
                      const float* __restrict__ h, const float* __restrict__ u_h) {
    __shared__ __half sA[64 * 72];
    __shared__ __half sB[64 * 72];

    int tid = threadIdx.x;
    int lane = tid & 31, w = tid >> 5;
    int wm = w >> 1, wn = w & 1;

    int slice = blockIdx.y;
    bool isX = (slice < 4);
    const float* A = isX ? x   : h;
    const float* U = isX ? u_x : u_h;
    int K      = isX ? In : Hn;
    int kBase  = (isX ? slice : (slice - 4)) * 128;
    int rowBase = blockIdx.x * 64;
    float* outSlab = g_Pp + (size_t)slice * SLAB;

    float C[4][4];
    #pragma unroll
    for (int n = 0; n < 4; n++)
        #pragma unroll
        for (int q = 0; q < 4; q++) C[n][q] = 0.f;

    #pragma unroll
    for (int kc = 0; kc < 2; kc++) {
        int k0 = kBase + kc * 64;
        #pragma unroll
        for (int p = 0; p < 4; p++) {
            int e = p * 256 + tid;
            int row = e >> 4, c4 = e & 15;
            float4 v = *(const float4*)(A + (size_t)(rowBase + row) * K + k0 + c4 * 4);
            uint2 hv;
            hv.x = pack_f16(__float2half(v.x), __float2half(v.y));
            hv.y = pack_f16(__float2half(v.z), __float2half(v.w));
            *(uint2*)&sA[row * 72 + c4 * 4] = hv;
            float4 u = *(const float4*)(U + (size_t)(k0 + row) * 64 + c4 * 4);
            uint2 hu;
            hu.x = pack_f16(__float2half(u.x), __float2half(u.y));
            hu.y = pack_f16(__float2half(u.z), __float2half(u.w));
            *(uint2*)&sB[row * 72 + c4 * 4] = hu;
        }
        __syncthreads();

        #pragma unroll
        for (int kk = 0; kk < 64; kk += 16) {
            uint32_t aF[4];
            {
                int row = wm * 16 + (lane & 15);
                int col = kk + 8 * (lane >> 4);
                ldsm_x4(aF, smem_u32(&sA[row * 72 + col]));
            }
            uint32_t bF[4][2];
            #pragma unroll
            for (int p = 0; p < 2; p++) {
                int kr = kk + (lane & 15);
                int nc = wn * 32 + p * 16 + 8 * (lane >> 4);
                uint32_t r[4];
                ldsm_x4_t(r, smem_u32(&sB[kr * 72 + nc]));
                bF[2 * p][0] = r[0]; bF[2 * p][1] = r[1];
                bF[2 * p + 1][0] = r[2]; bF[2 * p + 1][1] = r[3];
            }
            #pragma unroll
            for (int n = 0; n < 4; n++)
                mma16816h(C[n], aF, bF[n][0], bF[n][1]);
        }
        __syncthreads();
    }

    int quad = lane >> 2, a4 = lane & 3;
    #pragma unroll
    for (int n = 0; n < 4; n++) {
        int col = wn * 32 + n * 8 + a4 * 2;
        int r0  = rowBase + wm * 16 + quad;
        *(float2*)(outSlab + (size_t)r0 * 64 + col) = make_float2(C[n][0], C[n][1]);
        *(float2*)(outSlab + (size_t)(r0 + 8) * 64 + col) = make_float2(C[n][2], C[n][3]);
    }
}

// ------------------------------------------------------------------
// Combine: sum partial slabs (4 for x-cols, 8 for h-cols), emit P fp16.
// ------------------------------------------------------------------
__global__ __launch_bounds__(256)
void combine_kernel() {
    int idx = blockIdx.x * 256 + threadIdx.x;     // 0 .. Bn*32-1
    int row = idx >> 5;
    int c4  = idx & 31;
    int col = c4 * 4;

    float4 v = make_float4(0.f, 0.f, 0.f, 0.f);
    if (col < 64) {
        const float* p = g_Pp + (size_t)row * 64 + col;
        #pragma unroll
        for (int s = 0; s < 4; s++) {
            float4 a = *(const float4*)(p + (size_t)s * SLAB);
            v.x += a.x; v.y += a.y; v.z += a.z; v.w += a.w;
        }
    } else {
        const float* p = g_Pp + 4 * (size_t)SLAB + (size_t)row * 64 + (col - 64);
        #pragma unroll
        for (int s = 0; s < 8; s++) {
            float4 a = *(const float4*)(p + (size_t)s * SLAB);
            v.x += a.x; v.y += a.y; v.z += a.z; v.w += a.w;
        }
    }

    uint2 w;
    w.x = pack_f16(__float2half(v.x), __float2half(v.y));
    w.y = pack_f16(__float2half(v.z), __float2half(v.w));
    *(uint2*)&g_Pf[(size_t)row * 128 + col] = w;
}

// ------------------------------------------------------------------
// Main GEMM (P @ Vt, K=128, fp16 single-pass) + coalesced epilogue.
// CTA tile M=64 x N=128, 256 thr, 8 warps (2m x 4n), warp 32x32.
// Two K=64 chunks, double-buffered, 3 barriers. 4 CTAs/SM.
// L2-prefetch of epilogue x/h/c tiles at entry.
// ------------------------------------------------------------------
#define AST 72
#define BST 136
#define U_A  0
#define U_B  (64 * AST)
#define STAGE_UNITS (64 * AST + 64 * BST)            // 13312 units = 26624 B
#define CST 132
#define SMEM_TOTAL (2 * STAGE_UNITS * 2)             // 53248 B (sC 33792 fits)

__global__ __launch_bounds__(256, 4)
void main_kernel(const float* __restrict__ x, const float* __restrict__ h,
                 const float* __restrict__ c,
                 const float* __restrict__ dia_x, const float* __restrict__ dia_h,
                 float* __restrict__ out) {
    extern __shared__ __half smh[];

    int tid = threadIdx.x;
    int lane = tid & 31, w = tid >> 5;
    int wm = w >> 2, wn = w & 3;
    int rowBase = blockIdx.y * 64;
    int colBase = blockIdx.x * 128;
    int j0 = colBase >> 2;
    bool ctaHasX = (j0 < In);

    // L2 prefetch of epilogue tiles: one 128B line per row per tensor.
    {
        int r = tid & 63;       // row within tile
        int which = tid >> 6;   // 0:x 1:h 2:c 3:none
        int b = rowBase + r;
        if (which == 0) {
            if (ctaHasX) prefetchL2(x + (size_t)b * In + j0);
        } else if (which == 1) {
            prefetchL2(h + (size_t)b * Hn + j0);
        } else if (which == 2) {
            prefetchL2(c + (size_t)b * Hn + j0);
        }
    }

    uint32_t sbase = smem_u32(smh);

    auto load_chunk = [&](int k0, int stage) {
        uint32_t sb = sbase + stage * STAGE_UNITS * 2;
        #pragma unroll
        for (int t = 0; t < 2; t++) {
            int e = t * 256 + tid;
            int r = e >> 3, cc = e & 7;
            cpa16(sb + U_A * 2 + (r * AST + cc * 8) * 2,
                  g_Pf + (size_t)(rowBase + r) * 128 + k0 + cc * 8);
        }
        #pragma unroll
        for (int t = 0; t < 4; t++) {
            int e = t * 256 + tid;
            int kr = e >> 4, cc = e & 15;
            cpa16(sb + U_B * 2 + (kr * BST + cc * 8) * 2,
                  g_Vt + (size_t)(k0 + kr) * FourH + colBase + cc * 8);
        }
        CP_COMMIT();
    };

    float C[2][4][4];
    #pragma unroll
    for (int m = 0; m < 2; m++)
        #pragma unroll
        for (int n = 0; n < 4; n++)
            #pragma unroll
            for (int q = 0; q < 4; q++) C[m][n][q] = 0.f;

    load_chunk(0, 0);
    load_chunk(64, 1);

    #pragma unroll
    for (int ck = 0; ck < 2; ck++) {
        if (ck == 0) { CP_WAIT1(); } else { CP_WAIT0(); }
        __syncthreads();

        __half* sA = smh + ck * STAGE_UNITS + U_A;
        __half* sB = smh + ck * STAGE_UNITS + U_B;

        #pragma unroll
        for (int kk = 0; kk < 64; kk += 16) {
            uint32_t bF[4][2];
            #pragma unroll
            for (int p = 0; p < 2; p++) {
                int kr = kk + (lane & 15);
                int nc = wn * 32 + p * 16 + 8 * (lane >> 4);
                uint32_t r[4];
                ldsm_x4_t(r, smem_u32(&sB[kr * BST + nc]));
                bF[2 * p][0] = r[0]; bF[2 * p][1] = r[1];
                bF[2 * p + 1][0] = r[2]; bF[2 * p + 1][1] = r[3];
            }
            #pragma unroll
            for (int m = 0; m < 2; m++) {
                uint32_t aF[4];
                int row = wm * 32 + m * 16 + (lane & 15);
                int col = kk + 8 * (lane >> 4);
                ldsm_x4(aF, smem_u32(&sA[row * AST + col]));
                #pragma unroll
                for (int n = 0; n < 4; n++)
                    mma16816h(C[m][n], aF, bF[n][0], bF[n][1]);
            }
        }
    }
    __syncthreads();

    // ---------------- epilogue: stage C in smem, coalesced I/O ----------------
    float* sC = (float*)smh;
    int quad = lane >> 2, a4 = lane & 3;

    #pragma unroll
    for (int n = 0; n < 4; n++) {
        int col = wn * 32 + n * 8 + a4 * 2;
        #pragma unroll
        for (int m = 0; m < 2; m++) {
            int r0 = wm * 32 + m * 16 + quad;
            *(float2*)&sC[r0 * CST + col]       = make_float2(C[m][n][0], C[m][n][1]);
            *(float2*)&sC[(r0 + 8) * CST + col] = make_float2(C[m][n][2], C[m][n][3]);
        }
    }
    __syncthreads();

    int jl = tid & 31;
    int j  = j0 + jl;
    bool hasX = ctaHasX;

    float4 cfx = *(const float4*)(g_cfx  + (size_t)j * 4);
    float4 cfh = *(const float4*)(g_cfh  + (size_t)j * 4);
    float4 bs  = *(const float4*)(g_bias + (size_t)j * 4);
    float dxv = hasX ? dia_x[j] : 0.f;
    float dhv = dia_h[j];

    #pragma unroll
    for (int pass = 0; pass < 8; pass++) {
        int bl = pass * 8 + (tid >> 5);
        int b  = rowBase + bl;

        float4 g4 = *(const float4*)&sC[bl * CST + jl * 4];
        float xv = hasX ? x[(size_t)b * In + j] : 0.f;
        float hv = h[(size_t)b * Hn + j];
        float cv = c[(size_t)b * Hn + j];
        float z  = dxv * xv + dhv * hv;

        float gi = g4.x - xv * cfx.x - hv * cfh.x + bs.x + z;
        float gf = g4.y - xv * cfx.y - hv * cfh.y + bs.y + z;
        float go = g4.z - xv * cfx.z - hv * cfh.z + bs.z + z;
        float gn = g4.w - xv * cfx.w - hv * cfh.w + bs.w + z;

        float ig = fsigmoid(gi);
        float fg = fsigmoid(gf);
        float og = fsigmoid(go);
        float ng = tanha(gn);

        float cn = fg * cv + ig * ng;
        float hn = og * tanha(cn);

        out[(size_t)b * Hn + j]                   = hn;
        out[(size_t)Bn * Hn + (size_t)b * Hn + j] = cn;
    }
}

// ------------------------------------------------------------------
extern "C" void kernel_launch(void* const* d_in, const int* in_sizes, int n_in,
                              void* d_out, int out_size) {
    const float* x     = (const float*)d_in[0];
    const float* h     = (const float*)d_in[1];
    const float* c     = (const float*)d_in[2];
    const float* u_x   = (const float*)d_in[3];
    const float* u_h   = (const float*)d_in[4];
    const float* v_x   = (const float*)d_in[5];
    const float* v_h   = (const float*)d_in[6];
    const float* b_x   = (const float*)d_in[7];
    const float* b_h   = (const float*)d_in[8];
    const float* dia_x = (const float*)d_in[9];
    const float* dia_h = (const float*)d_in[10];
    float* out = (float*)d_out;

    prep_coef_kernel<<<FourH / 256, 256>>>(u_x, u_h, v_x, v_h, b_x, b_h);
    prep_vt_kernel<<<(128 * FourH) / 256, 256>>>(v_x, v_h);

    proj_part_kernel<<<dim3(Bn / 64, 12), 256>>>(x, u_x, h, u_h);
    combine_kernel<<<(Bn * 32) / 256, 256>>>();

    cudaFuncSetAttribute(main_kernel,
                         cudaFuncAttributeMaxDynamicSharedMemorySize, SMEM_TOTAL);
    dim3 grid(FourH / 128, Bn / 64);
    main_kernel<<<grid, 256, SMEM_TOTAL>>>(x, h, c, dia_x, dia_h, out);
}

// round 13
// speedup vs baseline: 3.6723x; 1.0563x over previous
#include <cuda_runtime.h>
#include <cuda_bf16.h>
#include <cuda_fp16.h>
#include <math.h>
#include <stdint.h>

#define Bn   8192
#define In   512
#define Hn   1024
#define Rn   64
#define FourH 4096
#define SLAB (Bn * 64)

// ------------------------------------------------------------------
// Device scratch
// ------------------------------------------------------------------
__device__ __half g_Pf[Bn * 128];          // P fp16 [B][128]
__device__ __half g_Vt[128 * FourH];       // Vt fp16 [k][4096], col = j*4+g
__device__ float g_Pp[12 * SLAB];          // proj partial slabs
__device__ float g_cfx[FourH];
__device__ float g_cfh[FourH];
__device__ float g_bias[FourH];

// ------------------------------------------------------------------
// PTX helpers
// ------------------------------------------------------------------
__device__ __forceinline__ uint32_t smem_u32(const void* p) {
    return (uint32_t)__cvta_generic_to_shared(p);
}
__device__ __forceinline__ void ldsm_x4(uint32_t* r, uint32_t a) {
    asm volatile("ldmatrix.sync.aligned.m8n8.x4.shared.b16 {%0,%1,%2,%3}, [%4];"
        : "=r"(r[0]), "=r"(r[1]), "=r"(r[2]), "=r"(r[3]) : "r"(a));
}
__device__ __forceinline__ void ldsm_x4_t(uint32_t* r, uint32_t a) {
    asm volatile("ldmatrix.sync.aligned.m8n8.x4.trans.shared.b16 {%0,%1,%2,%3}, [%4];"
        : "=r"(r[0]), "=r"(r[1]), "=r"(r[2]), "=r"(r[3]) : "r"(a));
}
// fp16 mma
__device__ __forceinline__ void mma16816h(float* c, const uint32_t* a,
                                          uint32_t b0, uint32_t b1) {
    asm volatile("mma.sync.aligned.m16n8k16.row.col.f32.f16.f16.f32 "
        "{%0,%1,%2,%3}, {%4,%5,%6,%7}, {%8,%9}, {%0,%1,%2,%3};"
        : "+f"(c[0]), "+f"(c[1]), "+f"(c[2]), "+f"(c[3])
        : "r"(a[0]), "r"(a[1]), "r"(a[2]), "r"(a[3]), "r"(b0), "r"(b1));
}
__device__ __forceinline__ uint32_t pack_f16(__half lo16, __half hi16) {
    return (uint32_t)__half_as_ushort(lo16) |
           ((uint32_t)__half_as_ushort(hi16) << 16);
}
__device__ __forceinline__ void cpa16(uint32_t dst, const void* src) {
    asm volatile("cp.async.cg.shared.global [%0], [%1], 16;"
        :: "r"(dst), "l"(src) : "memory");
}
#define CP_COMMIT() asm volatile("cp.async.commit_group;" ::: "memory")
#define CP_WAIT1()  asm volatile("cp.async.wait_group 1;" ::: "memory")
#define CP_WAIT0()  asm volatile("cp.async.wait_group 0;" ::: "memory")

// fast activations via MUFU.TANH (sm_75+): 1 MUFU each
__device__ __forceinline__ float tanha(float v) {
    float r;
    asm("tanh.approx.f32 %0, %1;" : "=f"(r) : "f"(v));
    return r;
}
__device__ __forceinline__ float fsigmoid(float v) {
    return fmaf(0.5f, tanha(0.5f * v), 0.5f);
}

// ------------------------------------------------------------------
// Fused prep: Vt fp16 + (first FourH threads also do coef/bias)
// grid: (128*4096)/256 = 2048 blocks of 256
// ------------------------------------------------------------------
__global__ void prep_kernel(const float* __restrict__ u_x,
                            const float* __restrict__ u_h,
                            const float* __restrict__ v_x,
                            const float* __restrict__ v_h,
                            const float* __restrict__ b_x,
                            const float* __restrict__ b_h) {
    int idx = blockIdx.x * blockDim.x + threadIdx.x;
    // Vt part
    {
        int r   = idx >> 12;
        int col = idx & (FourH - 1);
        int j = col >> 2;
        int g = col & 3;
        int row4h = g * Hn + j;
        float v = (r < 64) ? v_x[row4h * Rn + r] : v_h[row4h * Rn + (r - 64)];
        g_Vt[idx] = __float2half(v);
    }
    // coef/bias part (first FourH threads)
    if (idx < FourH) {
        int j = idx >> 2;
        int g = idx & 3;
        int row4h = g * Hn + j;
        float cx = 0.f;
        if (j < In) {
            const float* uxr = u_x + j * Rn;
            const float* vxr = v_x + row4h * Rn;
            #pragma unroll 8
            for (int r = 0; r < Rn; r++) cx += uxr[r] * vxr[r];
        }
        float ch = 0.f;
        {
            const float* uhr = u_h + j * Rn;
            const float* vhr = v_h + row4h * Rn;
            #pragma unroll 8
            for (int r = 0; r < Rn; r++) ch += uhr[r] * vhr[r];
        }
        g_cfx[idx]  = cx;
        g_cfh[idx]  = ch;
        g_bias[idx] = b_x[row4h] + b_h[row4h];
    }
}

// ------------------------------------------------------------------
// Projection split-K partials (fp16 single-pass HMMA, fp32 out).
// 12 slices of K=128: slices 0-3 = x@u_x, slices 4-11 = h@u_h.
// CTA: 64 rows x 64 cols, 2 serial k-chunks of 64. Warps 4m x 2n, warp 16x32.
// ------------------------------------------------------------------
__global__ __launch_bounds__(256)
void proj_part_kernel(const float* __restrict__ x, const float* __restrict__ u_x,
                      const float* __restrict__ h, const float* __restrict__ u_h) {
    __shared__ __half sA[64 * 72];
    __shared__ __half sB[64 * 72];

    int tid = threadIdx.x;
    int lane = tid & 31, w = tid >> 5;
    int wm = w >> 1, wn = w & 1;

    int slice = blockIdx.y;
    bool isX = (slice < 4);
    const float* A = isX ? x   : h;
    const float* U = isX ? u_x : u_h;
    int K      = isX ? In : Hn;
    int kBase  = (isX ? slice : (slice - 4)) * 128;
    int rowBase = blockIdx.x * 64;
    float* outSlab = g_Pp + (size_t)slice * SLAB;

    float C[4][4];
    #pragma unroll
    for (int n = 0; n < 4; n++)
        #pragma unroll
        for (int q = 0; q < 4; q++) C[n][q] = 0.f;

    #pragma unroll
    for (int kc = 0; kc < 2; kc++) {
        int k0 = kBase + kc * 64;
        #pragma unroll
        for (int p = 0; p < 4; p++) {
            int e = p * 256 + tid;
            int row = e >> 4, c4 = e & 15;
            float4 v = *(const float4*)(A + (size_t)(rowBase + row) * K + k0 + c4 * 4);
            uint2 hv;
            hv.x = pack_f16(__float2half(v.x), __float2half(v.y));
            hv.y = pack_f16(__float2half(v.z), __float2half(v.w));
            *(uint2*)&sA[row * 72 + c4 * 4] = hv;
            float4 u = *(const float4*)(U + (size_t)(k0 + row) * 64 + c4 * 4);
            uint2 hu;
            hu.x = pack_f16(__float2half(u.x), __float2half(u.y));
            hu.y = pack_f16(__float2half(u.z), __float2half(u.w));
            *(uint2*)&sB[row * 72 + c4 * 4] = hu;
        }
        __syncthreads();

        #pragma unroll
        for (int kk = 0; kk < 64; kk += 16) {
            uint32_t aF[4];
            {
                int row = wm * 16 + (lane & 15);
                int col = kk + 8 * (lane >> 4);
                ldsm_x4(aF, smem_u32(&sA[row * 72 + col]));
            }
            uint32_t bF[4][2];
            #pragma unroll
            for (int p = 0; p < 2; p++) {
                int kr = kk + (lane & 15);
                int nc = wn * 32 + p * 16 + 8 * (lane >> 4);
                uint32_t r[4];
                ldsm_x4_t(r, smem_u32(&sB[kr * 72 + nc]));
                bF[2 * p][0] = r[0]; bF[2 * p][1] = r[1];
                bF[2 * p + 1][0] = r[2]; bF[2 * p + 1][1] = r[3];
            }
            #pragma unroll
            for (int n = 0; n < 4; n++)
                mma16816h(C[n], aF, bF[n][0], bF[n][1]);
        }
        __syncthreads();
    }

    int quad = lane >> 2, a4 = lane & 3;
    #pragma unroll
    for (int n = 0; n < 4; n++) {
        int col = wn * 32 + n * 8 + a4 * 2;
        int r0  = rowBase + wm * 16 + quad;
        *(float2*)(outSlab + (size_t)r0 * 64 + col) = make_float2(C[n][0], C[n][1]);
        *(float2*)(outSlab + (size_t)(r0 + 8) * 64 + col) = make_float2(C[n][2], C[n][3]);
    }
}

// ------------------------------------------------------------------
// Combine: sum partial slabs (4 for x-cols, 8 for h-cols), emit P fp16.
// ------------------------------------------------------------------
__global__ __launch_bounds__(256)
void combine_kernel() {
    int idx = blockIdx.x * 256 + threadIdx.x;     // 0 .. Bn*32-1
    int row = idx >> 5;
    int c4  = idx & 31;
    int col = c4 * 4;

    float4 v = make_float4(0.f, 0.f, 0.f, 0.f);
    if (col < 64) {
        const float* p = g_Pp + (size_t)row * 64 + col;
        #pragma unroll
        for (int s = 0; s < 4; s++) {
            float4 a = *(const float4*)(p + (size_t)s * SLAB);
            v.x += a.x; v.y += a.y; v.z += a.z; v.w += a.w;
        }
    } else {
        const float* p = g_Pp + 4 * (size_t)SLAB + (size_t)row * 64 + (col - 64);
        #pragma unroll
        for (int s = 0; s < 8; s++) {
            float4 a = *(const float4*)(p + (size_t)s * SLAB);
            v.x += a.x; v.y += a.y; v.z += a.z; v.w += a.w;
        }
    }

    uint2 w;
    w.x = pack_f16(__float2half(v.x), __float2half(v.y));
    w.y = pack_f16(__float2half(v.z), __float2half(v.w));
    *(uint2*)&g_Pf[(size_t)row * 128 + col] = w;
}

// ------------------------------------------------------------------
// Main GEMM (P @ Vt, K=128, fp16 single-pass) + coalesced epilogue.
// CTA tile M=128 x N=128, 512 thr, 16 warps (4m x 4n), warp 32x32.
// Two K=64 chunks, double-buffered, 3 barriers. 2 CTAs/SM.
// Halves B-side LTS traffic vs M=64 tiling.
// ------------------------------------------------------------------
#define AST 72
#define BST 136
#define U_A  0
#define U_B  (128 * AST)
#define STAGE_UNITS (128 * AST + 64 * BST)           // 17920 units = 35840 B
#define CST 132
#define SMEM_TOTAL (2 * STAGE_UNITS * 2)             // 71680 B (sC 128*132*4=67584 fits)

__global__ __launch_bounds__(512, 2)
void main_kernel(const float* __restrict__ x, const float* __restrict__ h,
                 const float* __restrict__ c,
                 const float* __restrict__ dia_x, const float* __restrict__ dia_h,
                 float* __restrict__ out) {
    extern __shared__ __half smh[];

    int tid = threadIdx.x;
    int lane = tid & 31, w = tid >> 5;
    int wm = w >> 2, wn = w & 3;
    int rowBase = blockIdx.y * 128;
    int colBase = blockIdx.x * 128;
    int j0 = colBase >> 2;
    bool ctaHasX = (j0 < In);

    uint32_t sbase = smem_u32(smh);

    auto load_chunk = [&](int k0, int stage) {
        uint32_t sb = sbase + stage * STAGE_UNITS * 2;
        // A: 128 rows x 64 k = 1024 x 16B chunks
        #pragma unroll
        for (int t = 0; t < 2; t++) {
            int e = t * 512 + tid;
            int r = e >> 3, cc = e & 7;
            cpa16(sb + U_A * 2 + (r * AST + cc * 8) * 2,
                  g_Pf + (size_t)(rowBase + r) * 128 + k0 + cc * 8);
        }
        // B: 64 k x 128 n = 1024 x 16B chunks
        #pragma unroll
        for (int t = 0; t < 2; t++) {
            int e = t * 512 + tid;
            int kr = e >> 4, cc = e & 15;
            cpa16(sb + U_B * 2 + (kr * BST + cc * 8) * 2,
                  g_Vt + (size_t)(k0 + kr) * FourH + colBase + cc * 8);
        }
        CP_COMMIT();
    };

    float C[2][4][4];
    #pragma unroll
    for (int m = 0; m < 2; m++)
        #pragma unroll
        for (int n = 0; n < 4; n++)
            #pragma unroll
            for (int q = 0; q < 4; q++) C[m][n][q] = 0.f;

    load_chunk(0, 0);
    load_chunk(64, 1);

    #pragma unroll
    for (int ck = 0; ck < 2; ck++) {
        if (ck == 0) { CP_WAIT1(); } else { CP_WAIT0(); }
        __syncthreads();

        __half* sA = smh + ck * STAGE_UNITS + U_A;
        __half* sB = smh + ck * STAGE_UNITS + U_B;

        #pragma unroll
        for (int kk = 0; kk < 64; kk += 16) {
            uint32_t bF[4][2];
            #pragma unroll
            for (int p = 0; p < 2; p++) {
                int kr = kk + (lane & 15);
                int nc = wn * 32 + p * 16 + 8 * (lane >> 4);
                uint32_t r[4];
                ldsm_x4_t(r, smem_u32(&sB[kr * BST + nc]));
                bF[2 * p][0] = r[0]; bF[2 * p][1] = r[1];
                bF[2 * p + 1][0] = r[2]; bF[2 * p + 1][1] = r[3];
            }
            #pragma unroll
            for (int m = 0; m < 2; m++) {
                uint32_t aF[4];
                int row = wm * 32 + m * 16 + (lane & 15);
                int col = kk + 8 * (lane >> 4);
                ldsm_x4(aF, smem_u32(&sA[row * AST + col]));
                #pragma unroll
                for (int n = 0; n < 4; n++)
                    mma16816h(C[m][n], aF, bF[n][0], bF[n][1]);
            }
        }
    }
    __syncthreads();

    // ---------------- epilogue: stage C in smem, coalesced I/O ----------------
    float* sC = (float*)smh;
    int quad = lane >> 2, a4 = lane & 3;

    #pragma unroll
    for (int n = 0; n < 4; n++) {
        int col = wn * 32 + n * 8 + a4 * 2;
        #pragma unroll
        for (int m = 0; m < 2; m++) {
            int r0 = wm * 32 + m * 16 + quad;
            *(float2*)&sC[r0 * CST + col]       = make_float2(C[m][n][0], C[m][n][1]);
            *(float2*)&sC[(r0 + 8) * CST + col] = make_float2(C[m][n][2], C[m][n][3]);
        }
    }
    __syncthreads();

    int jl = tid & 31;
    int j  = j0 + jl;
    bool hasX = ctaHasX;

    float4 cfx = *(const float4*)(g_cfx  + (size_t)j * 4);
    float4 cfh = *(const float4*)(g_cfh  + (size_t)j * 4);
    float4 bs  = *(const float4*)(g_bias + (size_t)j * 4);
    float dxv = hasX ? dia_x[j] : 0.f;
    float dhv = dia_h[j];

    #pragma unroll
    for (int pass = 0; pass < 8; pass++) {
        int bl = pass * 16 + (tid >> 5);
        int b  = rowBase + bl;

        float4 g4 = *(const float4*)&sC[bl * CST + jl * 4];
        float xv = hasX ? x[(size_t)b * In + j] : 0.f;
        float hv = h[(size_t)b * Hn + j];
        float cv = c[(size_t)b * Hn + j];
        float z  = dxv * xv + dhv * hv;

        float gi = g4.x - xv * cfx.x - hv * cfh.x + bs.x + z;
        float gf = g4.y - xv * cfx.y - hv * cfh.y + bs.y + z;
        float go = g4.z - xv * cfx.z - hv * cfh.z + bs.z + z;
        float gn = g4.w - xv * cfx.w - hv * cfh.w + bs.w + z;

        float ig = fsigmoid(gi);
        float fg = fsigmoid(gf);
        float og = fsigmoid(go);
        float ng = tanha(gn);

        float cn = fg * cv + ig * ng;
        float hn = og * tanha(cn);

        out[(size_t)b * Hn + j]                   = hn;
        out[(size_t)Bn * Hn + (size_t)b * Hn + j] = cn;
    }
}

// ------------------------------------------------------------------
extern "C" void kernel_launch(void* const* d_in, const int* in_sizes, int n_in,
                              void* d_out, int out_size) {
    const float* x     = (const float*)d_in[0];
    const float* h     = (const float*)d_in[1];
    const float* c     = (const float*)d_in[2];
    const float* u_x   = (const float*)d_in[3];
    const float* u_h   = (const float*)d_in[4];
    const float* v_x   = (const float*)d_in[5];
    const float* v_h   = (const float*)d_in[6];
    const float* b_x   = (const float*)d_in[7];
    const float* b_h   = (const float*)d_in[8];
    const float* dia_x = (const float*)d_in[9];
    const float* dia_h = (const float*)d_in[10];
    float* out = (float*)d_out;

    prep_kernel<<<(128 * FourH) / 256, 256>>>(u_x, u_h, v_x, v_h, b_x, b_h);

    proj_part_kernel<<<dim3(Bn / 64, 12), 256>>>(x, u_x, h, u_h);
    combine_kernel<<<(Bn * 32) / 256, 256>>>();

    cudaFuncSetAttribute(main_kernel,
                         cudaFuncAttributeMaxDynamicSharedMemorySize, SMEM_TOTAL);
    dim3 grid(FourH / 128, Bn / 128);
    main_kernel<<<grid, 512, SMEM_TOTAL>>>(x, h, c, dia_x, dia_h, out);
}